// round 8
// baseline (speedup 1.0000x reference)
#include <cuda_runtime.h>
#include <cuda_bf16.h>
#include <cstdint>

#define BB 4
#define NN 4096
#define MM 2048
#define DD 512
#define CC 10
#define KTOP 64u

// ---------------- scratch (device globals; no cudaMalloc allowed) ----------------
__device__ __align__(256) __nv_bfloat16 g_hq[3][BB * MM * DD];
__device__ __align__(256) __nv_bfloat16 g_hs[3][BB * NN * DD];
__device__ __align__(256) __nv_bfloat16 g_wq[3][DD * DD];
__device__ __align__(256) __nv_bfloat16 g_wk[3][DD * DD];
__device__ __align__(256) __nv_bfloat16 g_qs[3][BB * MM * DD];
__device__ __align__(256) __nv_bfloat16 g_ks[3][BB * NN * DD];
__device__ float g_gamma[(size_t)BB * MM * NN];
__device__ float g_prior[BB * CC];
__device__ float g_rhoinv[BB * CC];

// ---------------- helpers ----------------
__device__ __forceinline__ uint32_t smem_u32(const void* p) {
    uint32_t a;
    asm("{ .reg .u64 t; cvta.to.shared.u64 t, %1; cvt.u32.u64 %0, t; }" : "=r"(a) : "l"(p));
    return a;
}

#define CP16(dst, src) \
    asm volatile("cp.async.cg.shared.global [%0], [%1], 16;" :: "r"(dst), "l"(src))
#define CP_COMMIT() asm volatile("cp.async.commit_group;" ::: "memory")
#define CP_WAIT2()  asm volatile("cp.async.wait_group 2;" ::: "memory")
#define CP_WAIT0()  asm volatile("cp.async.wait_group 0;" ::: "memory")

#define LDSM4(r0, r1, r2, r3, addr) \
    asm volatile("ldmatrix.sync.aligned.m8n8.x4.shared.b16 {%0,%1,%2,%3}, [%4];" \
                 : "=r"(r0), "=r"(r1), "=r"(r2), "=r"(r3) : "r"(addr))

#define MMA16816(d, a, b0, b1) \
    asm volatile("mma.sync.aligned.m16n8k16.row.col.f32.bf16.bf16.f32 " \
                 "{%0,%1,%2,%3}, {%4,%5,%6,%7}, {%8,%9}, {%0,%1,%2,%3};" \
                 : "+f"((d)[0]), "+f"((d)[1]), "+f"((d)[2]), "+f"((d)[3]) \
                 : "r"((a)[0]), "r"((a)[1]), "r"((a)[2]), "r"((a)[3]), "r"(b0), "r"(b1))

// ---------------- LayerNorm fused with 3-way bf16 split ----------------
__global__ void ln_split(const float* __restrict__ x, const float* __restrict__ w,
                         const float* __restrict__ b,
                         __nv_bfloat16* __restrict__ o0, __nv_bfloat16* __restrict__ o1,
                         __nv_bfloat16* __restrict__ o2) {
    int row = blockIdx.x;
    const float* xr = x + (size_t)row * DD;
    int t = threadIdx.x;
    float v[4];
    float s = 0.f, s2 = 0.f;
#pragma unroll
    for (int i = 0; i < 4; i++) {
        v[i] = xr[t + i * 128];
        s += v[i];
        s2 += v[i] * v[i];
    }
#pragma unroll
    for (int o = 16; o > 0; o >>= 1) {
        s  += __shfl_down_sync(0xFFFFFFFFu, s, o);
        s2 += __shfl_down_sync(0xFFFFFFFFu, s2, o);
    }
    __shared__ float ps[4], ps2[4];
    if ((t & 31) == 0) { ps[t >> 5] = s; ps2[t >> 5] = s2; }
    __syncthreads();
    s  = ps[0] + ps[1] + ps[2] + ps[3];
    s2 = ps2[0] + ps2[1] + ps2[2] + ps2[3];
    float mu  = s * (1.f / DD);
    float var = s2 * (1.f / DD) - mu * mu;
    float rs  = 1.f / sqrtf(var + 1e-5f);
#pragma unroll
    for (int i = 0; i < 4; i++) {
        int c = t + i * 128;
        float val = (v[i] - mu) * rs * w[c] + b[c];
        __nv_bfloat16 h0 = __float2bfloat16_rn(val);
        float r1 = val - __bfloat162float(h0);
        __nv_bfloat16 h1 = __float2bfloat16_rn(r1);
        float r2 = r1 - __bfloat162float(h1);
        __nv_bfloat16 h2 = __float2bfloat16_rn(r2);
        size_t oi = (size_t)row * DD + c;
        o0[oi] = h0; o1[oi] = h1; o2[oi] = h2;
    }
}

__global__ void split3(const float* __restrict__ x, __nv_bfloat16* __restrict__ o0,
                       __nv_bfloat16* __restrict__ o1, __nv_bfloat16* __restrict__ o2, int n) {
    int i = blockIdx.x * 256 + threadIdx.x;
    if (i < n) {
        float v = x[i];
        __nv_bfloat16 h0 = __float2bfloat16_rn(v);
        float r1 = v - __bfloat162float(h0);
        __nv_bfloat16 h1 = __float2bfloat16_rn(r1);
        float r2 = r1 - __bfloat162float(h1);
        __nv_bfloat16 h2 = __float2bfloat16_rn(r2);
        o0[i] = h0; o1[i] = h1; o2[i] = h2;
    }
}

// ---------------- mma.sync bf16 GEMM: C = A @ B^T, 6-product bf16x3 split ----------------
// Extended-K, SMALL-FIRST segment order: {a0b2, a2b0, a1b1, a0b1, a1b0, a0b0}.
// a0b0's 16 chunks split 8 (accA) / 8 (accB).
// 512 threads / 16 warps (4x4), warp tile 32x32. Per-output-element accumulation
// chain is UNCHANGED from the passing round-6 kernel (same chunk order, same k16
// order, same accA/accB boundary) -> bit-identical results.
#define KT 32
#define ROWB 80
#define TILE10 (128 * ROWB)          // 10240 B per matrix
#define STAGE_B (2 * TILE10)         // 20480 B per stage (A+B)
#define SMEM_GEMM (4 * STAGE_B)      // 81920 B
#define NCHUNK 96
#define SPLITC 88                    // chunks [88,96) go to accB
#define NTHR 512

template <int MODE>
__global__ void __launch_bounds__(NTHR, 1) mma_gemm(
    const __nv_bfloat16* __restrict__ A0, const __nv_bfloat16* __restrict__ A1,
    const __nv_bfloat16* __restrict__ A2,
    const __nv_bfloat16* __restrict__ B0, const __nv_bfloat16* __restrict__ B1,
    const __nv_bfloat16* __restrict__ B2,
    size_t sA, size_t sB,
    float* __restrict__ gout, size_t sC, int ldc,
    __nv_bfloat16* __restrict__ o0, __nv_bfloat16* __restrict__ o1,
    __nv_bfloat16* __restrict__ o2,
    const float* __restrict__ taup, const float* __restrict__ biasp) {
    extern __shared__ __align__(128) char smem[];
    const int tid  = threadIdx.x;
    const int lane = tid & 31, warp = tid >> 5;
    const int wm = warp >> 2, wn = warp & 3;          // 4x4 warp grid
    const int m0 = blockIdx.y * 128, n0 = blockIdx.x * 128;

    const size_t aOff = (size_t)blockIdx.z * sA + (size_t)m0 * DD;
    const size_t bOff = (size_t)blockIdx.z * sB + (size_t)n0 * DD;
    // small-first order: a0b2, a2b0, a1b1, a0b1, a1b0, a0b0
    const __nv_bfloat16* aSeg[6] = { A0 + aOff, A2 + aOff, A1 + aOff,
                                     A0 + aOff, A1 + aOff, A0 + aOff };
    const __nv_bfloat16* bSeg[6] = { B2 + bOff, B0 + bOff, B1 + bOff,
                                     B1 + bOff, B0 + bOff, B0 + bOff };

    const uint32_t sbase = smem_u32(smem);
    const int r0i = tid >> 2, c0i = tid & 3;          // 512 threads: rows 0..127

    const uint32_t aRowOff = (uint32_t)(((lane & 7) + (lane & 8)) * ROWB + (lane & 16));
    const uint32_t bRowOff = (uint32_t)(((lane & 7) + ((lane & 16) >> 1)) * ROWB + ((lane & 8) << 1));

    float accA[2][4][4];
#pragma unroll
    for (int i = 0; i < 2; i++)
#pragma unroll
        for (int j = 0; j < 4; j++)
#pragma unroll
            for (int q = 0; q < 4; q++) accA[i][j][q] = 0.f;

    auto issue = [&](int c) {
        int seg = c >> 4, k0 = (c & 15) * KT;
        uint32_t sb0 = sbase + (c & 3) * STAGE_B;
        const __nv_bfloat16* ap = aSeg[seg] + k0;
        const __nv_bfloat16* bp = bSeg[seg] + k0;
        CP16(sb0 + (uint32_t)(r0i * ROWB + c0i * 16), ap + (size_t)r0i * DD + c0i * 8);
        uint32_t sb1 = sb0 + TILE10;
        CP16(sb1 + (uint32_t)(r0i * ROWB + c0i * 16), bp + (size_t)r0i * DD + c0i * 8);
    };

    auto body = [&](int c, float (&acc)[2][4][4]) {
        CP_WAIT2();
        __syncthreads();          // orders prior-chunk reads before overwrite below
        int cn = c + 3;
        if (cn < NCHUNK) issue(cn);
        CP_COMMIT();

        uint32_t sa = sbase + (c & 3) * STAGE_B;
        uint32_t sb = sa + TILE10;
#pragma unroll
        for (int k16 = 0; k16 < 2; k16++) {
            uint32_t a[2][4];
#pragma unroll
            for (int mt = 0; mt < 2; mt++) {
                uint32_t addr = sa + (uint32_t)((wm * 32 + mt * 16) * ROWB) + aRowOff + k16 * 32;
                LDSM4(a[mt][0], a[mt][1], a[mt][2], a[mt][3], addr);
            }
            uint32_t bfr[2][4];
#pragma unroll
            for (int nt2 = 0; nt2 < 2; nt2++) {
                uint32_t addr = sb + (uint32_t)((wn * 32 + nt2 * 16) * ROWB) + bRowOff + k16 * 32;
                LDSM4(bfr[nt2][0], bfr[nt2][1], bfr[nt2][2], bfr[nt2][3], addr);
            }
#pragma unroll
            for (int mt = 0; mt < 2; mt++)
#pragma unroll
                for (int nt = 0; nt < 4; nt++)
                    MMA16816(acc[mt][nt], a[mt], bfr[nt >> 1][(nt & 1) * 2],
                             bfr[nt >> 1][(nt & 1) * 2 + 1]);
        }
    };

    issue(0); CP_COMMIT();
    issue(1); CP_COMMIT();
    issue(2); CP_COMMIT();

    for (int c = 0; c < SPLITC; c++) body(c, accA);

    float accB[2][4][4];
#pragma unroll
    for (int i = 0; i < 2; i++)
#pragma unroll
        for (int j = 0; j < 4; j++)
#pragma unroll
            for (int q = 0; q < 4; q++) accB[i][j][q] = 0.f;

    for (int c = SPLITC; c < NCHUNK; c++) body(c, accB);
    CP_WAIT0();

    // ---------------- epilogue ----------------
    const int mrow = lane >> 2, ncol = (lane & 3) * 2;
    if (MODE == 1) {
        float alpha = log1pf(expf(*taup)) + 1e-6f;
        float beta  = *biasp;
        float* Cb = gout + (size_t)blockIdx.z * sC;
#pragma unroll
        for (int mt = 0; mt < 2; mt++) {
#pragma unroll
            for (int half = 0; half < 2; half++) {
                int gr = m0 + wm * 32 + mt * 16 + mrow + half * 8;
                float* crow = Cb + (size_t)gr * ldc + n0 + wn * 32 + ncol;
#pragma unroll
                for (int nt = 0; nt < 4; nt++) {
                    float vx = accA[mt][nt][half * 2 + 0] + accB[mt][nt][half * 2 + 0];
                    float vy = accA[mt][nt][half * 2 + 1] + accB[mt][nt][half * 2 + 1];
                    float2 f;
                    f.x = 1.f / (1.f + expf(-(alpha * vx + beta)));
                    f.y = 1.f / (1.f + expf(-(alpha * vy + beta)));
                    *reinterpret_cast<float2*>(crow + nt * 8) = f;
                }
            }
        }
    } else {
#pragma unroll
        for (int mt = 0; mt < 2; mt++) {
#pragma unroll
            for (int half = 0; half < 2; half++) {
                int gr = m0 + wm * 32 + mt * 16 + mrow + half * 8;
                size_t base = (size_t)gr * DD + n0 + wn * 32 + ncol;
#pragma unroll
                for (int nt = 0; nt < 4; nt++) {
                    float vx = accA[mt][nt][half * 2 + 0] + accB[mt][nt][half * 2 + 0];
                    float vy = accA[mt][nt][half * 2 + 1] + accB[mt][nt][half * 2 + 1];
                    __nv_bfloat162 h0v, h1v, h2v;
                    __nv_bfloat16 x0 = __float2bfloat16_rn(vx);
                    float x1f = vx - __bfloat162float(x0);
                    __nv_bfloat16 x1 = __float2bfloat16_rn(x1f);
                    __nv_bfloat16 x2 = __float2bfloat16_rn(x1f - __bfloat162float(x1));
                    __nv_bfloat16 y0 = __float2bfloat16_rn(vy);
                    float y1f = vy - __bfloat162float(y0);
                    __nv_bfloat16 y1 = __float2bfloat16_rn(y1f);
                    __nv_bfloat16 y2 = __float2bfloat16_rn(y1f - __bfloat162float(y1));
                    h0v.x = x0; h0v.y = y0;
                    h1v.x = x1; h1v.y = y1;
                    h2v.x = x2; h2v.y = y2;
                    *reinterpret_cast<__nv_bfloat162*>(o0 + base + nt * 8) = h0v;
                    *reinterpret_cast<__nv_bfloat162*>(o1 + base + nt * 8) = h1v;
                    *reinterpret_cast<__nv_bfloat162*>(o2 + base + nt * 8) = h2v;
                }
            }
        }
    }
}

// ---------------- prior / rho-inverse per batch ----------------
__global__ void prior_kernel(const int* __restrict__ y) {
    int b = blockIdx.x;
    __shared__ int cnt[CC];
    int t = threadIdx.x;
    if (t < CC) cnt[t] = 0;
    __syncthreads();
    for (int i = t; i < NN; i += 256) atomicAdd(&cnt[y[(size_t)b * NN + i]], 1);
    __syncthreads();
    if (t == 0) {
        int tot = 0;
        for (int c = 0; c < CC; c++) tot += cnt[c];
        float denom = fmaxf((float)tot, 1.f);
        for (int c = 0; c < CC; c++) {
            float pr = (float)cnt[c] / denom;
            g_prior[b * CC + c]  = pr;
            g_rhoinv[b * CC + c] = 1.f / fmaxf(1.f - pr, 1e-6f);
        }
    }
}

// ---------------- per-query top-k select + class aggregation ----------------
__device__ __forceinline__ unsigned f2u(float f) {
    unsigned u = __float_as_uint(f);
    return (u & 0x80000000u) ? ~u : (u | 0x80000000u);
}

__global__ void select_agg(const int* __restrict__ y, float* __restrict__ out) {
    int m = blockIdx.x, b = blockIdx.y;
    const float* grow = g_gamma + ((size_t)b * MM + m) * NN;
    __shared__ float gs[NN];
    __shared__ unsigned short cand[NN];
    __shared__ unsigned whist[8][256];
    __shared__ unsigned hist[256];
    __shared__ unsigned sh_pref, sh_k, sh_nc;
    __shared__ float S[CC], W[CC], sh_prior[CC], sh_rinv[CC];
    __shared__ unsigned cntk;
    const int t = threadIdx.x;
    const int warp = t >> 5;

    for (int i = t; i < NN / 4; i += 256)
        reinterpret_cast<float4*>(gs)[i] = reinterpret_cast<const float4*>(grow)[i];
    for (int i = t; i < 8 * 256; i += 256) (&whist[0][0])[i] = 0u;
    if (t < CC) {
        S[t] = 0.f; W[t] = 0.f;
        sh_prior[t] = g_prior[b * CC + t];
        sh_rinv[t]  = g_rhoinv[b * CC + t];
    }
    if (t == 0) { cntk = 0; sh_nc = 0; }
    __syncthreads();

    // ---- pass 1: top 8 bits, per-warp hist ----
    for (int i = t; i < NN; i += 256)
        atomicAdd(&whist[warp][f2u(gs[i]) >> 24], 1u);
    __syncthreads();
    {
        unsigned h = 0;
#pragma unroll
        for (int w = 0; w < 8; w++) h += whist[w][t];
        hist[t] = h;
    }
    __syncthreads();
    if (t == 0) {
        unsigned acc = 0, krem = KTOP;
        int bin = 0;
        for (int i = 255; i >= 0; i--) {
            unsigned h = hist[i];
            if (acc + h >= KTOP) { bin = i; krem = KTOP - acc; break; }
            acc += h;
        }
        sh_pref = (unsigned)bin << 24;
        sh_k = krem;
    }
    __syncthreads();
    unsigned prefix = sh_pref;

    // ---- compact candidates (top-8 == winning bin) ----
    for (int i = t; i < NN; i += 256) {
        if ((f2u(gs[i]) & 0xFF000000u) == prefix) {
            unsigned idx = atomicAdd(&sh_nc, 1u);
            cand[idx] = (unsigned short)i;
        }
    }
    __syncthreads();
    const int ncand = (int)sh_nc;

    // ---- passes 2-4 over candidates only ----
#pragma unroll
    for (int shift = 16; shift >= 0; shift -= 8) {
        hist[t] = 0;
        __syncthreads();
        unsigned pm = 0xFFFFFFFFu << (shift + 8);
        for (int j = t; j < ncand; j += 256) {
            unsigned u = f2u(gs[cand[j]]);
            if ((u & pm) == prefix) atomicAdd(&hist[(u >> shift) & 255u], 1u);
        }
        __syncthreads();
        if (t == 0) {
            unsigned kneed = sh_k, acc = 0, krem = kneed;
            int bin = 0;
            for (int i = 255; i >= 0; i--) {
                unsigned h = hist[i];
                if (acc + h >= kneed) { bin = i; krem = kneed - acc; break; }
                acc += h;
            }
            sh_pref = prefix | ((unsigned)bin << shift);
            sh_k = krem;
        }
        __syncthreads();
        prefix = sh_pref;
    }
    // prefix = sortable key of the exact 64th-largest gamma.
    const int* yrow = y + (size_t)b * NN;
    for (int i = t; i < NN; i += 256) {
        float g = gs[i];
        if (f2u(g) >= prefix) {
            int c = yrow[i];
            atomicAdd(&S[c], g);
            atomicAdd(&W[c], (1.f - g) * sh_rinv[c]);
            atomicAdd(&cntk, 1u);
        }
    }
    __syncthreads();
    if (t == 0) {
        float Wt = 0.f;
        for (int c = 0; c < CC; c++) Wt += W[c];
        float dq = fmaxf((float)cntk, 1.f);
        float p[CC];
        float sum = 0.f;
        for (int c = 0; c < CC; c++) {
            float v = S[c] + sh_prior[c] * (Wt - W[c]);
            v = fmaxf(v, 0.f) / dq;
            p[c] = v;
            sum += v;
        }
        float inv = 1.f / fmaxf(sum, 1e-12f);
        float* orow = out + ((size_t)b * MM + m) * CC;
        for (int c = 0; c < CC; c++) orow[c] = p[c] * inv;
    }
}

// ---------------- launcher ----------------
extern "C" void kernel_launch(void* const* d_in, const int* in_sizes, int n_in,
                              void* d_out, int out_size) {
    const float* Hs   = (const float*)d_in[0];
    const float* Hq   = (const float*)d_in[1];
    const int*   ys   = (const int*)d_in[2];
    const float* lnw  = (const float*)d_in[4];
    const float* lnb  = (const float*)d_in[5];
    const float* WQ   = (const float*)d_in[6];
    const float* WK   = (const float*)d_in[7];
    const float* taup = (const float*)d_in[8];
    const float* bisp = (const float*)d_in[9];
    float* out = (float*)d_out;

    __nv_bfloat16 *hqB, *hsB, *wqB, *wkB, *qB, *kB;
    float* Gam;
    cudaGetSymbolAddress((void**)&hqB, g_hq);
    cudaGetSymbolAddress((void**)&hsB, g_hs);
    cudaGetSymbolAddress((void**)&wqB, g_wq);
    cudaGetSymbolAddress((void**)&wkB, g_wk);
    cudaGetSymbolAddress((void**)&qB, g_qs);
    cudaGetSymbolAddress((void**)&kB, g_ks);
    cudaGetSymbolAddress((void**)&Gam, g_gamma);

    const size_t HQ = (size_t)BB * MM * DD;
    const size_t HS = (size_t)BB * NN * DD;
    const size_t WW = (size_t)DD * DD;

    cudaFuncSetAttribute(mma_gemm<0>, cudaFuncAttributeMaxDynamicSharedMemorySize, SMEM_GEMM);
    cudaFuncSetAttribute(mma_gemm<1>, cudaFuncAttributeMaxDynamicSharedMemorySize, SMEM_GEMM);

    // 1) LayerNorm + splits
    ln_split<<<BB * MM, 128>>>(Hq, lnw, lnb, hqB, hqB + HQ, hqB + 2 * HQ);
    ln_split<<<BB * NN, 128>>>(Hs, lnw, lnb, hsB, hsB + HS, hsB + 2 * HS);
    split3<<<(int)((WW + 255) / 256), 256>>>(WQ, wqB, wqB + WW, wqB + 2 * WW, (int)WW);
    split3<<<(int)((WW + 255) / 256), 256>>>(WK, wkB, wkB + WW, wkB + 2 * WW, (int)WW);

    // 2) priors
    prior_kernel<<<BB, 256>>>(ys);

    // 3) projections: Q = Hq_ln @ WQ^T, K = Hs_ln @ WK^T (bf16-split outputs)
    mma_gemm<0><<<dim3(DD / 128, (BB * MM) / 128, 1), NTHR, SMEM_GEMM>>>(
        hqB, hqB + HQ, hqB + 2 * HQ, wqB, wqB + WW, wqB + 2 * WW,
        0, 0, nullptr, 0, 0, qB, qB + HQ, qB + 2 * HQ, nullptr, nullptr);
    mma_gemm<0><<<dim3(DD / 128, (BB * NN) / 128, 1), NTHR, SMEM_GEMM>>>(
        hsB, hsB + HS, hsB + 2 * HS, wkB, wkB + WW, wkB + 2 * WW,
        0, 0, nullptr, 0, 0, kB, kB + HS, kB + 2 * HS, nullptr, nullptr);

    // 4) gamma = sigmoid(tau * Q K^T + bias)
    mma_gemm<1><<<dim3(NN / 128, MM / 128, BB), NTHR, SMEM_GEMM>>>(
        qB, qB + HQ, qB + 2 * HQ, kB, kB + HS, kB + 2 * HS,
        (size_t)MM * DD, (size_t)NN * DD, Gam, (size_t)MM * NN, NN,
        nullptr, nullptr, nullptr, taup, bisp);

    // 5) top-k select + aggregate + normalize
    select_agg<<<dim3(MM, BB), 256>>>(ys, out);
}

// round 9
// speedup vs baseline: 1.0989x; 1.0989x over previous
#include <cuda_runtime.h>
#include <cuda_bf16.h>
#include <cstdint>

#define BB 4
#define NN 4096
#define MM 2048
#define DD 512
#define CC 10
#define KTOP 64u

// ---------------- scratch (device globals; no cudaMalloc allowed) ----------------
__device__ __align__(256) __nv_bfloat16 g_hq[3][BB * MM * DD];
__device__ __align__(256) __nv_bfloat16 g_hs[3][BB * NN * DD];
__device__ __align__(256) __nv_bfloat16 g_wq[3][DD * DD];
__device__ __align__(256) __nv_bfloat16 g_wk[3][DD * DD];
__device__ __align__(256) __nv_bfloat16 g_qs[3][BB * MM * DD];
__device__ __align__(256) __nv_bfloat16 g_ks[3][BB * NN * DD];
__device__ float g_gamma[(size_t)BB * MM * NN];
__device__ float g_prior[BB * CC];
__device__ float g_rhoinv[BB * CC];

// ---------------- helpers ----------------
__device__ __forceinline__ uint32_t smem_u32(const void* p) {
    uint32_t a;
    asm("{ .reg .u64 t; cvta.to.shared.u64 t, %1; cvt.u32.u64 %0, t; }" : "=r"(a) : "l"(p));
    return a;
}

#define CP16(dst, src) \
    asm volatile("cp.async.cg.shared.global [%0], [%1], 16;" :: "r"(dst), "l"(src))
#define CP_COMMIT() asm volatile("cp.async.commit_group;" ::: "memory")
#define CP_WAIT2()  asm volatile("cp.async.wait_group 2;" ::: "memory")
#define CP_WAIT0()  asm volatile("cp.async.wait_group 0;" ::: "memory")

#define LDSM4(r0, r1, r2, r3, addr) \
    asm volatile("ldmatrix.sync.aligned.m8n8.x4.shared.b16 {%0,%1,%2,%3}, [%4];" \
                 : "=r"(r0), "=r"(r1), "=r"(r2), "=r"(r3) : "r"(addr))

#define MMA16816(d, a, b0, b1) \
    asm volatile("mma.sync.aligned.m16n8k16.row.col.f32.bf16.bf16.f32 " \
                 "{%0,%1,%2,%3}, {%4,%5,%6,%7}, {%8,%9}, {%0,%1,%2,%3};" \
                 : "+f"((d)[0]), "+f"((d)[1]), "+f"((d)[2]), "+f"((d)[3]) \
                 : "r"((a)[0]), "r"((a)[1]), "r"((a)[2]), "r"((a)[3]), "r"(b0), "r"(b1))

// ---------------- LayerNorm fused with 3-way bf16 split ----------------
__global__ void ln_split(const float* __restrict__ x, const float* __restrict__ w,
                         const float* __restrict__ b,
                         __nv_bfloat16* __restrict__ o0, __nv_bfloat16* __restrict__ o1,
                         __nv_bfloat16* __restrict__ o2) {
    int row = blockIdx.x;
    const float* xr = x + (size_t)row * DD;
    int t = threadIdx.x;
    float v[4];
    float s = 0.f, s2 = 0.f;
#pragma unroll
    for (int i = 0; i < 4; i++) {
        v[i] = xr[t + i * 128];
        s += v[i];
        s2 += v[i] * v[i];
    }
#pragma unroll
    for (int o = 16; o > 0; o >>= 1) {
        s  += __shfl_down_sync(0xFFFFFFFFu, s, o);
        s2 += __shfl_down_sync(0xFFFFFFFFu, s2, o);
    }
    __shared__ float ps[4], ps2[4];
    if ((t & 31) == 0) { ps[t >> 5] = s; ps2[t >> 5] = s2; }
    __syncthreads();
    s  = ps[0] + ps[1] + ps[2] + ps[3];
    s2 = ps2[0] + ps2[1] + ps2[2] + ps2[3];
    float mu  = s * (1.f / DD);
    float var = s2 * (1.f / DD) - mu * mu;
    float rs  = 1.f / sqrtf(var + 1e-5f);
#pragma unroll
    for (int i = 0; i < 4; i++) {
        int c = t + i * 128;
        float val = (v[i] - mu) * rs * w[c] + b[c];
        __nv_bfloat16 h0 = __float2bfloat16_rn(val);
        float r1 = val - __bfloat162float(h0);
        __nv_bfloat16 h1 = __float2bfloat16_rn(r1);
        float r2 = r1 - __bfloat162float(h1);
        __nv_bfloat16 h2 = __float2bfloat16_rn(r2);
        size_t oi = (size_t)row * DD + c;
        o0[oi] = h0; o1[oi] = h1; o2[oi] = h2;
    }
}

__global__ void split3(const float* __restrict__ x, __nv_bfloat16* __restrict__ o0,
                       __nv_bfloat16* __restrict__ o1, __nv_bfloat16* __restrict__ o2, int n) {
    int i = blockIdx.x * 256 + threadIdx.x;
    if (i < n) {
        float v = x[i];
        __nv_bfloat16 h0 = __float2bfloat16_rn(v);
        float r1 = v - __bfloat162float(h0);
        __nv_bfloat16 h1 = __float2bfloat16_rn(r1);
        float r2 = r1 - __bfloat162float(h1);
        __nv_bfloat16 h2 = __float2bfloat16_rn(r2);
        o0[i] = h0; o1[i] = h1; o2[i] = h2;
    }
}

// ---------------- mma.sync bf16 GEMM: C = A @ B^T, 6-product bf16x3 split ----------------
// Extended-K, SMALL-FIRST segment order: {a0b2, a2b0, a1b1, a0b1, a1b0, a0b0}.
// ROUND 9: single accumulator (no accA/accB split) + compact addressing to fit
// <=128 regs -> __launch_bounds__(256, 2) gives 2 resident CTAs/SM to fill
// barrier/latency gaps. Chunk order and segment order unchanged.
#define KT 32
#define ROWB 80
#define TILE10 (128 * ROWB)          // 10240 B per matrix
#define STAGE_B (2 * TILE10)         // 20480 B per stage (A+B)
#define SMEM_GEMM (4 * STAGE_B)      // 81920 B (x2 CTAs = 163840 < 227KB)
#define NCHUNK 96
#define NTHR 256

template <int MODE>
__global__ void __launch_bounds__(NTHR, 2) mma_gemm(
    const __nv_bfloat16* __restrict__ A0, const __nv_bfloat16* __restrict__ A1,
    const __nv_bfloat16* __restrict__ A2,
    const __nv_bfloat16* __restrict__ B0, const __nv_bfloat16* __restrict__ B1,
    const __nv_bfloat16* __restrict__ B2,
    size_t sA, size_t sB,
    float* __restrict__ gout, size_t sC, int ldc,
    __nv_bfloat16* __restrict__ o0, __nv_bfloat16* __restrict__ o1,
    __nv_bfloat16* __restrict__ o2,
    const float* __restrict__ taup, const float* __restrict__ biasp) {
    extern __shared__ __align__(128) char smem[];
    const int tid  = threadIdx.x;
    const int lane = tid & 31, warp = tid >> 5;
    const int wm = warp >> 2, wn = warp & 3;
    const int m0 = blockIdx.y * 128, n0 = blockIdx.x * 128;

    // compact segment addressing: base pointers + u32 element offsets
    const __nv_bfloat16* Abase = A0 + (size_t)blockIdx.z * sA + (size_t)m0 * DD;
    const __nv_bfloat16* Bbase = B0 + (size_t)blockIdx.z * sB + (size_t)n0 * DD;
    const uint32_t da1 = (uint32_t)(A1 - A0), da2 = (uint32_t)(A2 - A0);
    const uint32_t db1 = (uint32_t)(B1 - B0), db2 = (uint32_t)(B2 - B0);

    const uint32_t sbase = smem_u32(smem);
    const int r0i = tid >> 2, c0i = tid & 3;
    const int r1i = r0i + 64;

    const uint32_t aRowOff = (uint32_t)(((lane & 7) + (lane & 8)) * ROWB + (lane & 16));
    const uint32_t bRowOff = (uint32_t)(((lane & 7) + ((lane & 16) >> 1)) * ROWB + ((lane & 8) << 1));

    float acc[4][4][4];
#pragma unroll
    for (int i = 0; i < 4; i++)
#pragma unroll
        for (int j = 0; j < 4; j++)
#pragma unroll
            for (int q = 0; q < 4; q++) acc[i][j][q] = 0.f;

    auto issue = [&](int c) {
        int seg = c >> 4, k0 = (c & 15) * KT;
        // small-first segment order: 0:a0b2 1:a2b0 2:a1b1 3:a0b1 4:a1b0 5:a0b0
        uint32_t oa = (seg == 1) ? da2 : ((seg == 2) || (seg == 4)) ? da1 : 0u;
        uint32_t ob = (seg == 0) ? db2 : ((seg == 2) || (seg == 3)) ? db1 : 0u;
        uint32_t sb0 = sbase + (c & 3) * STAGE_B;
        const __nv_bfloat16* ap = Abase + oa + k0;
        const __nv_bfloat16* bp = Bbase + ob + k0;
        CP16(sb0 + (uint32_t)(r0i * ROWB + c0i * 16), ap + (size_t)r0i * DD + c0i * 8);
        CP16(sb0 + (uint32_t)(r1i * ROWB + c0i * 16), ap + (size_t)r1i * DD + c0i * 8);
        uint32_t sb1 = sb0 + TILE10;
        CP16(sb1 + (uint32_t)(r0i * ROWB + c0i * 16), bp + (size_t)r0i * DD + c0i * 8);
        CP16(sb1 + (uint32_t)(r1i * ROWB + c0i * 16), bp + (size_t)r1i * DD + c0i * 8);
    };

    issue(0); CP_COMMIT();
    issue(1); CP_COMMIT();
    issue(2); CP_COMMIT();

    for (int c = 0; c < NCHUNK; c++) {
        CP_WAIT2();
        __syncthreads();          // orders prior-chunk reads before overwrite below
        int cn = c + 3;
        if (cn < NCHUNK) issue(cn);
        CP_COMMIT();

        uint32_t sa = sbase + (c & 3) * STAGE_B;
        uint32_t sb = sa + TILE10;
#pragma unroll
        for (int k16 = 0; k16 < 2; k16++) {
            uint32_t a[4][4];
#pragma unroll
            for (int mt = 0; mt < 4; mt++) {
                uint32_t addr = sa + (uint32_t)((wm * 64 + mt * 16) * ROWB) + aRowOff + k16 * 32;
                LDSM4(a[mt][0], a[mt][1], a[mt][2], a[mt][3], addr);
            }
            uint32_t bfr[2][4];
#pragma unroll
            for (int nt2 = 0; nt2 < 2; nt2++) {
                uint32_t addr = sb + (uint32_t)((wn * 32 + nt2 * 16) * ROWB) + bRowOff + k16 * 32;
                LDSM4(bfr[nt2][0], bfr[nt2][1], bfr[nt2][2], bfr[nt2][3], addr);
            }
#pragma unroll
            for (int mt = 0; mt < 4; mt++)
#pragma unroll
                for (int nt = 0; nt < 4; nt++)
                    MMA16816(acc[mt][nt], a[mt], bfr[nt >> 1][(nt & 1) * 2],
                             bfr[nt >> 1][(nt & 1) * 2 + 1]);
        }
    }
    CP_WAIT0();

    // ---------------- epilogue ----------------
    const int mrow = lane >> 2, ncol = (lane & 3) * 2;
    if (MODE == 1) {
        float alpha = log1pf(expf(*taup)) + 1e-6f;
        float beta  = *biasp;
        float* Cb = gout + (size_t)blockIdx.z * sC;
#pragma unroll
        for (int mt = 0; mt < 4; mt++) {
#pragma unroll
            for (int half = 0; half < 2; half++) {
                int gr = m0 + wm * 64 + mt * 16 + mrow + half * 8;
                float* crow = Cb + (size_t)gr * ldc + n0 + wn * 32 + ncol;
#pragma unroll
                for (int nt = 0; nt < 4; nt++) {
                    float2 f;
                    f.x = 1.f / (1.f + expf(-(alpha * acc[mt][nt][half * 2 + 0] + beta)));
                    f.y = 1.f / (1.f + expf(-(alpha * acc[mt][nt][half * 2 + 1] + beta)));
                    *reinterpret_cast<float2*>(crow + nt * 8) = f;
                }
            }
        }
    } else {
#pragma unroll
        for (int mt = 0; mt < 4; mt++) {
#pragma unroll
            for (int half = 0; half < 2; half++) {
                int gr = m0 + wm * 64 + mt * 16 + mrow + half * 8;
                size_t base = (size_t)gr * DD + n0 + wn * 32 + ncol;
#pragma unroll
                for (int nt = 0; nt < 4; nt++) {
                    float vx = acc[mt][nt][half * 2 + 0];
                    float vy = acc[mt][nt][half * 2 + 1];
                    __nv_bfloat162 h0v, h1v, h2v;
                    __nv_bfloat16 x0 = __float2bfloat16_rn(vx);
                    float x1f = vx - __bfloat162float(x0);
                    __nv_bfloat16 x1 = __float2bfloat16_rn(x1f);
                    __nv_bfloat16 x2 = __float2bfloat16_rn(x1f - __bfloat162float(x1));
                    __nv_bfloat16 y0 = __float2bfloat16_rn(vy);
                    float y1f = vy - __bfloat162float(y0);
                    __nv_bfloat16 y1 = __float2bfloat16_rn(y1f);
                    __nv_bfloat16 y2 = __float2bfloat16_rn(y1f - __bfloat162float(y1));
                    h0v.x = x0; h0v.y = y0;
                    h1v.x = x1; h1v.y = y1;
                    h2v.x = x2; h2v.y = y2;
                    *reinterpret_cast<__nv_bfloat162*>(o0 + base + nt * 8) = h0v;
                    *reinterpret_cast<__nv_bfloat162*>(o1 + base + nt * 8) = h1v;
                    *reinterpret_cast<__nv_bfloat162*>(o2 + base + nt * 8) = h2v;
                }
            }
        }
    }
}

// ---------------- prior / rho-inverse per batch ----------------
__global__ void prior_kernel(const int* __restrict__ y) {
    int b = blockIdx.x;
    __shared__ int cnt[CC];
    int t = threadIdx.x;
    if (t < CC) cnt[t] = 0;
    __syncthreads();
    for (int i = t; i < NN; i += 256) atomicAdd(&cnt[y[(size_t)b * NN + i]], 1);
    __syncthreads();
    if (t == 0) {
        int tot = 0;
        for (int c = 0; c < CC; c++) tot += cnt[c];
        float denom = fmaxf((float)tot, 1.f);
        for (int c = 0; c < CC; c++) {
            float pr = (float)cnt[c] / denom;
            g_prior[b * CC + c]  = pr;
            g_rhoinv[b * CC + c] = 1.f / fmaxf(1.f - pr, 1e-6f);
        }
    }
}

// ---------------- per-query top-k select + class aggregation ----------------
__device__ __forceinline__ unsigned f2u(float f) {
    unsigned u = __float_as_uint(f);
    return (u & 0x80000000u) ? ~u : (u | 0x80000000u);
}

__global__ void select_agg(const int* __restrict__ y, float* __restrict__ out) {
    int m = blockIdx.x, b = blockIdx.y;
    const float* grow = g_gamma + ((size_t)b * MM + m) * NN;
    __shared__ float gs[NN];
    __shared__ unsigned short cand[NN];
    __shared__ unsigned whist[8][256];
    __shared__ unsigned hist[256];
    __shared__ unsigned sh_pref, sh_k, sh_nc;
    __shared__ float S[CC], W[CC], sh_prior[CC], sh_rinv[CC];
    __shared__ unsigned cntk;
    const int t = threadIdx.x;
    const int warp = t >> 5;

    for (int i = t; i < NN / 4; i += 256)
        reinterpret_cast<float4*>(gs)[i] = reinterpret_cast<const float4*>(grow)[i];
    for (int i = t; i < 8 * 256; i += 256) (&whist[0][0])[i] = 0u;
    if (t < CC) {
        S[t] = 0.f; W[t] = 0.f;
        sh_prior[t] = g_prior[b * CC + t];
        sh_rinv[t]  = g_rhoinv[b * CC + t];
    }
    if (t == 0) { cntk = 0; sh_nc = 0; }
    __syncthreads();

    // ---- pass 1: top 8 bits, per-warp hist ----
    for (int i = t; i < NN; i += 256)
        atomicAdd(&whist[warp][f2u(gs[i]) >> 24], 1u);
    __syncthreads();
    {
        unsigned h = 0;
#pragma unroll
        for (int w = 0; w < 8; w++) h += whist[w][t];
        hist[t] = h;
    }
    __syncthreads();
    if (t == 0) {
        unsigned acc = 0, krem = KTOP;
        int bin = 0;
        for (int i = 255; i >= 0; i--) {
            unsigned h = hist[i];
            if (acc + h >= KTOP) { bin = i; krem = KTOP - acc; break; }
            acc += h;
        }
        sh_pref = (unsigned)bin << 24;
        sh_k = krem;
    }
    __syncthreads();
    unsigned prefix = sh_pref;

    // ---- compact candidates (top-8 == winning bin) ----
    for (int i = t; i < NN; i += 256) {
        if ((f2u(gs[i]) & 0xFF000000u) == prefix) {
            unsigned idx = atomicAdd(&sh_nc, 1u);
            cand[idx] = (unsigned short)i;
        }
    }
    __syncthreads();
    const int ncand = (int)sh_nc;

    // ---- passes 2-4 over candidates only ----
#pragma unroll
    for (int shift = 16; shift >= 0; shift -= 8) {
        hist[t] = 0;
        __syncthreads();
        unsigned pm = 0xFFFFFFFFu << (shift + 8);
        for (int j = t; j < ncand; j += 256) {
            unsigned u = f2u(gs[cand[j]]);
            if ((u & pm) == prefix) atomicAdd(&hist[(u >> shift) & 255u], 1u);
        }
        __syncthreads();
        if (t == 0) {
            unsigned kneed = sh_k, acc = 0, krem = kneed;
            int bin = 0;
            for (int i = 255; i >= 0; i--) {
                unsigned h = hist[i];
                if (acc + h >= kneed) { bin = i; krem = kneed - acc; break; }
                acc += h;
            }
            sh_pref = prefix | ((unsigned)bin << shift);
            sh_k = krem;
        }
        __syncthreads();
        prefix = sh_pref;
    }
    // prefix = sortable key of the exact 64th-largest gamma.
    const int* yrow = y + (size_t)b * NN;
    for (int i = t; i < NN; i += 256) {
        float g = gs[i];
        if (f2u(g) >= prefix) {
            int c = yrow[i];
            atomicAdd(&S[c], g);
            atomicAdd(&W[c], (1.f - g) * sh_rinv[c]);
            atomicAdd(&cntk, 1u);
        }
    }
    __syncthreads();
    if (t == 0) {
        float Wt = 0.f;
        for (int c = 0; c < CC; c++) Wt += W[c];
        float dq = fmaxf((float)cntk, 1.f);
        float p[CC];
        float sum = 0.f;
        for (int c = 0; c < CC; c++) {
            float v = S[c] + sh_prior[c] * (Wt - W[c]);
            v = fmaxf(v, 0.f) / dq;
            p[c] = v;
            sum += v;
        }
        float inv = 1.f / fmaxf(sum, 1e-12f);
        float* orow = out + ((size_t)b * MM + m) * CC;
        for (int c = 0; c < CC; c++) orow[c] = p[c] * inv;
    }
}

// ---------------- launcher ----------------
extern "C" void kernel_launch(void* const* d_in, const int* in_sizes, int n_in,
                              void* d_out, int out_size) {
    const float* Hs   = (const float*)d_in[0];
    const float* Hq   = (const float*)d_in[1];
    const int*   ys   = (const int*)d_in[2];
    const float* lnw  = (const float*)d_in[4];
    const float* lnb  = (const float*)d_in[5];
    const float* WQ   = (const float*)d_in[6];
    const float* WK   = (const float*)d_in[7];
    const float* taup = (const float*)d_in[8];
    const float* bisp = (const float*)d_in[9];
    float* out = (float*)d_out;

    __nv_bfloat16 *hqB, *hsB, *wqB, *wkB, *qB, *kB;
    float* Gam;
    cudaGetSymbolAddress((void**)&hqB, g_hq);
    cudaGetSymbolAddress((void**)&hsB, g_hs);
    cudaGetSymbolAddress((void**)&wqB, g_wq);
    cudaGetSymbolAddress((void**)&wkB, g_wk);
    cudaGetSymbolAddress((void**)&qB, g_qs);
    cudaGetSymbolAddress((void**)&kB, g_ks);
    cudaGetSymbolAddress((void**)&Gam, g_gamma);

    const size_t HQ = (size_t)BB * MM * DD;
    const size_t HS = (size_t)BB * NN * DD;
    const size_t WW = (size_t)DD * DD;

    cudaFuncSetAttribute(mma_gemm<0>, cudaFuncAttributeMaxDynamicSharedMemorySize, SMEM_GEMM);
    cudaFuncSetAttribute(mma_gemm<1>, cudaFuncAttributeMaxDynamicSharedMemorySize, SMEM_GEMM);

    // 1) LayerNorm + splits
    ln_split<<<BB * MM, 128>>>(Hq, lnw, lnb, hqB, hqB + HQ, hqB + 2 * HQ);
    ln_split<<<BB * NN, 128>>>(Hs, lnw, lnb, hsB, hsB + HS, hsB + 2 * HS);
    split3<<<(int)((WW + 255) / 256), 256>>>(WQ, wqB, wqB + WW, wqB + 2 * WW, (int)WW);
    split3<<<(int)((WW + 255) / 256), 256>>>(WK, wkB, wkB + WW, wkB + 2 * WW, (int)WW);

    // 2) priors
    prior_kernel<<<BB, 256>>>(ys);

    // 3) projections: Q = Hq_ln @ WQ^T, K = Hs_ln @ WK^T (bf16-split outputs)
    mma_gemm<0><<<dim3(DD / 128, (BB * MM) / 128, 1), NTHR, SMEM_GEMM>>>(
        hqB, hqB + HQ, hqB + 2 * HQ, wqB, wqB + WW, wqB + 2 * WW,
        0, 0, nullptr, 0, 0, qB, qB + HQ, qB + 2 * HQ, nullptr, nullptr);
    mma_gemm<0><<<dim3(DD / 128, (BB * NN) / 128, 1), NTHR, SMEM_GEMM>>>(
        hsB, hsB + HS, hsB + 2 * HS, wkB, wkB + WW, wkB + 2 * WW,
        0, 0, nullptr, 0, 0, kB, kB + HS, kB + 2 * HS, nullptr, nullptr);

    // 4) gamma = sigmoid(tau * Q K^T + bias)
    mma_gemm<1><<<dim3(NN / 128, MM / 128, BB), NTHR, SMEM_GEMM>>>(
        qB, qB + HQ, qB + 2 * HQ, kB, kB + HS, kB + 2 * HS,
        (size_t)MM * DD, (size_t)NN * DD, Gam, (size_t)MM * NN, NN,
        nullptr, nullptr, nullptr, taup, bisp);

    // 5) top-k select + aggregate + normalize
    select_agg<<<dim3(MM, BB), 256>>>(ys, out);
}

// round 11
// speedup vs baseline: 1.2980x; 1.1812x over previous
#include <cuda_runtime.h>
#include <cuda_bf16.h>
#include <cstdint>

#define BB 4
#define NN 4096
#define MM 2048
#define DD 512
#define CC 10
#define KTOP 64u

// ---------------- scratch (device globals; no cudaMalloc allowed) ----------------
__device__ __align__(256) __nv_bfloat16 g_hq[3][BB * MM * DD];
__device__ __align__(256) __nv_bfloat16 g_hs[3][BB * NN * DD];
__device__ __align__(256) __nv_bfloat16 g_wq[3][DD * DD];
__device__ __align__(256) __nv_bfloat16 g_wk[3][DD * DD];
__device__ __align__(256) __nv_bfloat16 g_qs[3][BB * MM * DD];
__device__ __align__(256) __nv_bfloat16 g_ks[3][BB * NN * DD];
__device__ float g_gamma[(size_t)BB * MM * NN];
__device__ float g_prior[BB * CC];
__device__ float g_rhoinv[BB * CC];

// ---------------- helpers ----------------
__device__ __forceinline__ uint32_t smem_u32(const void* p) {
    uint32_t a;
    asm("{ .reg .u64 t; cvta.to.shared.u64 t, %1; cvt.u32.u64 %0, t; }" : "=r"(a) : "l"(p));
    return a;
}

#define CP16(dst, src) \
    asm volatile("cp.async.cg.shared.global [%0], [%1], 16;" :: "r"(dst), "l"(src))
#define CP_COMMIT() asm volatile("cp.async.commit_group;" ::: "memory")
#define CP_WAIT2()  asm volatile("cp.async.wait_group 2;" ::: "memory")
#define CP_WAIT0()  asm volatile("cp.async.wait_group 0;" ::: "memory")

#define LDSM4(r0, r1, r2, r3, addr) \
    asm volatile("ldmatrix.sync.aligned.m8n8.x4.shared.b16 {%0,%1,%2,%3}, [%4];" \
                 : "=r"(r0), "=r"(r1), "=r"(r2), "=r"(r3) : "r"(addr))

#define MMA16816(d, a, b0, b1) \
    asm volatile("mma.sync.aligned.m16n8k16.row.col.f32.bf16.bf16.f32 " \
                 "{%0,%1,%2,%3}, {%4,%5,%6,%7}, {%8,%9}, {%0,%1,%2,%3};" \
                 : "+f"((d)[0]), "+f"((d)[1]), "+f"((d)[2]), "+f"((d)[3]) \
                 : "r"((a)[0]), "r"((a)[1]), "r"((a)[2]), "r"((a)[3]), "r"(b0), "r"(b1))

// ---------------- LayerNorm fused with 3-way bf16 split ----------------
__global__ void ln_split(const float* __restrict__ x, const float* __restrict__ w,
                         const float* __restrict__ b,
                         __nv_bfloat16* __restrict__ o0, __nv_bfloat16* __restrict__ o1,
                         __nv_bfloat16* __restrict__ o2) {
    int row = blockIdx.x;
    const float* xr = x + (size_t)row * DD;
    int t = threadIdx.x;
    float v[4];
    float s = 0.f, s2 = 0.f;
#pragma unroll
    for (int i = 0; i < 4; i++) {
        v[i] = xr[t + i * 128];
        s += v[i];
        s2 += v[i] * v[i];
    }
#pragma unroll
    for (int o = 16; o > 0; o >>= 1) {
        s  += __shfl_down_sync(0xFFFFFFFFu, s, o);
        s2 += __shfl_down_sync(0xFFFFFFFFu, s2, o);
    }
    __shared__ float ps[4], ps2[4];
    if ((t & 31) == 0) { ps[t >> 5] = s; ps2[t >> 5] = s2; }
    __syncthreads();
    s  = ps[0] + ps[1] + ps[2] + ps[3];
    s2 = ps2[0] + ps2[1] + ps2[2] + ps2[3];
    float mu  = s * (1.f / DD);
    float var = s2 * (1.f / DD) - mu * mu;
    float rs  = 1.f / sqrtf(var + 1e-5f);
#pragma unroll
    for (int i = 0; i < 4; i++) {
        int c = t + i * 128;
        float val = (v[i] - mu) * rs * w[c] + b[c];
        __nv_bfloat16 h0 = __float2bfloat16_rn(val);
        float r1 = val - __bfloat162float(h0);
        __nv_bfloat16 h1 = __float2bfloat16_rn(r1);
        float r2 = r1 - __bfloat162float(h1);
        __nv_bfloat16 h2 = __float2bfloat16_rn(r2);
        size_t oi = (size_t)row * DD + c;
        o0[oi] = h0; o1[oi] = h1; o2[oi] = h2;
    }
}

__global__ void split3(const float* __restrict__ x, __nv_bfloat16* __restrict__ o0,
                       __nv_bfloat16* __restrict__ o1, __nv_bfloat16* __restrict__ o2, int n) {
    int i = blockIdx.x * 256 + threadIdx.x;
    if (i < n) {
        float v = x[i];
        __nv_bfloat16 h0 = __float2bfloat16_rn(v);
        float r1 = v - __bfloat162float(h0);
        __nv_bfloat16 h1 = __float2bfloat16_rn(r1);
        float r2 = r1 - __bfloat162float(h1);
        __nv_bfloat16 h2 = __float2bfloat16_rn(r2);
        o0[i] = h0; o1[i] = h1; o2[i] = h2;
    }
}

// ---------------- mma.sync bf16 GEMM: C = A @ B^T ----------------
// MODE 0 (projections): 6 products, small-first {a0b2,a2b0,a1b1,a0b1,a1b0,a0b0}, 96 chunks.
// MODE 1 (logits): 3 products {a0b1,a1b0,a0b0}, 48 chunks; boundary corrected in select_agg.
#define KT 32
#define ROWB 80
#define TILE10 (128 * ROWB)
#define STAGE_B (2 * TILE10)
#define SMEM_GEMM (4 * STAGE_B)      // 81920 B (x2 CTAs = 163840 < 227KB)
#define NTHR 256

template <int MODE>
__global__ void __launch_bounds__(NTHR, 2) mma_gemm(
    const __nv_bfloat16* __restrict__ A0, const __nv_bfloat16* __restrict__ A1,
    const __nv_bfloat16* __restrict__ A2,
    const __nv_bfloat16* __restrict__ B0, const __nv_bfloat16* __restrict__ B1,
    const __nv_bfloat16* __restrict__ B2,
    size_t sA, size_t sB,
    float* __restrict__ gout, size_t sC, int ldc,
    __nv_bfloat16* __restrict__ o0, __nv_bfloat16* __restrict__ o1,
    __nv_bfloat16* __restrict__ o2,
    const float* __restrict__ taup, const float* __restrict__ biasp) {
    extern __shared__ __align__(128) char smem[];
    const int NCHUNK_M = (MODE == 1) ? 48 : 96;
    const int tid  = threadIdx.x;
    const int lane = tid & 31, warp = tid >> 5;
    const int wm = warp >> 2, wn = warp & 3;
    const int m0 = blockIdx.y * 128, n0 = blockIdx.x * 128;

    const __nv_bfloat16* Abase = A0 + (size_t)blockIdx.z * sA + (size_t)m0 * DD;
    const __nv_bfloat16* Bbase = B0 + (size_t)blockIdx.z * sB + (size_t)n0 * DD;
    const uint32_t da1 = (uint32_t)(A1 - A0), da2 = (uint32_t)(A2 - A0);
    const uint32_t db1 = (uint32_t)(B1 - B0), db2 = (uint32_t)(B2 - B0);

    const uint32_t sbase = smem_u32(smem);
    const int r0i = tid >> 2, c0i = tid & 3;
    const int r1i = r0i + 64;

    const uint32_t aRowOff = (uint32_t)(((lane & 7) + (lane & 8)) * ROWB + (lane & 16));
    const uint32_t bRowOff = (uint32_t)(((lane & 7) + ((lane & 16) >> 1)) * ROWB + ((lane & 8) << 1));

    float acc[4][4][4];
#pragma unroll
    for (int i = 0; i < 4; i++)
#pragma unroll
        for (int j = 0; j < 4; j++)
#pragma unroll
            for (int q = 0; q < 4; q++) acc[i][j][q] = 0.f;

    auto issue = [&](int c) {
        int seg = c >> 4, k0 = (c & 15) * KT;
        uint32_t oa, ob;
        if (MODE == 1) {
            oa = (seg == 1) ? da1 : 0u;
            ob = (seg == 0) ? db1 : 0u;
        } else {
            oa = (seg == 1) ? da2 : ((seg == 2) || (seg == 4)) ? da1 : 0u;
            ob = (seg == 0) ? db2 : ((seg == 2) || (seg == 3)) ? db1 : 0u;
        }
        uint32_t sb0 = sbase + (c & 3) * STAGE_B;
        const __nv_bfloat16* ap = Abase + oa + k0;
        const __nv_bfloat16* bp = Bbase + ob + k0;
        CP16(sb0 + (uint32_t)(r0i * ROWB + c0i * 16), ap + (size_t)r0i * DD + c0i * 8);
        CP16(sb0 + (uint32_t)(r1i * ROWB + c0i * 16), ap + (size_t)r1i * DD + c0i * 8);
        uint32_t sb1 = sb0 + TILE10;
        CP16(sb1 + (uint32_t)(r0i * ROWB + c0i * 16), bp + (size_t)r0i * DD + c0i * 8);
        CP16(sb1 + (uint32_t)(r1i * ROWB + c0i * 16), bp + (size_t)r1i * DD + c0i * 8);
    };

    issue(0); CP_COMMIT();
    issue(1); CP_COMMIT();
    issue(2); CP_COMMIT();

    for (int c = 0; c < NCHUNK_M; c++) {
        CP_WAIT2();
        __syncthreads();
        int cn = c + 3;
        if (cn < NCHUNK_M) issue(cn);
        CP_COMMIT();

        uint32_t sa = sbase + (c & 3) * STAGE_B;
        uint32_t sb = sa + TILE10;
#pragma unroll
        for (int k16 = 0; k16 < 2; k16++) {
            uint32_t a[4][4];
#pragma unroll
            for (int mt = 0; mt < 4; mt++) {
                uint32_t addr = sa + (uint32_t)((wm * 64 + mt * 16) * ROWB) + aRowOff + k16 * 32;
                LDSM4(a[mt][0], a[mt][1], a[mt][2], a[mt][3], addr);
            }
            uint32_t bfr[2][4];
#pragma unroll
            for (int nt2 = 0; nt2 < 2; nt2++) {
                uint32_t addr = sb + (uint32_t)((wn * 32 + nt2 * 16) * ROWB) + bRowOff + k16 * 32;
                LDSM4(bfr[nt2][0], bfr[nt2][1], bfr[nt2][2], bfr[nt2][3], addr);
            }
#pragma unroll
            for (int mt = 0; mt < 4; mt++)
#pragma unroll
                for (int nt = 0; nt < 4; nt++)
                    MMA16816(acc[mt][nt], a[mt], bfr[nt >> 1][(nt & 1) * 2],
                             bfr[nt >> 1][(nt & 1) * 2 + 1]);
        }
    }
    CP_WAIT0();

    const int mrow = lane >> 2, ncol = (lane & 3) * 2;
    if (MODE == 1) {
        float alpha = log1pf(expf(*taup)) + 1e-6f;
        float beta  = *biasp;
        float* Cb = gout + (size_t)blockIdx.z * sC;
#pragma unroll
        for (int mt = 0; mt < 4; mt++) {
#pragma unroll
            for (int half = 0; half < 2; half++) {
                int gr = m0 + wm * 64 + mt * 16 + mrow + half * 8;
                float* crow = Cb + (size_t)gr * ldc + n0 + wn * 32 + ncol;
#pragma unroll
                for (int nt = 0; nt < 4; nt++) {
                    float2 f;
                    f.x = 1.f / (1.f + expf(-(alpha * acc[mt][nt][half * 2 + 0] + beta)));
                    f.y = 1.f / (1.f + expf(-(alpha * acc[mt][nt][half * 2 + 1] + beta)));
                    *reinterpret_cast<float2*>(crow + nt * 8) = f;
                }
            }
        }
    } else {
#pragma unroll
        for (int mt = 0; mt < 4; mt++) {
#pragma unroll
            for (int half = 0; half < 2; half++) {
                int gr = m0 + wm * 64 + mt * 16 + mrow + half * 8;
                size_t base = (size_t)gr * DD + n0 + wn * 32 + ncol;
#pragma unroll
                for (int nt = 0; nt < 4; nt++) {
                    float vx = acc[mt][nt][half * 2 + 0];
                    float vy = acc[mt][nt][half * 2 + 1];
                    __nv_bfloat162 h0v, h1v, h2v;
                    __nv_bfloat16 x0 = __float2bfloat16_rn(vx);
                    float x1f = vx - __bfloat162float(x0);
                    __nv_bfloat16 x1 = __float2bfloat16_rn(x1f);
                    __nv_bfloat16 x2 = __float2bfloat16_rn(x1f - __bfloat162float(x1));
                    __nv_bfloat16 y0 = __float2bfloat16_rn(vy);
                    float y1f = vy - __bfloat162float(y0);
                    __nv_bfloat16 y1 = __float2bfloat16_rn(y1f);
                    __nv_bfloat16 y2 = __float2bfloat16_rn(y1f - __bfloat162float(y1));
                    h0v.x = x0; h0v.y = y0;
                    h1v.x = x1; h1v.y = y1;
                    h2v.x = x2; h2v.y = y2;
                    *reinterpret_cast<__nv_bfloat162*>(o0 + base + nt * 8) = h0v;
                    *reinterpret_cast<__nv_bfloat162*>(o1 + base + nt * 8) = h1v;
                    *reinterpret_cast<__nv_bfloat162*>(o2 + base + nt * 8) = h2v;
                }
            }
        }
    }
}

// ---------------- prior / rho-inverse per batch ----------------
__global__ void prior_kernel(const int* __restrict__ y) {
    int b = blockIdx.x;
    __shared__ int cnt[CC];
    int t = threadIdx.x;
    if (t < CC) cnt[t] = 0;
    __syncthreads();
    for (int i = t; i < NN; i += 256) atomicAdd(&cnt[y[(size_t)b * NN + i]], 1);
    __syncthreads();
    if (t == 0) {
        int tot = 0;
        for (int c = 0; c < CC; c++) tot += cnt[c];
        float denom = fmaxf((float)tot, 1.f);
        for (int c = 0; c < CC; c++) {
            float pr = (float)cnt[c] / denom;
            g_prior[b * CC + c]  = pr;
            g_rhoinv[b * CC + c] = 1.f / fmaxf(1.f - pr, 1e-6f);
        }
    }
}

// ---------------- top-k select (ref-faithful boundary fix-up) + aggregation ----------------
__device__ __forceinline__ unsigned f2u(float f) {
    unsigned u = __float_as_uint(f);
    return (u & 0x80000000u) ? ~u : (u | 0x80000000u);
}

#define BAND_CAP 64
#define BAND_DELTA 2e-5f

__global__ void select_agg(const int* __restrict__ y,
                           const __nv_bfloat16* __restrict__ q0, const __nv_bfloat16* __restrict__ q1,
                           const __nv_bfloat16* __restrict__ q2,
                           const __nv_bfloat16* __restrict__ k0, const __nv_bfloat16* __restrict__ k1,
                           const __nv_bfloat16* __restrict__ k2,
                           const float* __restrict__ taup, const float* __restrict__ biasp,
                           float* __restrict__ out) {
    int m = blockIdx.x, b = blockIdx.y;
    const float* grow = g_gamma + ((size_t)b * MM + m) * NN;
    __shared__ float gs[NN];
    __shared__ unsigned short cand[NN];
    __shared__ unsigned whist[8][256];
    __shared__ unsigned hist[256];
    __shared__ unsigned sh_pref, sh_k, sh_nc;
    __shared__ float S[CC], W[CC], sh_prior[CC], sh_rinv[CC];
    __shared__ unsigned cntk;
    __shared__ unsigned sh_above, sh_nb, sh_kept;
    __shared__ unsigned short bandIdx[BAND_CAP];
    __shared__ unsigned char bandKeep[BAND_CAP];
    __shared__ double Lband[BAND_CAP];
    __shared__ float Gband[BAND_CAP];
    const int t = threadIdx.x;
    const int warp = t >> 5, lane = t & 31;

    for (int i = t; i < NN / 4; i += 256)
        reinterpret_cast<float4*>(gs)[i] = reinterpret_cast<const float4*>(grow)[i];
    for (int i = t; i < 8 * 256; i += 256) (&whist[0][0])[i] = 0u;
    if (t < CC) {
        S[t] = 0.f; W[t] = 0.f;
        sh_prior[t] = g_prior[b * CC + t];
        sh_rinv[t]  = g_rhoinv[b * CC + t];
    }
    if (t == 0) { cntk = 0; sh_nc = 0; sh_above = 0; sh_nb = 0; sh_kept = 0; }
    __syncthreads();

    // ---- radix select exact 64th-largest of gamma~ ----
    for (int i = t; i < NN; i += 256)
        atomicAdd(&whist[warp][f2u(gs[i]) >> 24], 1u);
    __syncthreads();
    {
        unsigned h = 0;
#pragma unroll
        for (int w = 0; w < 8; w++) h += whist[w][t];
        hist[t] = h;
    }
    __syncthreads();
    if (t == 0) {
        unsigned acc = 0, krem = KTOP;
        int bin = 0;
        for (int i = 255; i >= 0; i--) {
            unsigned h = hist[i];
            if (acc + h >= KTOP) { bin = i; krem = KTOP - acc; break; }
            acc += h;
        }
        sh_pref = (unsigned)bin << 24;
        sh_k = krem;
    }
    __syncthreads();
    unsigned prefix = sh_pref;

    for (int i = t; i < NN; i += 256) {
        if ((f2u(gs[i]) & 0xFF000000u) == prefix) {
            unsigned idx = atomicAdd(&sh_nc, 1u);
            cand[idx] = (unsigned short)i;
        }
    }
    __syncthreads();
    const int ncand = (int)sh_nc;

#pragma unroll
    for (int shift = 16; shift >= 0; shift -= 8) {
        hist[t] = 0;
        __syncthreads();
        unsigned pm = 0xFFFFFFFFu << (shift + 8);
        for (int j = t; j < ncand; j += 256) {
            unsigned u = f2u(gs[cand[j]]);
            if ((u & pm) == prefix) atomicAdd(&hist[(u >> shift) & 255u], 1u);
        }
        __syncthreads();
        if (t == 0) {
            unsigned kneed = sh_k, acc = 0, krem = kneed;
            int bin = 0;
            for (int i = 255; i >= 0; i--) {
                unsigned h = hist[i];
                if (acc + h >= kneed) { bin = i; krem = kneed - acc; break; }
                acc += h;
            }
            sh_pref = prefix | ((unsigned)bin << shift);
            sh_k = krem;
        }
        __syncthreads();
        prefix = sh_pref;
    }
    const float v64f = __uint_as_float(prefix & 0x7FFFFFFFu);
    const float hi = v64f + BAND_DELTA;
    const float lo = v64f - BAND_DELTA;

    // ---- definite members + boundary band ----
    for (int i = t; i < NN; i += 256) {
        float g = gs[i];
        if (g > hi) {
            atomicAdd(&sh_above, 1u);
        } else if (g >= lo) {
            unsigned idx = atomicAdd(&sh_nb, 1u);
            if (idx < BAND_CAP) bandIdx[idx] = (unsigned short)i;
        }
    }
    __syncthreads();
    const int above = (int)sh_above;
    const int nb = (int)sh_nb;
    const int need = (int)KTOP - above;
    const bool fallback = (nb > BAND_CAP);
    const int* yrow = y + (size_t)b * NN;

    if (!fallback) {
        if (nb > need) {
            // fp64 exact dot of band members from bf16x3 Q/K splits
            const size_t qoff = ((size_t)b * MM + m) * DD;
            const __nv_bfloat16* qr0 = q0 + qoff;
            const __nv_bfloat16* qr1 = q1 + qoff;
            const __nv_bfloat16* qr2 = q2 + qoff;
            for (int j = warp; j < nb; j += 8) {
                int n = bandIdx[j];
                const size_t koff = ((size_t)b * NN + n) * DD;
                double acc = 0.0;
                for (int e = lane; e < DD; e += 32) {
                    double qd = (double)__bfloat162float(qr0[e]) +
                                (double)__bfloat162float(qr1[e]) +
                                (double)__bfloat162float(qr2[e]);
                    double kd = (double)__bfloat162float(k0[koff + e]) +
                                (double)__bfloat162float(k1[koff + e]) +
                                (double)__bfloat162float(k2[koff + e]);
                    acc = fma(qd, kd, acc);
                }
#pragma unroll
                for (int o = 16; o > 0; o >>= 1)
                    acc += __shfl_down_sync(0xFFFFFFFFu, acc, o);
                if (lane == 0) Lband[j] = acc;
            }
            __syncthreads();
            // reference-style fp32 gamma of band members (replicates fp32 ties)
            if (t < nb) {
                float alpha = log1pf(expf(*taup)) + 1e-6f;
                float beta  = *biasp;
                float dotf = (float)Lband[t];
                float l = __fadd_rn(__fmul_rn(alpha, dotf), beta);
                Gband[t] = 1.f / (1.f + expf(-l));
            }
            __syncthreads();
            // reference semantics: keep all with gamma >= (need-th largest), ties included
            if (t < nb) {
                float gt = Gband[t];
                int rank = 0;
                for (int j = 0; j < nb; j++) rank += (Gband[j] > gt);
                unsigned char kp = (rank < need) ? 1 : 0;
                bandKeep[t] = kp;
                if (kp) atomicAdd(&sh_kept, 1u);
            }
            __syncthreads();
            for (int j = t; j < nb; j += 256) {
                if (bandKeep[j]) {
                    int i = bandIdx[j];
                    float g = Gband[j];
                    int c = yrow[i];
                    atomicAdd(&S[c], g);
                    atomicAdd(&W[c], (1.f - g) * sh_rinv[c]);
                }
            }
            if (t == 0) cntk = (unsigned)above + sh_kept;
        } else {
            for (int j = t; j < nb; j += 256) {
                int i = bandIdx[j];
                float g = gs[i];
                int c = yrow[i];
                atomicAdd(&S[c], g);
                atomicAdd(&W[c], (1.f - g) * sh_rinv[c]);
            }
            if (t == 0) cntk = (unsigned)(above + nb);
        }
        __syncthreads();
        // definite members
        for (int i = t; i < NN; i += 256) {
            float g = gs[i];
            if (g > hi) {
                int c = yrow[i];
                atomicAdd(&S[c], g);
                atomicAdd(&W[c], (1.f - g) * sh_rinv[c]);
            }
        }
        __syncthreads();
    } else {
        for (int i = t; i < NN; i += 256) {
            float g = gs[i];
            if (f2u(g) >= prefix) {
                int c = yrow[i];
                atomicAdd(&S[c], g);
                atomicAdd(&W[c], (1.f - g) * sh_rinv[c]);
                atomicAdd(&cntk, 1u);
            }
        }
        __syncthreads();
    }

    if (t == 0) {
        float Wt = 0.f;
        for (int c = 0; c < CC; c++) Wt += W[c];
        float dq = fmaxf((float)cntk, 1.f);
        float p[CC];
        float sum = 0.f;
        for (int c = 0; c < CC; c++) {
            float v = S[c] + sh_prior[c] * (Wt - W[c]);
            v = fmaxf(v, 0.f) / dq;
            p[c] = v;
            sum += v;
        }
        float inv = 1.f / fmaxf(sum, 1e-12f);
        float* orow = out + ((size_t)b * MM + m) * CC;
        for (int c = 0; c < CC; c++) orow[c] = p[c] * inv;
    }
}

// ---------------- launcher ----------------
extern "C" void kernel_launch(void* const* d_in, const int* in_sizes, int n_in,
                              void* d_out, int out_size) {
    const float* Hs   = (const float*)d_in[0];
    const float* Hq   = (const float*)d_in[1];
    const int*   ys   = (const int*)d_in[2];
    const float* lnw  = (const float*)d_in[4];
    const float* lnb  = (const float*)d_in[5];
    const float* WQ   = (const float*)d_in[6];
    const float* WK   = (const float*)d_in[7];
    const float* taup = (const float*)d_in[8];
    const float* bisp = (const float*)d_in[9];
    float* out = (float*)d_out;

    __nv_bfloat16 *hqB, *hsB, *wqB, *wkB, *qB, *kB;
    float* Gam;
    cudaGetSymbolAddress((void**)&hqB, g_hq);
    cudaGetSymbolAddress((void**)&hsB, g_hs);
    cudaGetSymbolAddress((void**)&wqB, g_wq);
    cudaGetSymbolAddress((void**)&wkB, g_wk);
    cudaGetSymbolAddress((void**)&qB, g_qs);
    cudaGetSymbolAddress((void**)&kB, g_ks);
    cudaGetSymbolAddress((void**)&Gam, g_gamma);

    const size_t HQ = (size_t)BB * MM * DD;
    const size_t HS = (size_t)BB * NN * DD;
    const size_t WW = (size_t)DD * DD;

    cudaFuncSetAttribute(mma_gemm<0>, cudaFuncAttributeMaxDynamicSharedMemorySize, SMEM_GEMM);
    cudaFuncSetAttribute(mma_gemm<1>, cudaFuncAttributeMaxDynamicSharedMemorySize, SMEM_GEMM);

    // 1) LayerNorm + splits
    ln_split<<<BB * MM, 128>>>(Hq, lnw, lnb, hqB, hqB + HQ, hqB + 2 * HQ);
    ln_split<<<BB * NN, 128>>>(Hs, lnw, lnb, hsB, hsB + HS, hsB + 2 * HS);
    split3<<<(int)((WW + 255) / 256), 256>>>(WQ, wqB, wqB + WW, wqB + 2 * WW, (int)WW);
    split3<<<(int)((WW + 255) / 256), 256>>>(WK, wkB, wkB + WW, wkB + 2 * WW, (int)WW);

    // 2) priors
    prior_kernel<<<BB, 256>>>(ys);

    // 3) projections (6-product exact, bf16-split outputs)
    mma_gemm<0><<<dim3(DD / 128, (BB * MM) / 128, 1), NTHR, SMEM_GEMM>>>(
        hqB, hqB + HQ, hqB + 2 * HQ, wqB, wqB + WW, wqB + 2 * WW,
        0, 0, nullptr, 0, 0, qB, qB + HQ, qB + 2 * HQ, nullptr, nullptr);
    mma_gemm<0><<<dim3(DD / 128, (BB * NN) / 128, 1), NTHR, SMEM_GEMM>>>(
        hsB, hsB + HS, hsB + 2 * HS, wkB, wkB + WW, wkB + 2 * WW,
        0, 0, nullptr, 0, 0, kB, kB + HS, kB + 2 * HS, nullptr, nullptr);

    // 4) gamma~ = sigmoid(tau * [3-product Q K^T] + bias)
    mma_gemm<1><<<dim3(NN / 128, MM / 128, BB), NTHR, SMEM_GEMM>>>(
        qB, qB + HQ, qB + 2 * HQ, kB, kB + HS, kB + 2 * HS,
        (size_t)MM * DD, (size_t)NN * DD, Gam, (size_t)MM * NN, NN,
        nullptr, nullptr, nullptr, taup, bisp);

    // 5) top-k select (ref-faithful boundary fix-up) + aggregate + normalize
    select_agg<<<dim3(MM, BB), 256>>>(ys, qB, qB + HQ, qB + 2 * HQ,
                                      kB, kB + HS, kB + 2 * HS, taup, bisp, out);
}

// round 13
// speedup vs baseline: 1.5848x; 1.2210x over previous
#include <cuda_runtime.h>
#include <cuda_bf16.h>
#include <cuda_fp16.h>
#include <cstdint>

#define BB 4
#define NN 4096
#define MM 2048
#define DD 512
#define CC 10
#define KTOP 64u

// ---------------- scratch (device globals; no cudaMalloc allowed) ----------------
__device__ __align__(256) __nv_bfloat16 g_hq[3][BB * MM * DD];
__device__ __align__(256) __nv_bfloat16 g_hs[3][BB * NN * DD];
__device__ __align__(256) __nv_bfloat16 g_wq[3][DD * DD];
__device__ __align__(256) __nv_bfloat16 g_wk[3][DD * DD];
__device__ __align__(256) __nv_bfloat16 g_qs[3][BB * MM * DD];
__device__ __align__(256) __nv_bfloat16 g_ks[3][BB * NN * DD];
__device__ __align__(256) __half g_qh[BB * MM * DD];
__device__ __align__(256) __half g_kh[BB * NN * DD];
__device__ float g_gamma[(size_t)BB * MM * NN];
__device__ float g_prior[BB * CC];
__device__ float g_rhoinv[BB * CC];

// ---------------- helpers ----------------
__device__ __forceinline__ uint32_t smem_u32(const void* p) {
    uint32_t a;
    asm("{ .reg .u64 t; cvta.to.shared.u64 t, %1; cvt.u32.u64 %0, t; }" : "=r"(a) : "l"(p));
    return a;
}

#define CP16(dst, src) \
    asm volatile("cp.async.cg.shared.global [%0], [%1], 16;" :: "r"(dst), "l"(src))
#define CP_COMMIT() asm volatile("cp.async.commit_group;" ::: "memory")
#define CP_WAIT2()  asm volatile("cp.async.wait_group 2;" ::: "memory")
#define CP_WAIT0()  asm volatile("cp.async.wait_group 0;" ::: "memory")

#define LDSM4(r0, r1, r2, r3, addr) \
    asm volatile("ldmatrix.sync.aligned.m8n8.x4.shared.b16 {%0,%1,%2,%3}, [%4];" \
                 : "=r"(r0), "=r"(r1), "=r"(r2), "=r"(r3) : "r"(addr))

#define MMA_BF16(d, a, b0, b1) \
    asm volatile("mma.sync.aligned.m16n8k16.row.col.f32.bf16.bf16.f32 " \
                 "{%0,%1,%2,%3}, {%4,%5,%6,%7}, {%8,%9}, {%0,%1,%2,%3};" \
                 : "+f"((d)[0]), "+f"((d)[1]), "+f"((d)[2]), "+f"((d)[3]) \
                 : "r"((a)[0]), "r"((a)[1]), "r"((a)[2]), "r"((a)[3]), "r"(b0), "r"(b1))

#define MMA_FP16(d, a, b0, b1) \
    asm volatile("mma.sync.aligned.m16n8k16.row.col.f32.f16.f16.f32 " \
                 "{%0,%1,%2,%3}, {%4,%5,%6,%7}, {%8,%9}, {%0,%1,%2,%3};" \
                 : "+f"((d)[0]), "+f"((d)[1]), "+f"((d)[2]), "+f"((d)[3]) \
                 : "r"((a)[0]), "r"((a)[1]), "r"((a)[2]), "r"((a)[3]), "r"(b0), "r"(b1))

// ---------------- LayerNorm fused with 3-way bf16 split ----------------
__global__ void ln_split(const float* __restrict__ x, const float* __restrict__ w,
                         const float* __restrict__ b,
                         __nv_bfloat16* __restrict__ o0, __nv_bfloat16* __restrict__ o1,
                         __nv_bfloat16* __restrict__ o2) {
    int row = blockIdx.x;
    const float* xr = x + (size_t)row * DD;
    int t = threadIdx.x;
    float v[4];
    float s = 0.f, s2 = 0.f;
#pragma unroll
    for (int i = 0; i < 4; i++) {
        v[i] = xr[t + i * 128];
        s += v[i];
        s2 += v[i] * v[i];
    }
#pragma unroll
    for (int o = 16; o > 0; o >>= 1) {
        s  += __shfl_down_sync(0xFFFFFFFFu, s, o);
        s2 += __shfl_down_sync(0xFFFFFFFFu, s2, o);
    }
    __shared__ float ps[4], ps2[4];
    if ((t & 31) == 0) { ps[t >> 5] = s; ps2[t >> 5] = s2; }
    __syncthreads();
    s  = ps[0] + ps[1] + ps[2] + ps[3];
    s2 = ps2[0] + ps2[1] + ps2[2] + ps2[3];
    float mu  = s * (1.f / DD);
    float var = s2 * (1.f / DD) - mu * mu;
    float rs  = 1.f / sqrtf(var + 1e-5f);
#pragma unroll
    for (int i = 0; i < 4; i++) {
        int c = t + i * 128;
        float val = (v[i] - mu) * rs * w[c] + b[c];
        __nv_bfloat16 h0 = __float2bfloat16_rn(val);
        float r1 = val - __bfloat162float(h0);
        __nv_bfloat16 h1 = __float2bfloat16_rn(r1);
        float r2 = r1 - __bfloat162float(h1);
        __nv_bfloat16 h2 = __float2bfloat16_rn(r2);
        size_t oi = (size_t)row * DD + c;
        o0[oi] = h0; o1[oi] = h1; o2[oi] = h2;
    }
}

__global__ void split3(const float* __restrict__ x, __nv_bfloat16* __restrict__ o0,
                       __nv_bfloat16* __restrict__ o1, __nv_bfloat16* __restrict__ o2, int n) {
    int i = blockIdx.x * 256 + threadIdx.x;
    if (i < n) {
        float v = x[i];
        __nv_bfloat16 h0 = __float2bfloat16_rn(v);
        float r1 = v - __bfloat162float(h0);
        __nv_bfloat16 h1 = __float2bfloat16_rn(r1);
        float r2 = r1 - __bfloat162float(h1);
        __nv_bfloat16 h2 = __float2bfloat16_rn(r2);
        o0[i] = h0; o1[i] = h1; o2[i] = h2;
    }
}

// bf16x3 -> fp16 (round of fp32 sum)
__global__ void to_half(const __nv_bfloat16* __restrict__ a0,
                        const __nv_bfloat16* __restrict__ a1,
                        const __nv_bfloat16* __restrict__ a2,
                        __half* __restrict__ o, int n) {
    int i = blockIdx.x * 256 + threadIdx.x;
    if (i < n) {
        float v = __bfloat162float(a0[i]) + __bfloat162float(a1[i]) + __bfloat162float(a2[i]);
        o[i] = __float2half_rn(v);
    }
}

// ---------------- tiling constants ----------------
#define KT 32
#define ROWB 80
#define TILE10 (128 * ROWB)
#define STAGE_B (2 * TILE10)
#define SMEM_GEMM (4 * STAGE_B)      // 81920 B (x2 CTAs = 163840 < 227KB)
#define NTHR 256

// ---------------- projection GEMM (bf16x3, 6-product, round-11 bit-identical) ----------------
__global__ void __launch_bounds__(NTHR, 2) mma_proj(
    const __nv_bfloat16* __restrict__ A0, const __nv_bfloat16* __restrict__ A1,
    const __nv_bfloat16* __restrict__ A2,
    const __nv_bfloat16* __restrict__ B0, const __nv_bfloat16* __restrict__ B1,
    const __nv_bfloat16* __restrict__ B2,
    __nv_bfloat16* __restrict__ o0, __nv_bfloat16* __restrict__ o1,
    __nv_bfloat16* __restrict__ o2) {
    extern __shared__ __align__(128) char smem[];
    const int NCHUNK_M = 96;
    const int tid  = threadIdx.x;
    const int lane = tid & 31, warp = tid >> 5;
    const int wm = warp >> 2, wn = warp & 3;
    const int m0 = blockIdx.y * 128, n0 = blockIdx.x * 128;

    const __nv_bfloat16* Abase = A0 + (size_t)m0 * DD;
    const __nv_bfloat16* Bbase = B0 + (size_t)n0 * DD;
    const uint32_t da1 = (uint32_t)(A1 - A0), da2 = (uint32_t)(A2 - A0);
    const uint32_t db1 = (uint32_t)(B1 - B0), db2 = (uint32_t)(B2 - B0);

    const uint32_t sbase = smem_u32(smem);
    const int r0i = tid >> 2, c0i = tid & 3;
    const int r1i = r0i + 64;

    const uint32_t aRowOff = (uint32_t)(((lane & 7) + (lane & 8)) * ROWB + (lane & 16));
    const uint32_t bRowOff = (uint32_t)(((lane & 7) + ((lane & 16) >> 1)) * ROWB + ((lane & 8) << 1));

    float acc[4][4][4];
#pragma unroll
    for (int i = 0; i < 4; i++)
#pragma unroll
        for (int j = 0; j < 4; j++)
#pragma unroll
            for (int q = 0; q < 4; q++) acc[i][j][q] = 0.f;

    auto issue = [&](int c) {
        int seg = c >> 4, k0 = (c & 15) * KT;
        // small-first: 0:a0b2 1:a2b0 2:a1b1 3:a0b1 4:a1b0 5:a0b0
        uint32_t oa = (seg == 1) ? da2 : ((seg == 2) || (seg == 4)) ? da1 : 0u;
        uint32_t ob = (seg == 0) ? db2 : ((seg == 2) || (seg == 3)) ? db1 : 0u;
        uint32_t sb0 = sbase + (c & 3) * STAGE_B;
        const __nv_bfloat16* ap = Abase + oa + k0;
        const __nv_bfloat16* bp = Bbase + ob + k0;
        CP16(sb0 + (uint32_t)(r0i * ROWB + c0i * 16), ap + (size_t)r0i * DD + c0i * 8);
        CP16(sb0 + (uint32_t)(r1i * ROWB + c0i * 16), ap + (size_t)r1i * DD + c0i * 8);
        uint32_t sb1 = sb0 + TILE10;
        CP16(sb1 + (uint32_t)(r0i * ROWB + c0i * 16), bp + (size_t)r0i * DD + c0i * 8);
        CP16(sb1 + (uint32_t)(r1i * ROWB + c0i * 16), bp + (size_t)r1i * DD + c0i * 8);
    };

    issue(0); CP_COMMIT();
    issue(1); CP_COMMIT();
    issue(2); CP_COMMIT();

    for (int c = 0; c < NCHUNK_M; c++) {
        CP_WAIT2();
        __syncthreads();
        int cn = c + 3;
        if (cn < NCHUNK_M) issue(cn);
        CP_COMMIT();

        uint32_t sa = sbase + (c & 3) * STAGE_B;
        uint32_t sb = sa + TILE10;
#pragma unroll
        for (int k16 = 0; k16 < 2; k16++) {
            uint32_t a[4][4];
#pragma unroll
            for (int mt = 0; mt < 4; mt++) {
                uint32_t addr = sa + (uint32_t)((wm * 64 + mt * 16) * ROWB) + aRowOff + k16 * 32;
                LDSM4(a[mt][0], a[mt][1], a[mt][2], a[mt][3], addr);
            }
            uint32_t bfr[2][4];
#pragma unroll
            for (int nt2 = 0; nt2 < 2; nt2++) {
                uint32_t addr = sb + (uint32_t)((wn * 32 + nt2 * 16) * ROWB) + bRowOff + k16 * 32;
                LDSM4(bfr[nt2][0], bfr[nt2][1], bfr[nt2][2], bfr[nt2][3], addr);
            }
#pragma unroll
            for (int mt = 0; mt < 4; mt++)
#pragma unroll
                for (int nt = 0; nt < 4; nt++)
                    MMA_BF16(acc[mt][nt], a[mt], bfr[nt >> 1][(nt & 1) * 2],
                             bfr[nt >> 1][(nt & 1) * 2 + 1]);
        }
    }
    CP_WAIT0();

    const int mrow = lane >> 2, ncol = (lane & 3) * 2;
#pragma unroll
    for (int mt = 0; mt < 4; mt++) {
#pragma unroll
        for (int half = 0; half < 2; half++) {
            int gr = m0 + wm * 64 + mt * 16 + mrow + half * 8;
            size_t base = (size_t)gr * DD + n0 + wn * 32 + ncol;
#pragma unroll
            for (int nt = 0; nt < 4; nt++) {
                float vx = acc[mt][nt][half * 2 + 0];
                float vy = acc[mt][nt][half * 2 + 1];
                __nv_bfloat162 h0v, h1v, h2v;
                __nv_bfloat16 x0 = __float2bfloat16_rn(vx);
                float x1f = vx - __bfloat162float(x0);
                __nv_bfloat16 x1 = __float2bfloat16_rn(x1f);
                __nv_bfloat16 x2 = __float2bfloat16_rn(x1f - __bfloat162float(x1));
                __nv_bfloat16 y0 = __float2bfloat16_rn(vy);
                float y1f = vy - __bfloat162float(y0);
                __nv_bfloat16 y1 = __float2bfloat16_rn(y1f);
                __nv_bfloat16 y2 = __float2bfloat16_rn(y1f - __bfloat162float(y1));
                h0v.x = x0; h0v.y = y0;
                h1v.x = x1; h1v.y = y1;
                h2v.x = x2; h2v.y = y2;
                *reinterpret_cast<__nv_bfloat162*>(o0 + base + nt * 8) = h0v;
                *reinterpret_cast<__nv_bfloat162*>(o1 + base + nt * 8) = h1v;
                *reinterpret_cast<__nv_bfloat162*>(o2 + base + nt * 8) = h2v;
            }
        }
    }
}

// ---------------- logits GEMM (fp16 single-product, 16 chunks, sigmoid epilogue) ----------------
__global__ void __launch_bounds__(NTHR, 2) mma_logits(
    const __half* __restrict__ Q, const __half* __restrict__ K,
    float* __restrict__ gout,
    const float* __restrict__ taup, const float* __restrict__ biasp) {
    extern __shared__ __align__(128) char smem[];
    const int NCHUNK_M = 16;
    const int tid  = threadIdx.x;
    const int lane = tid & 31, warp = tid >> 5;
    const int wm = warp >> 2, wn = warp & 3;
    const int m0 = blockIdx.y * 128, n0 = blockIdx.x * 128;

    const __half* Abase = Q + (size_t)blockIdx.z * MM * DD + (size_t)m0 * DD;
    const __half* Bbase = K + (size_t)blockIdx.z * NN * DD + (size_t)n0 * DD;

    const uint32_t sbase = smem_u32(smem);
    const int r0i = tid >> 2, c0i = tid & 3;
    const int r1i = r0i + 64;

    const uint32_t aRowOff = (uint32_t)(((lane & 7) + (lane & 8)) * ROWB + (lane & 16));
    const uint32_t bRowOff = (uint32_t)(((lane & 7) + ((lane & 16) >> 1)) * ROWB + ((lane & 8) << 1));

    float acc[4][4][4];
#pragma unroll
    for (int i = 0; i < 4; i++)
#pragma unroll
        for (int j = 0; j < 4; j++)
#pragma unroll
            for (int q = 0; q < 4; q++) acc[i][j][q] = 0.f;

    auto issue = [&](int c) {
        int k0 = c * KT;
        uint32_t sb0 = sbase + (c & 3) * STAGE_B;
        const __half* ap = Abase + k0;
        const __half* bp = Bbase + k0;
        CP16(sb0 + (uint32_t)(r0i * ROWB + c0i * 16), ap + (size_t)r0i * DD + c0i * 8);
        CP16(sb0 + (uint32_t)(r1i * ROWB + c0i * 16), ap + (size_t)r1i * DD + c0i * 8);
        uint32_t sb1 = sb0 + TILE10;
        CP16(sb1 + (uint32_t)(r0i * ROWB + c0i * 16), bp + (size_t)r0i * DD + c0i * 8);
        CP16(sb1 + (uint32_t)(r1i * ROWB + c0i * 16), bp + (size_t)r1i * DD + c0i * 8);
    };

    issue(0); CP_COMMIT();
    issue(1); CP_COMMIT();
    issue(2); CP_COMMIT();

    for (int c = 0; c < NCHUNK_M; c++) {
        CP_WAIT2();
        __syncthreads();
        int cn = c + 3;
        if (cn < NCHUNK_M) issue(cn);
        CP_COMMIT();

        uint32_t sa = sbase + (c & 3) * STAGE_B;
        uint32_t sb = sa + TILE10;
#pragma unroll
        for (int k16 = 0; k16 < 2; k16++) {
            uint32_t a[4][4];
#pragma unroll
            for (int mt = 0; mt < 4; mt++) {
                uint32_t addr = sa + (uint32_t)((wm * 64 + mt * 16) * ROWB) + aRowOff + k16 * 32;
                LDSM4(a[mt][0], a[mt][1], a[mt][2], a[mt][3], addr);
            }
            uint32_t bfr[2][4];
#pragma unroll
            for (int nt2 = 0; nt2 < 2; nt2++) {
                uint32_t addr = sb + (uint32_t)((wn * 32 + nt2 * 16) * ROWB) + bRowOff + k16 * 32;
                LDSM4(bfr[nt2][0], bfr[nt2][1], bfr[nt2][2], bfr[nt2][3], addr);
            }
#pragma unroll
            for (int mt = 0; mt < 4; mt++)
#pragma unroll
                for (int nt = 0; nt < 4; nt++)
                    MMA_FP16(acc[mt][nt], a[mt], bfr[nt >> 1][(nt & 1) * 2],
                             bfr[nt >> 1][(nt & 1) * 2 + 1]);
        }
    }
    CP_WAIT0();

    const int mrow = lane >> 2, ncol = (lane & 3) * 2;
    float alpha = log1pf(expf(*taup)) + 1e-6f;
    float beta  = *biasp;
    float* Cb = gout + (size_t)blockIdx.z * MM * NN;
#pragma unroll
    for (int mt = 0; mt < 4; mt++) {
#pragma unroll
        for (int half = 0; half < 2; half++) {
            int gr = m0 + wm * 64 + mt * 16 + mrow + half * 8;
            float* crow = Cb + (size_t)gr * NN + n0 + wn * 32 + ncol;
#pragma unroll
            for (int nt = 0; nt < 4; nt++) {
                float2 f;
                f.x = 1.f / (1.f + expf(-(alpha * acc[mt][nt][half * 2 + 0] + beta)));
                f.y = 1.f / (1.f + expf(-(alpha * acc[mt][nt][half * 2 + 1] + beta)));
                *reinterpret_cast<float2*>(crow + nt * 8) = f;
            }
        }
    }
}

// ---------------- prior / rho-inverse per batch ----------------
__global__ void prior_kernel(const int* __restrict__ y) {
    int b = blockIdx.x;
    __shared__ int cnt[CC];
    int t = threadIdx.x;
    if (t < CC) cnt[t] = 0;
    __syncthreads();
    for (int i = t; i < NN; i += 256) atomicAdd(&cnt[y[(size_t)b * NN + i]], 1);
    __syncthreads();
    if (t == 0) {
        int tot = 0;
        for (int c = 0; c < CC; c++) tot += cnt[c];
        float denom = fmaxf((float)tot, 1.f);
        for (int c = 0; c < CC; c++) {
            float pr = (float)cnt[c] / denom;
            g_prior[b * CC + c]  = pr;
            g_rhoinv[b * CC + c] = 1.f / fmaxf(1.f - pr, 1e-6f);
        }
    }
}

// ---------------- top-k select (logit-space band + fp64 fix-up on bf16x3 Q/K) ----------------
__device__ __forceinline__ unsigned f2u(float f) {
    unsigned u = __float_as_uint(f);
    return (u & 0x80000000u) ? ~u : (u | 0x80000000u);
}

#define BAND_CAP 64

__global__ void select_agg(const int* __restrict__ y,
                           const __nv_bfloat16* __restrict__ q0, const __nv_bfloat16* __restrict__ q1,
                           const __nv_bfloat16* __restrict__ q2,
                           const __nv_bfloat16* __restrict__ k0, const __nv_bfloat16* __restrict__ k1,
                           const __nv_bfloat16* __restrict__ k2,
                           const float* __restrict__ taup, const float* __restrict__ biasp,
                           float* __restrict__ out) {
    int m = blockIdx.x, b = blockIdx.y;
    const float* grow = g_gamma + ((size_t)b * MM + m) * NN;
    __shared__ float gs[NN];
    __shared__ unsigned short cand[NN];
    __shared__ unsigned whist[8][256];
    __shared__ unsigned hist[256];
    __shared__ unsigned sh_pref, sh_k, sh_nc;
    __shared__ float S[CC], W[CC], sh_prior[CC], sh_rinv[CC];
    __shared__ unsigned cntk;
    __shared__ unsigned sh_above, sh_nb, sh_kept;
    __shared__ unsigned short bandIdx[BAND_CAP];
    __shared__ unsigned char bandKeep[BAND_CAP];
    __shared__ double Lband[BAND_CAP];
    __shared__ float Gband[BAND_CAP];
    const int t = threadIdx.x;
    const int warp = t >> 5, lane = t & 31;

    for (int i = t; i < NN / 4; i += 256)
        reinterpret_cast<float4*>(gs)[i] = reinterpret_cast<const float4*>(grow)[i];
    for (int i = t; i < 8 * 256; i += 256) (&whist[0][0])[i] = 0u;
    if (t < CC) {
        S[t] = 0.f; W[t] = 0.f;
        sh_prior[t] = g_prior[b * CC + t];
        sh_rinv[t]  = g_rhoinv[b * CC + t];
    }
    if (t == 0) { cntk = 0; sh_nc = 0; sh_above = 0; sh_nb = 0; sh_kept = 0; }
    __syncthreads();

    // ---- radix select exact 64th-largest of gamma~ ----
    for (int i = t; i < NN; i += 256)
        atomicAdd(&whist[warp][f2u(gs[i]) >> 24], 1u);
    __syncthreads();
    {
        unsigned h = 0;
#pragma unroll
        for (int w = 0; w < 8; w++) h += whist[w][t];
        hist[t] = h;
    }
    __syncthreads();
    if (t == 0) {
        unsigned acc = 0, krem = KTOP;
        int bin = 0;
        for (int i = 255; i >= 0; i--) {
            unsigned h = hist[i];
            if (acc + h >= KTOP) { bin = i; krem = KTOP - acc; break; }
            acc += h;
        }
        sh_pref = (unsigned)bin << 24;
        sh_k = krem;
    }
    __syncthreads();
    unsigned prefix = sh_pref;

    for (int i = t; i < NN; i += 256) {
        if ((f2u(gs[i]) & 0xFF000000u) == prefix) {
            unsigned idx = atomicAdd(&sh_nc, 1u);
            cand[idx] = (unsigned short)i;
        }
    }
    __syncthreads();
    const int ncand = (int)sh_nc;

#pragma unroll
    for (int shift = 16; shift >= 0; shift -= 8) {
        hist[t] = 0;
        __syncthreads();
        unsigned pm = 0xFFFFFFFFu << (shift + 8);
        for (int j = t; j < ncand; j += 256) {
            unsigned u = f2u(gs[cand[j]]);
            if ((u & pm) == prefix) atomicAdd(&hist[(u >> shift) & 255u], 1u);
        }
        __syncthreads();
        if (t == 0) {
            unsigned kneed = sh_k, acc = 0, krem = kneed;
            int bin = 0;
            for (int i = 255; i >= 0; i--) {
                unsigned h = hist[i];
                if (acc + h >= kneed) { bin = i; krem = kneed - acc; break; }
                acc += h;
            }
            sh_pref = prefix | ((unsigned)bin << shift);
            sh_k = krem;
        }
        __syncthreads();
        prefix = sh_pref;
    }
    const float v64f = __uint_as_float(prefix & 0x7FFFFFFFu);

    // ---- band: +/- 8e-3 in LOGIT space (fp16 GEMM noise ~6e-4 -> 13 sigma) ----
    float hi, lo;
    if (v64f > 0.999999f || v64f < 1e-6f) {
        hi = v64f + 2e-5f;
        lo = v64f - 2e-5f;
    } else {
        const float LD = 8e-3f;
        float l64 = logf(v64f / (1.f - v64f));
        hi = 1.f / (1.f + expf(-(l64 + LD)));
        lo = 1.f / (1.f + expf(-(l64 - LD)));
        hi = fmaxf(hi, v64f + 1e-7f);
        lo = fminf(lo, v64f - 1e-7f);
    }

    // ---- definite members + boundary band ----
    for (int i = t; i < NN; i += 256) {
        float g = gs[i];
        if (g > hi) {
            atomicAdd(&sh_above, 1u);
        } else if (g >= lo) {
            unsigned idx = atomicAdd(&sh_nb, 1u);
            if (idx < BAND_CAP) bandIdx[idx] = (unsigned short)i;
        }
    }
    __syncthreads();
    const int above = (int)sh_above;
    const int nb = (int)sh_nb;
    const int need = (int)KTOP - above;
    const bool fallback = (nb > BAND_CAP) || (need < 0);
    const int* yrow = y + (size_t)b * NN;

    if (!fallback) {
        if (nb > need) {
            // fp64 exact dot of band members from bf16x3 Q/K splits
            const size_t qoff = ((size_t)b * MM + m) * DD;
            const __nv_bfloat16* qr0 = q0 + qoff;
            const __nv_bfloat16* qr1 = q1 + qoff;
            const __nv_bfloat16* qr2 = q2 + qoff;
            for (int j = warp; j < nb; j += 8) {
                int n = bandIdx[j];
                const size_t koff = ((size_t)b * NN + n) * DD;
                double acc = 0.0;
                for (int e = lane; e < DD; e += 32) {
                    double qd = (double)__bfloat162float(qr0[e]) +
                                (double)__bfloat162float(qr1[e]) +
                                (double)__bfloat162float(qr2[e]);
                    double kd = (double)__bfloat162float(k0[koff + e]) +
                                (double)__bfloat162float(k1[koff + e]) +
                                (double)__bfloat162float(k2[koff + e]);
                    acc = fma(qd, kd, acc);
                }
#pragma unroll
                for (int o = 16; o > 0; o >>= 1)
                    acc += __shfl_down_sync(0xFFFFFFFFu, acc, o);
                if (lane == 0) Lband[j] = acc;
            }
            __syncthreads();
            // reference-style fp32 gamma of band members (replicates fp32 ties)
            if (t < nb) {
                float alpha = log1pf(expf(*taup)) + 1e-6f;
                float beta  = *biasp;
                float dotf = (float)Lband[t];
                float l = __fadd_rn(__fmul_rn(alpha, dotf), beta);
                Gband[t] = 1.f / (1.f + expf(-l));
            }
            __syncthreads();
            // reference semantics: keep all with gamma >= (need-th largest), ties included
            if (t < nb) {
                float gt = Gband[t];
                int rank = 0;
                for (int j = 0; j < nb; j++) rank += (Gband[j] > gt);
                unsigned char kp = (rank < need) ? 1 : 0;
                bandKeep[t] = kp;
                if (kp) atomicAdd(&sh_kept, 1u);
            }
            __syncthreads();
            for (int j = t; j < nb; j += 256) {
                if (bandKeep[j]) {
                    int i = bandIdx[j];
                    float g = Gband[j];
                    int c = yrow[i];
                    atomicAdd(&S[c], g);
                    atomicAdd(&W[c], (1.f - g) * sh_rinv[c]);
                }
            }
            if (t == 0) cntk = (unsigned)above + sh_kept;
        } else {
            for (int j = t; j < nb; j += 256) {
                int i = bandIdx[j];
                float g = gs[i];
                int c = yrow[i];
                atomicAdd(&S[c], g);
                atomicAdd(&W[c], (1.f - g) * sh_rinv[c]);
            }
            if (t == 0) cntk = (unsigned)(above + nb);
        }
        __syncthreads();
        // definite members
        for (int i = t; i < NN; i += 256) {
            float g = gs[i];
            if (g > hi) {
                int c = yrow[i];
                atomicAdd(&S[c], g);
                atomicAdd(&W[c], (1.f - g) * sh_rinv[c]);
            }
        }
        __syncthreads();
    } else {
        for (int i = t; i < NN; i += 256) {
            float g = gs[i];
            if (f2u(g) >= prefix) {
                int c = yrow[i];
                atomicAdd(&S[c], g);
                atomicAdd(&W[c], (1.f - g) * sh_rinv[c]);
                atomicAdd(&cntk, 1u);
            }
        }
        __syncthreads();
    }

    if (t == 0) {
        float Wt = 0.f;
        for (int c = 0; c < CC; c++) Wt += W[c];
        float dq = fmaxf((float)cntk, 1.f);
        float p[CC];
        float sum = 0.f;
        for (int c = 0; c < CC; c++) {
            float v = S[c] + sh_prior[c] * (Wt - W[c]);
            v = fmaxf(v, 0.f) / dq;
            p[c] = v;
            sum += v;
        }
        float inv = 1.f / fmaxf(sum, 1e-12f);
        float* orow = out + ((size_t)b * MM + m) * CC;
        for (int c = 0; c < CC; c++) orow[c] = p[c] * inv;
    }
}

// ---------------- launcher ----------------
extern "C" void kernel_launch(void* const* d_in, const int* in_sizes, int n_in,
                              void* d_out, int out_size) {
    const float* Hs   = (const float*)d_in[0];
    const float* Hq   = (const float*)d_in[1];
    const int*   ys   = (const int*)d_in[2];
    const float* lnw  = (const float*)d_in[4];
    const float* lnb  = (const float*)d_in[5];
    const float* WQ   = (const float*)d_in[6];
    const float* WK   = (const float*)d_in[7];
    const float* taup = (const float*)d_in[8];
    const float* bisp = (const float*)d_in[9];
    float* out = (float*)d_out;

    __nv_bfloat16 *hqB, *hsB, *wqB, *wkB, *qB, *kB;
    __half *qH, *kH;
    float* Gam;
    cudaGetSymbolAddress((void**)&hqB, g_hq);
    cudaGetSymbolAddress((void**)&hsB, g_hs);
    cudaGetSymbolAddress((void**)&wqB, g_wq);
    cudaGetSymbolAddress((void**)&wkB, g_wk);
    cudaGetSymbolAddress((void**)&qB, g_qs);
    cudaGetSymbolAddress((void**)&kB, g_ks);
    cudaGetSymbolAddress((void**)&qH, g_qh);
    cudaGetSymbolAddress((void**)&kH, g_kh);
    cudaGetSymbolAddress((void**)&Gam, g_gamma);

    const size_t HQ = (size_t)BB * MM * DD;
    const size_t HS = (size_t)BB * NN * DD;
    const size_t WW = (size_t)DD * DD;

    cudaFuncSetAttribute(mma_proj, cudaFuncAttributeMaxDynamicSharedMemorySize, SMEM_GEMM);
    cudaFuncSetAttribute(mma_logits, cudaFuncAttributeMaxDynamicSharedMemorySize, SMEM_GEMM);

    // 1) LayerNorm + splits
    ln_split<<<BB * MM, 128>>>(Hq, lnw, lnb, hqB, hqB + HQ, hqB + 2 * HQ);
    ln_split<<<BB * NN, 128>>>(Hs, lnw, lnb, hsB, hsB + HS, hsB + 2 * HS);
    split3<<<(int)((WW + 255) / 256), 256>>>(WQ, wqB, wqB + WW, wqB + 2 * WW, (int)WW);
    split3<<<(int)((WW + 255) / 256), 256>>>(WK, wkB, wkB + WW, wkB + 2 * WW, (int)WW);

    // 2) priors
    prior_kernel<<<BB, 256>>>(ys);

    // 3) projections (bf16x3 6-product, bit-identical to round-11)
    mma_proj<<<dim3(DD / 128, (BB * MM) / 128, 1), NTHR, SMEM_GEMM>>>(
        hqB, hqB + HQ, hqB + 2 * HQ, wqB, wqB + WW, wqB + 2 * WW,
        qB, qB + HQ, qB + 2 * HQ);
    mma_proj<<<dim3(DD / 128, (BB * NN) / 128, 1), NTHR, SMEM_GEMM>>>(
        hsB, hsB + HS, hsB + 2 * HS, wkB, wkB + WW, wkB + 2 * WW,
        kB, kB + HS, kB + 2 * HS);

    // 3b) fp16 copies of Q/K for the logits GEMM
    to_half<<<(int)((HQ + 255) / 256), 256>>>(qB, qB + HQ, qB + 2 * HQ, qH, (int)HQ);
    to_half<<<(int)((HS + 255) / 256), 256>>>(kB, kB + HS, kB + 2 * HS, kH, (int)HS);

    // 4) gamma~ = sigmoid(tau * [fp16 Q K^T] + bias) — single-product, 16 chunks
    mma_logits<<<dim3(NN / 128, MM / 128, BB), NTHR, SMEM_GEMM>>>(qH, kH, Gam, taup, bisp);

    // 5) top-k select (logit band + fp64 fix-up on bf16x3 Q/K) + aggregate
    select_agg<<<dim3(MM, BB), 256>>>(ys, qB, qB + HQ, qB + 2 * HQ,
                                      kB, kB + HS, kB + 2 * HS, taup, bisp, out);
}

// round 14
// speedup vs baseline: 1.6062x; 1.0135x over previous
#include <cuda_runtime.h>
#include <cuda_bf16.h>
#include <cuda_fp16.h>
#include <cstdint>

#define BB 4
#define NN 4096
#define MM 2048
#define DD 512
#define CC 10
#define KTOP 64u

// ---------------- scratch (device globals; no cudaMalloc allowed) ----------------
__device__ __align__(256) __nv_bfloat16 g_hq[3][BB * MM * DD];
__device__ __align__(256) __nv_bfloat16 g_hs[3][BB * NN * DD];
__device__ __align__(256) __nv_bfloat16 g_wq[3][DD * DD];
__device__ __align__(256) __nv_bfloat16 g_wk[3][DD * DD];
__device__ __align__(256) float  g_qf[BB * MM * DD];   // fp32 Q (fixup fidelity)
__device__ __align__(256) float  g_kf[BB * NN * DD];   // fp32 K
__device__ __align__(256) __half g_qh[BB * MM * DD];   // fp16 Q (logits GEMM)
__device__ __align__(256) __half g_kh[BB * NN * DD];   // fp16 K
__device__ float g_gamma[(size_t)BB * MM * NN];
__device__ float g_prior[BB * CC];
__device__ float g_rhoinv[BB * CC];

// ---------------- helpers ----------------
__device__ __forceinline__ uint32_t smem_u32(const void* p) {
    uint32_t a;
    asm("{ .reg .u64 t; cvta.to.shared.u64 t, %1; cvt.u32.u64 %0, t; }" : "=r"(a) : "l"(p));
    return a;
}

#define CP16(dst, src) \
    asm volatile("cp.async.cg.shared.global [%0], [%1], 16;" :: "r"(dst), "l"(src))
#define CP_COMMIT() asm volatile("cp.async.commit_group;" ::: "memory")
#define CP_WAIT2()  asm volatile("cp.async.wait_group 2;" ::: "memory")
#define CP_WAIT0()  asm volatile("cp.async.wait_group 0;" ::: "memory")

#define LDSM4(r0, r1, r2, r3, addr) \
    asm volatile("ldmatrix.sync.aligned.m8n8.x4.shared.b16 {%0,%1,%2,%3}, [%4];" \
                 : "=r"(r0), "=r"(r1), "=r"(r2), "=r"(r3) : "r"(addr))

#define MMA_BF16(d, a, b0, b1) \
    asm volatile("mma.sync.aligned.m16n8k16.row.col.f32.bf16.bf16.f32 " \
                 "{%0,%1,%2,%3}, {%4,%5,%6,%7}, {%8,%9}, {%0,%1,%2,%3};" \
                 : "+f"((d)[0]), "+f"((d)[1]), "+f"((d)[2]), "+f"((d)[3]) \
                 : "r"((a)[0]), "r"((a)[1]), "r"((a)[2]), "r"((a)[3]), "r"(b0), "r"(b1))

#define MMA_FP16(d, a, b0, b1) \
    asm volatile("mma.sync.aligned.m16n8k16.row.col.f32.f16.f16.f32 " \
                 "{%0,%1,%2,%3}, {%4,%5,%6,%7}, {%8,%9}, {%0,%1,%2,%3};" \
                 : "+f"((d)[0]), "+f"((d)[1]), "+f"((d)[2]), "+f"((d)[3]) \
                 : "r"((a)[0]), "r"((a)[1]), "r"((a)[2]), "r"((a)[3]), "r"(b0), "r"(b1))

// ---------------- LayerNorm fused with 3-way bf16 split ----------------
__global__ void ln_split(const float* __restrict__ x, const float* __restrict__ w,
                         const float* __restrict__ b,
                         __nv_bfloat16* __restrict__ o0, __nv_bfloat16* __restrict__ o1,
                         __nv_bfloat16* __restrict__ o2) {
    int row = blockIdx.x;
    const float* xr = x + (size_t)row * DD;
    int t = threadIdx.x;
    float v[4];
    float s = 0.f, s2 = 0.f;
#pragma unroll
    for (int i = 0; i < 4; i++) {
        v[i] = xr[t + i * 128];
        s += v[i];
        s2 += v[i] * v[i];
    }
#pragma unroll
    for (int o = 16; o > 0; o >>= 1) {
        s  += __shfl_down_sync(0xFFFFFFFFu, s, o);
        s2 += __shfl_down_sync(0xFFFFFFFFu, s2, o);
    }
    __shared__ float ps[4], ps2[4];
    if ((t & 31) == 0) { ps[t >> 5] = s; ps2[t >> 5] = s2; }
    __syncthreads();
    s  = ps[0] + ps[1] + ps[2] + ps[3];
    s2 = ps2[0] + ps2[1] + ps2[2] + ps2[3];
    float mu  = s * (1.f / DD);
    float var = s2 * (1.f / DD) - mu * mu;
    float rs  = 1.f / sqrtf(var + 1e-5f);
#pragma unroll
    for (int i = 0; i < 4; i++) {
        int c = t + i * 128;
        float val = (v[i] - mu) * rs * w[c] + b[c];
        __nv_bfloat16 h0 = __float2bfloat16_rn(val);
        float r1 = val - __bfloat162float(h0);
        __nv_bfloat16 h1 = __float2bfloat16_rn(r1);
        float r2 = r1 - __bfloat162float(h1);
        __nv_bfloat16 h2 = __float2bfloat16_rn(r2);
        size_t oi = (size_t)row * DD + c;
        o0[oi] = h0; o1[oi] = h1; o2[oi] = h2;
    }
}

__global__ void split3(const float* __restrict__ x, __nv_bfloat16* __restrict__ o0,
                       __nv_bfloat16* __restrict__ o1, __nv_bfloat16* __restrict__ o2, int n) {
    int i = blockIdx.x * 256 + threadIdx.x;
    if (i < n) {
        float v = x[i];
        __nv_bfloat16 h0 = __float2bfloat16_rn(v);
        float r1 = v - __bfloat162float(h0);
        __nv_bfloat16 h1 = __float2bfloat16_rn(r1);
        float r2 = r1 - __bfloat162float(h1);
        __nv_bfloat16 h2 = __float2bfloat16_rn(r2);
        o0[i] = h0; o1[i] = h1; o2[i] = h2;
    }
}

// ---------------- tiling constants ----------------
#define KT 32
#define ROWB 80
#define TILE10 (128 * ROWB)
#define STAGE_B (2 * TILE10)
#define SMEM_GEMM (4 * STAGE_B)      // 81920 B (x2 CTAs = 163840 < 227KB)
#define NTHR 256

// ---------------- projection GEMM (bf16x3, 6-product; fp32 + fp16 outputs) ----------------
__global__ void __launch_bounds__(NTHR, 2) mma_proj(
    const __nv_bfloat16* __restrict__ A0, const __nv_bfloat16* __restrict__ A1,
    const __nv_bfloat16* __restrict__ A2,
    const __nv_bfloat16* __restrict__ B0, const __nv_bfloat16* __restrict__ B1,
    const __nv_bfloat16* __restrict__ B2,
    float* __restrict__ of, __half* __restrict__ oh) {
    extern __shared__ __align__(128) char smem[];
    const int NCHUNK_M = 96;
    const int tid  = threadIdx.x;
    const int lane = tid & 31, warp = tid >> 5;
    const int wm = warp >> 2, wn = warp & 3;
    const int m0 = blockIdx.y * 128, n0 = blockIdx.x * 128;

    const __nv_bfloat16* Abase = A0 + (size_t)m0 * DD;
    const __nv_bfloat16* Bbase = B0 + (size_t)n0 * DD;
    const uint32_t da1 = (uint32_t)(A1 - A0), da2 = (uint32_t)(A2 - A0);
    const uint32_t db1 = (uint32_t)(B1 - B0), db2 = (uint32_t)(B2 - B0);

    const uint32_t sbase = smem_u32(smem);
    const int r0i = tid >> 2, c0i = tid & 3;
    const int r1i = r0i + 64;

    const uint32_t aRowOff = (uint32_t)(((lane & 7) + (lane & 8)) * ROWB + (lane & 16));
    const uint32_t bRowOff = (uint32_t)(((lane & 7) + ((lane & 16) >> 1)) * ROWB + ((lane & 8) << 1));

    float acc[4][4][4];
#pragma unroll
    for (int i = 0; i < 4; i++)
#pragma unroll
        for (int j = 0; j < 4; j++)
#pragma unroll
            for (int q = 0; q < 4; q++) acc[i][j][q] = 0.f;

    auto issue = [&](int c) {
        int seg = c >> 4, k0 = (c & 15) * KT;
        // small-first: 0:a0b2 1:a2b0 2:a1b1 3:a0b1 4:a1b0 5:a0b0
        uint32_t oa = (seg == 1) ? da2 : ((seg == 2) || (seg == 4)) ? da1 : 0u;
        uint32_t ob = (seg == 0) ? db2 : ((seg == 2) || (seg == 3)) ? db1 : 0u;
        uint32_t sb0 = sbase + (c & 3) * STAGE_B;
        const __nv_bfloat16* ap = Abase + oa + k0;
        const __nv_bfloat16* bp = Bbase + ob + k0;
        CP16(sb0 + (uint32_t)(r0i * ROWB + c0i * 16), ap + (size_t)r0i * DD + c0i * 8);
        CP16(sb0 + (uint32_t)(r1i * ROWB + c0i * 16), ap + (size_t)r1i * DD + c0i * 8);
        uint32_t sb1 = sb0 + TILE10;
        CP16(sb1 + (uint32_t)(r0i * ROWB + c0i * 16), bp + (size_t)r0i * DD + c0i * 8);
        CP16(sb1 + (uint32_t)(r1i * ROWB + c0i * 16), bp + (size_t)r1i * DD + c0i * 8);
    };

    issue(0); CP_COMMIT();
    issue(1); CP_COMMIT();
    issue(2); CP_COMMIT();

    for (int c = 0; c < NCHUNK_M; c++) {
        CP_WAIT2();
        __syncthreads();
        int cn = c + 3;
        if (cn < NCHUNK_M) issue(cn);
        CP_COMMIT();

        uint32_t sa = sbase + (c & 3) * STAGE_B;
        uint32_t sb = sa + TILE10;
#pragma unroll
        for (int k16 = 0; k16 < 2; k16++) {
            uint32_t a[4][4];
#pragma unroll
            for (int mt = 0; mt < 4; mt++) {
                uint32_t addr = sa + (uint32_t)((wm * 64 + mt * 16) * ROWB) + aRowOff + k16 * 32;
                LDSM4(a[mt][0], a[mt][1], a[mt][2], a[mt][3], addr);
            }
            uint32_t bfr[2][4];
#pragma unroll
            for (int nt2 = 0; nt2 < 2; nt2++) {
                uint32_t addr = sb + (uint32_t)((wn * 32 + nt2 * 16) * ROWB) + bRowOff + k16 * 32;
                LDSM4(bfr[nt2][0], bfr[nt2][1], bfr[nt2][2], bfr[nt2][3], addr);
            }
#pragma unroll
            for (int mt = 0; mt < 4; mt++)
#pragma unroll
                for (int nt = 0; nt < 4; nt++)
                    MMA_BF16(acc[mt][nt], a[mt], bfr[nt >> 1][(nt & 1) * 2],
                             bfr[nt >> 1][(nt & 1) * 2 + 1]);
        }
    }
    CP_WAIT0();

    const int mrow = lane >> 2, ncol = (lane & 3) * 2;
#pragma unroll
    for (int mt = 0; mt < 4; mt++) {
#pragma unroll
        for (int half = 0; half < 2; half++) {
            int gr = m0 + wm * 64 + mt * 16 + mrow + half * 8;
            size_t base = (size_t)gr * DD + n0 + wn * 32 + ncol;
#pragma unroll
            for (int nt = 0; nt < 4; nt++) {
                float vx = acc[mt][nt][half * 2 + 0];
                float vy = acc[mt][nt][half * 2 + 1];
                float2 fv; fv.x = vx; fv.y = vy;
                *reinterpret_cast<float2*>(of + base + nt * 8) = fv;
                __half2 hv; hv.x = __float2half_rn(vx); hv.y = __float2half_rn(vy);
                *reinterpret_cast<__half2*>(oh + base + nt * 8) = hv;
            }
        }
    }
}

// ---------------- logits GEMM (fp16 single-product, 16 chunks, sigmoid epilogue) ----------------
__global__ void __launch_bounds__(NTHR, 2) mma_logits(
    const __half* __restrict__ Q, const __half* __restrict__ K,
    float* __restrict__ gout,
    const float* __restrict__ taup, const float* __restrict__ biasp) {
    extern __shared__ __align__(128) char smem[];
    const int NCHUNK_M = 16;
    const int tid  = threadIdx.x;
    const int lane = tid & 31, warp = tid >> 5;
    const int wm = warp >> 2, wn = warp & 3;
    const int m0 = blockIdx.y * 128, n0 = blockIdx.x * 128;

    const __half* Abase = Q + (size_t)blockIdx.z * MM * DD + (size_t)m0 * DD;
    const __half* Bbase = K + (size_t)blockIdx.z * NN * DD + (size_t)n0 * DD;

    const uint32_t sbase = smem_u32(smem);
    const int r0i = tid >> 2, c0i = tid & 3;
    const int r1i = r0i + 64;

    const uint32_t aRowOff = (uint32_t)(((lane & 7) + (lane & 8)) * ROWB + (lane & 16));
    const uint32_t bRowOff = (uint32_t)(((lane & 7) + ((lane & 16) >> 1)) * ROWB + ((lane & 8) << 1));

    float acc[4][4][4];
#pragma unroll
    for (int i = 0; i < 4; i++)
#pragma unroll
        for (int j = 0; j < 4; j++)
#pragma unroll
            for (int q = 0; q < 4; q++) acc[i][j][q] = 0.f;

    auto issue = [&](int c) {
        int k0 = c * KT;
        uint32_t sb0 = sbase + (c & 3) * STAGE_B;
        const __half* ap = Abase + k0;
        const __half* bp = Bbase + k0;
        CP16(sb0 + (uint32_t)(r0i * ROWB + c0i * 16), ap + (size_t)r0i * DD + c0i * 8);
        CP16(sb0 + (uint32_t)(r1i * ROWB + c0i * 16), ap + (size_t)r1i * DD + c0i * 8);
        uint32_t sb1 = sb0 + TILE10;
        CP16(sb1 + (uint32_t)(r0i * ROWB + c0i * 16), bp + (size_t)r0i * DD + c0i * 8);
        CP16(sb1 + (uint32_t)(r1i * ROWB + c0i * 16), bp + (size_t)r1i * DD + c0i * 8);
    };

    issue(0); CP_COMMIT();
    issue(1); CP_COMMIT();
    issue(2); CP_COMMIT();

    for (int c = 0; c < NCHUNK_M; c++) {
        CP_WAIT2();
        __syncthreads();
        int cn = c + 3;
        if (cn < NCHUNK_M) issue(cn);
        CP_COMMIT();

        uint32_t sa = sbase + (c & 3) * STAGE_B;
        uint32_t sb = sa + TILE10;
#pragma unroll
        for (int k16 = 0; k16 < 2; k16++) {
            uint32_t a[4][4];
#pragma unroll
            for (int mt = 0; mt < 4; mt++) {
                uint32_t addr = sa + (uint32_t)((wm * 64 + mt * 16) * ROWB) + aRowOff + k16 * 32;
                LDSM4(a[mt][0], a[mt][1], a[mt][2], a[mt][3], addr);
            }
            uint32_t bfr[2][4];
#pragma unroll
            for (int nt2 = 0; nt2 < 2; nt2++) {
                uint32_t addr = sb + (uint32_t)((wn * 32 + nt2 * 16) * ROWB) + bRowOff + k16 * 32;
                LDSM4(bfr[nt2][0], bfr[nt2][1], bfr[nt2][2], bfr[nt2][3], addr);
            }
#pragma unroll
            for (int mt = 0; mt < 4; mt++)
#pragma unroll
                for (int nt = 0; nt < 4; nt++)
                    MMA_FP16(acc[mt][nt], a[mt], bfr[nt >> 1][(nt & 1) * 2],
                             bfr[nt >> 1][(nt & 1) * 2 + 1]);
        }
    }
    CP_WAIT0();

    const int mrow = lane >> 2, ncol = (lane & 3) * 2;
    float alpha = log1pf(expf(*taup)) + 1e-6f;
    float beta  = *biasp;
    float* Cb = gout + (size_t)blockIdx.z * MM * NN;
#pragma unroll
    for (int mt = 0; mt < 4; mt++) {
#pragma unroll
        for (int half = 0; half < 2; half++) {
            int gr = m0 + wm * 64 + mt * 16 + mrow + half * 8;
            float* crow = Cb + (size_t)gr * NN + n0 + wn * 32 + ncol;
#pragma unroll
            for (int nt = 0; nt < 4; nt++) {
                float2 f;
                f.x = 1.f / (1.f + expf(-(alpha * acc[mt][nt][half * 2 + 0] + beta)));
                f.y = 1.f / (1.f + expf(-(alpha * acc[mt][nt][half * 2 + 1] + beta)));
                *reinterpret_cast<float2*>(crow + nt * 8) = f;
            }
        }
    }
}

// ---------------- prior / rho-inverse per batch ----------------
__global__ void prior_kernel(const int* __restrict__ y) {
    int b = blockIdx.x;
    __shared__ int cnt[CC];
    int t = threadIdx.x;
    if (t < CC) cnt[t] = 0;
    __syncthreads();
    for (int i = t; i < NN; i += 256) atomicAdd(&cnt[y[(size_t)b * NN + i]], 1);
    __syncthreads();
    if (t == 0) {
        int tot = 0;
        for (int c = 0; c < CC; c++) tot += cnt[c];
        float denom = fmaxf((float)tot, 1.f);
        for (int c = 0; c < CC; c++) {
            float pr = (float)cnt[c] / denom;
            g_prior[b * CC + c]  = pr;
            g_rhoinv[b * CC + c] = 1.f / fmaxf(1.f - pr, 1e-6f);
        }
    }
}

// ---------------- top-k select (logit-space band + fp64 fix-up on fp32 Q/K) ----------------
__device__ __forceinline__ unsigned f2u(float f) {
    unsigned u = __float_as_uint(f);
    return (u & 0x80000000u) ? ~u : (u | 0x80000000u);
}

#define BAND_CAP 64

__global__ void select_agg(const int* __restrict__ y,
                           const float* __restrict__ qf, const float* __restrict__ kf,
                           const float* __restrict__ taup, const float* __restrict__ biasp,
                           float* __restrict__ out) {
    int m = blockIdx.x, b = blockIdx.y;
    const float* grow = g_gamma + ((size_t)b * MM + m) * NN;
    __shared__ float gs[NN];
    __shared__ unsigned short cand[NN];
    __shared__ unsigned whist[8][256];
    __shared__ unsigned hist[256];
    __shared__ unsigned sh_pref, sh_k, sh_nc;
    __shared__ float S[CC], W[CC], sh_prior[CC], sh_rinv[CC];
    __shared__ unsigned cntk;
    __shared__ unsigned sh_above, sh_nb, sh_kept;
    __shared__ unsigned short bandIdx[BAND_CAP];
    __shared__ unsigned char bandKeep[BAND_CAP];
    __shared__ double Lband[BAND_CAP];
    __shared__ float Gband[BAND_CAP];
    const int t = threadIdx.x;
    const int warp = t >> 5, lane = t & 31;

    for (int i = t; i < NN / 4; i += 256)
        reinterpret_cast<float4*>(gs)[i] = reinterpret_cast<const float4*>(grow)[i];
    for (int i = t; i < 8 * 256; i += 256) (&whist[0][0])[i] = 0u;
    if (t < CC) {
        S[t] = 0.f; W[t] = 0.f;
        sh_prior[t] = g_prior[b * CC + t];
        sh_rinv[t]  = g_rhoinv[b * CC + t];
    }
    if (t == 0) { cntk = 0; sh_nc = 0; sh_above = 0; sh_nb = 0; sh_kept = 0; }
    __syncthreads();

    // ---- radix select exact 64th-largest of gamma~ ----
    for (int i = t; i < NN; i += 256)
        atomicAdd(&whist[warp][f2u(gs[i]) >> 24], 1u);
    __syncthreads();
    {
        unsigned h = 0;
#pragma unroll
        for (int w = 0; w < 8; w++) h += whist[w][t];
        hist[t] = h;
    }
    __syncthreads();
    if (t == 0) {
        unsigned acc = 0, krem = KTOP;
        int bin = 0;
        for (int i = 255; i >= 0; i--) {
            unsigned h = hist[i];
            if (acc + h >= KTOP) { bin = i; krem = KTOP - acc; break; }
            acc += h;
        }
        sh_pref = (unsigned)bin << 24;
        sh_k = krem;
    }
    __syncthreads();
    unsigned prefix = sh_pref;

    for (int i = t; i < NN; i += 256) {
        if ((f2u(gs[i]) & 0xFF000000u) == prefix) {
            unsigned idx = atomicAdd(&sh_nc, 1u);
            cand[idx] = (unsigned short)i;
        }
    }
    __syncthreads();
    const int ncand = (int)sh_nc;

#pragma unroll
    for (int shift = 16; shift >= 0; shift -= 8) {
        hist[t] = 0;
        __syncthreads();
        unsigned pm = 0xFFFFFFFFu << (shift + 8);
        for (int j = t; j < ncand; j += 256) {
            unsigned u = f2u(gs[cand[j]]);
            if ((u & pm) == prefix) atomicAdd(&hist[(u >> shift) & 255u], 1u);
        }
        __syncthreads();
        if (t == 0) {
            unsigned kneed = sh_k, acc = 0, krem = kneed;
            int bin = 0;
            for (int i = 255; i >= 0; i--) {
                unsigned h = hist[i];
                if (acc + h >= kneed) { bin = i; krem = kneed - acc; break; }
                acc += h;
            }
            sh_pref = prefix | ((unsigned)bin << shift);
            sh_k = krem;
        }
        __syncthreads();
        prefix = sh_pref;
    }
    const float v64f = __uint_as_float(prefix & 0x7FFFFFFFu);

    // ---- band: +/- 8e-3 in LOGIT space (fp16 GEMM noise ~6e-4 -> 13 sigma) ----
    float hi, lo;
    if (v64f > 0.999999f || v64f < 1e-6f) {
        hi = v64f + 2e-5f;
        lo = v64f - 2e-5f;
    } else {
        const float LD = 8e-3f;
        float l64 = logf(v64f / (1.f - v64f));
        hi = 1.f / (1.f + expf(-(l64 + LD)));
        lo = 1.f / (1.f + expf(-(l64 - LD)));
        hi = fmaxf(hi, v64f + 1e-7f);
        lo = fminf(lo, v64f - 1e-7f);
    }

    // ---- definite members + boundary band ----
    for (int i = t; i < NN; i += 256) {
        float g = gs[i];
        if (g > hi) {
            atomicAdd(&sh_above, 1u);
        } else if (g >= lo) {
            unsigned idx = atomicAdd(&sh_nb, 1u);
            if (idx < BAND_CAP) bandIdx[idx] = (unsigned short)i;
        }
    }
    __syncthreads();
    const int above = (int)sh_above;
    const int nb = (int)sh_nb;
    const int need = (int)KTOP - above;
    const bool fallback = (nb > BAND_CAP) || (need < 0);
    const int* yrow = y + (size_t)b * NN;

    if (!fallback) {
        if (nb > need) {
            // fp64 exact dot of band members from fp32 Q/K
            const size_t qoff = ((size_t)b * MM + m) * DD;
            const float* qr = qf + qoff;
            for (int j = warp; j < nb; j += 8) {
                int n = bandIdx[j];
                const float* kr = kf + ((size_t)b * NN + n) * DD;
                double acc = 0.0;
                for (int e = lane; e < DD; e += 32)
                    acc = fma((double)qr[e], (double)kr[e], acc);
#pragma unroll
                for (int o = 16; o > 0; o >>= 1)
                    acc += __shfl_down_sync(0xFFFFFFFFu, acc, o);
                if (lane == 0) Lband[j] = acc;
            }
            __syncthreads();
            // reference-style fp32 gamma of band members (replicates fp32 ties)
            if (t < nb) {
                float alpha = log1pf(expf(*taup)) + 1e-6f;
                float beta  = *biasp;
                float dotf = (float)Lband[t];
                float l = __fadd_rn(__fmul_rn(alpha, dotf), beta);
                Gband[t] = 1.f / (1.f + expf(-l));
            }
            __syncthreads();
            // reference semantics: keep all with gamma >= (need-th largest), ties included
            if (t < nb) {
                float gt = Gband[t];
                int rank = 0;
                for (int j = 0; j < nb; j++) rank += (Gband[j] > gt);
                unsigned char kp = (rank < need) ? 1 : 0;
                bandKeep[t] = kp;
                if (kp) atomicAdd(&sh_kept, 1u);
            }
            __syncthreads();
            for (int j = t; j < nb; j += 256) {
                if (bandKeep[j]) {
                    int i = bandIdx[j];
                    float g = Gband[j];
                    int c = yrow[i];
                    atomicAdd(&S[c], g);
                    atomicAdd(&W[c], (1.f - g) * sh_rinv[c]);
                }
            }
            if (t == 0) cntk = (unsigned)above + sh_kept;
        } else {
            for (int j = t; j < nb; j += 256) {
                int i = bandIdx[j];
                float g = gs[i];
                int c = yrow[i];
                atomicAdd(&S[c], g);
                atomicAdd(&W[c], (1.f - g) * sh_rinv[c]);
            }
            if (t == 0) cntk = (unsigned)(above + nb);
        }
        __syncthreads();
        // definite members
        for (int i = t; i < NN; i += 256) {
            float g = gs[i];
            if (g > hi) {
                int c = yrow[i];
                atomicAdd(&S[c], g);
                atomicAdd(&W[c], (1.f - g) * sh_rinv[c]);
            }
        }
        __syncthreads();
    } else {
        for (int i = t; i < NN; i += 256) {
            float g = gs[i];
            if (f2u(g) >= prefix) {
                int c = yrow[i];
                atomicAdd(&S[c], g);
                atomicAdd(&W[c], (1.f - g) * sh_rinv[c]);
                atomicAdd(&cntk, 1u);
            }
        }
        __syncthreads();
    }

    if (t == 0) {
        float Wt = 0.f;
        for (int c = 0; c < CC; c++) Wt += W[c];
        float dq = fmaxf((float)cntk, 1.f);
        float p[CC];
        float sum = 0.f;
        for (int c = 0; c < CC; c++) {
            float v = S[c] + sh_prior[c] * (Wt - W[c]);
            v = fmaxf(v, 0.f) / dq;
            p[c] = v;
            sum += v;
        }
        float inv = 1.f / fmaxf(sum, 1e-12f);
        float* orow = out + ((size_t)b * MM + m) * CC;
        for (int c = 0; c < CC; c++) orow[c] = p[c] * inv;
    }
}

// ---------------- launcher ----------------
extern "C" void kernel_launch(void* const* d_in, const int* in_sizes, int n_in,
                              void* d_out, int out_size) {
    const float* Hs   = (const float*)d_in[0];
    const float* Hq   = (const float*)d_in[1];
    const int*   ys   = (const int*)d_in[2];
    const float* lnw  = (const float*)d_in[4];
    const float* lnb  = (const float*)d_in[5];
    const float* WQ   = (const float*)d_in[6];
    const float* WK   = (const float*)d_in[7];
    const float* taup = (const float*)d_in[8];
    const float* bisp = (const float*)d_in[9];
    float* out = (float*)d_out;

    __nv_bfloat16 *hqB, *hsB, *wqB, *wkB;
    float *qF, *kF;
    __half *qH, *kH;
    float* Gam;
    cudaGetSymbolAddress((void**)&hqB, g_hq);
    cudaGetSymbolAddress((void**)&hsB, g_hs);
    cudaGetSymbolAddress((void**)&wqB, g_wq);
    cudaGetSymbolAddress((void**)&wkB, g_wk);
    cudaGetSymbolAddress((void**)&qF, g_qf);
    cudaGetSymbolAddress((void**)&kF, g_kf);
    cudaGetSymbolAddress((void**)&qH, g_qh);
    cudaGetSymbolAddress((void**)&kH, g_kh);
    cudaGetSymbolAddress((void**)&Gam, g_gamma);

    const size_t HQ = (size_t)BB * MM * DD;
    const size_t HS = (size_t)BB * NN * DD;
    const size_t WW = (size_t)DD * DD;

    cudaFuncSetAttribute(mma_proj, cudaFuncAttributeMaxDynamicSharedMemorySize, SMEM_GEMM);
    cudaFuncSetAttribute(mma_logits, cudaFuncAttributeMaxDynamicSharedMemorySize, SMEM_GEMM);

    // 1) LayerNorm + splits
    ln_split<<<BB * MM, 128>>>(Hq, lnw, lnb, hqB, hqB + HQ, hqB + 2 * HQ);
    ln_split<<<BB * NN, 128>>>(Hs, lnw, lnb, hsB, hsB + HS, hsB + 2 * HS);
    split3<<<(int)((WW + 255) / 256), 256>>>(WQ, wqB, wqB + WW, wqB + 2 * WW, (int)WW);
    split3<<<(int)((WW + 255) / 256), 256>>>(WK, wkB, wkB + WW, wkB + 2 * WW, (int)WW);

    // 2) priors
    prior_kernel<<<BB, 256>>>(ys);

    // 3) projections (bf16x3 6-product; fp32 + fp16 outputs, no separate conversion)
    mma_proj<<<dim3(DD / 128, (BB * MM) / 128, 1), NTHR, SMEM_GEMM>>>(
        hqB, hqB + HQ, hqB + 2 * HQ, wqB, wqB + WW, wqB + 2 * WW, qF, qH);
    mma_proj<<<dim3(DD / 128, (BB * NN) / 128, 1), NTHR, SMEM_GEMM>>>(
        hsB, hsB + HS, hsB + 2 * HS, wkB, wkB + WW, wkB + 2 * WW, kF, kH);

    // 4) gamma~ = sigmoid(tau * [fp16 Q K^T] + bias) — single-product, 16 chunks
    mma_logits<<<dim3(NN / 128, MM / 128, BB), NTHR, SMEM_GEMM>>>(qH, kH, Gam, taup, bisp);

    // 5) top-k select (logit band + fp64 fix-up on fp32 Q/K) + aggregate
    select_agg<<<dim3(MM, BB), 256>>>(ys, qF, kF, taup, bisp, out);
}

// round 15
// speedup vs baseline: 1.6868x; 1.0502x over previous
#include <cuda_runtime.h>
#include <cuda_bf16.h>
#include <cuda_fp16.h>
#include <cstdint>

#define BB 4
#define NN 4096
#define MM 2048
#define DD 512
#define CC 10
#define KTOP 64u

// ---------------- scratch (device globals; no cudaMalloc allowed) ----------------
__device__ __align__(256) __nv_bfloat16 g_hq[3][BB * MM * DD];
__device__ __align__(256) __nv_bfloat16 g_hs[3][BB * NN * DD];
__device__ __align__(256) __nv_bfloat16 g_wq[3][DD * DD];
__device__ __align__(256) __nv_bfloat16 g_wk[3][DD * DD];
__device__ __align__(256) float  g_qf[BB * MM * DD];
__device__ __align__(256) float  g_kf[BB * NN * DD];
__device__ __align__(256) __half g_qh[BB * MM * DD];
__device__ __align__(256) __half g_kh[BB * NN * DD];
__device__ float g_gamma[(size_t)BB * MM * NN];
__device__ float g_prior[BB * CC];
__device__ float g_rhoinv[BB * CC];

// ---------------- helpers ----------------
__device__ __forceinline__ uint32_t smem_u32(const void* p) {
    uint32_t a;
    asm("{ .reg .u64 t; cvta.to.shared.u64 t, %1; cvt.u32.u64 %0, t; }" : "=r"(a) : "l"(p));
    return a;
}

#define CP16(dst, src) \
    asm volatile("cp.async.cg.shared.global [%0], [%1], 16;" :: "r"(dst), "l"(src))
#define CP_COMMIT() asm volatile("cp.async.commit_group;" ::: "memory")
#define CP_WAIT2()  asm volatile("cp.async.wait_group 2;" ::: "memory")
#define CP_WAIT0()  asm volatile("cp.async.wait_group 0;" ::: "memory")

#define LDSM4(r0, r1, r2, r3, addr) \
    asm volatile("ldmatrix.sync.aligned.m8n8.x4.shared.b16 {%0,%1,%2,%3}, [%4];" \
                 : "=r"(r0), "=r"(r1), "=r"(r2), "=r"(r3) : "r"(addr))

#define MMA_BF16(d, a, b0, b1) \
    asm volatile("mma.sync.aligned.m16n8k16.row.col.f32.bf16.bf16.f32 " \
                 "{%0,%1,%2,%3}, {%4,%5,%6,%7}, {%8,%9}, {%0,%1,%2,%3};" \
                 : "+f"((d)[0]), "+f"((d)[1]), "+f"((d)[2]), "+f"((d)[3]) \
                 : "r"((a)[0]), "r"((a)[1]), "r"((a)[2]), "r"((a)[3]), "r"(b0), "r"(b1))

#define MMA_FP16(d, a, b0, b1) \
    asm volatile("mma.sync.aligned.m16n8k16.row.col.f32.f16.f16.f32 " \
                 "{%0,%1,%2,%3}, {%4,%5,%6,%7}, {%8,%9}, {%0,%1,%2,%3};" \
                 : "+f"((d)[0]), "+f"((d)[1]), "+f"((d)[2]), "+f"((d)[3]) \
                 : "r"((a)[0]), "r"((a)[1]), "r"((a)[2]), "r"((a)[3]), "r"(b0), "r"(b1))

// ---------------- LayerNorm fused with 3-way bf16 split ----------------
__global__ void ln_split(const float* __restrict__ x, const float* __restrict__ w,
                         const float* __restrict__ b,
                         __nv_bfloat16* __restrict__ o0, __nv_bfloat16* __restrict__ o1,
                         __nv_bfloat16* __restrict__ o2) {
    int row = blockIdx.x;
    const float* xr = x + (size_t)row * DD;
    int t = threadIdx.x;
    float v[4];
    float s = 0.f, s2 = 0.f;
#pragma unroll
    for (int i = 0; i < 4; i++) {
        v[i] = xr[t + i * 128];
        s += v[i];
        s2 += v[i] * v[i];
    }
#pragma unroll
    for (int o = 16; o > 0; o >>= 1) {
        s  += __shfl_down_sync(0xFFFFFFFFu, s, o);
        s2 += __shfl_down_sync(0xFFFFFFFFu, s2, o);
    }
    __shared__ float ps[4], ps2[4];
    if ((t & 31) == 0) { ps[t >> 5] = s; ps2[t >> 5] = s2; }
    __syncthreads();
    s  = ps[0] + ps[1] + ps[2] + ps[3];
    s2 = ps2[0] + ps2[1] + ps2[2] + ps2[3];
    float mu  = s * (1.f / DD);
    float var = s2 * (1.f / DD) - mu * mu;
    float rs  = 1.f / sqrtf(var + 1e-5f);
#pragma unroll
    for (int i = 0; i < 4; i++) {
        int c = t + i * 128;
        float val = (v[i] - mu) * rs * w[c] + b[c];
        __nv_bfloat16 h0 = __float2bfloat16_rn(val);
        float r1 = val - __bfloat162float(h0);
        __nv_bfloat16 h1 = __float2bfloat16_rn(r1);
        float r2 = r1 - __bfloat162float(h1);
        __nv_bfloat16 h2 = __float2bfloat16_rn(r2);
        size_t oi = (size_t)row * DD + c;
        o0[oi] = h0; o1[oi] = h1; o2[oi] = h2;
    }
}

__global__ void split3(const float* __restrict__ x, __nv_bfloat16* __restrict__ o0,
                       __nv_bfloat16* __restrict__ o1, __nv_bfloat16* __restrict__ o2, int n) {
    int i = blockIdx.x * 256 + threadIdx.x;
    if (i < n) {
        float v = x[i];
        __nv_bfloat16 h0 = __float2bfloat16_rn(v);
        float r1 = v - __bfloat162float(h0);
        __nv_bfloat16 h1 = __float2bfloat16_rn(r1);
        float r2 = r1 - __bfloat162float(h1);
        __nv_bfloat16 h2 = __float2bfloat16_rn(r2);
        o0[i] = h0; o1[i] = h1; o2[i] = h2;
    }
}

// ---------------- tiling constants ----------------
#define KT 32
#define ROWB 80
#define TILE10 (128 * ROWB)
#define STAGE_B (2 * TILE10)
#define SMEM_GEMM (4 * STAGE_B)
#define NTHR 256
#define QTILES ((BB * MM) / 128)     // 64

// ---------------- merged projection GEMM (Q tiles then K tiles in one grid) ----------------
__global__ void __launch_bounds__(NTHR, 2) mma_proj(
    const __nv_bfloat16* __restrict__ qA0, const __nv_bfloat16* __restrict__ qA1,
    const __nv_bfloat16* __restrict__ qA2,
    const __nv_bfloat16* __restrict__ qB0, const __nv_bfloat16* __restrict__ qB1,
    const __nv_bfloat16* __restrict__ qB2,
    float* __restrict__ qof, __half* __restrict__ qoh,
    const __nv_bfloat16* __restrict__ sA0, const __nv_bfloat16* __restrict__ sA1,
    const __nv_bfloat16* __restrict__ sA2,
    const __nv_bfloat16* __restrict__ sB0, const __nv_bfloat16* __restrict__ sB1,
    const __nv_bfloat16* __restrict__ sB2,
    float* __restrict__ sof, __half* __restrict__ soh) {
    extern __shared__ __align__(128) char smem[];
    const int NCHUNK_M = 96;
    const int tid  = threadIdx.x;
    const int lane = tid & 31, warp = tid >> 5;
    const int wm = warp >> 2, wn = warp & 3;

    const bool isQ = (blockIdx.y < QTILES);
    const int mtile = isQ ? blockIdx.y : (blockIdx.y - QTILES);
    const int m0 = mtile * 128, n0 = blockIdx.x * 128;

    const __nv_bfloat16* A0 = isQ ? qA0 : sA0;
    const __nv_bfloat16* A1 = isQ ? qA1 : sA1;
    const __nv_bfloat16* A2 = isQ ? qA2 : sA2;
    const __nv_bfloat16* B0 = isQ ? qB0 : sB0;
    const __nv_bfloat16* B1 = isQ ? qB1 : sB1;
    const __nv_bfloat16* B2 = isQ ? qB2 : sB2;
    float*  of = isQ ? qof : sof;
    __half* oh = isQ ? qoh : soh;

    const __nv_bfloat16* Abase = A0 + (size_t)m0 * DD;
    const __nv_bfloat16* Bbase = B0 + (size_t)n0 * DD;
    const uint32_t da1 = (uint32_t)(A1 - A0), da2 = (uint32_t)(A2 - A0);
    const uint32_t db1 = (uint32_t)(B1 - B0), db2 = (uint32_t)(B2 - B0);

    const uint32_t sbase = smem_u32(smem);
    const int r0i = tid >> 2, c0i = tid & 3;
    const int r1i = r0i + 64;

    const uint32_t aRowOff = (uint32_t)(((lane & 7) + (lane & 8)) * ROWB + (lane & 16));
    const uint32_t bRowOff = (uint32_t)(((lane & 7) + ((lane & 16) >> 1)) * ROWB + ((lane & 8) << 1));

    float acc[4][4][4];
#pragma unroll
    for (int i = 0; i < 4; i++)
#pragma unroll
        for (int j = 0; j < 4; j++)
#pragma unroll
            for (int q = 0; q < 4; q++) acc[i][j][q] = 0.f;

    auto issue = [&](int c) {
        int seg = c >> 4, k0 = (c & 15) * KT;
        // small-first: 0:a0b2 1:a2b0 2:a1b1 3:a0b1 4:a1b0 5:a0b0
        uint32_t oa = (seg == 1) ? da2 : ((seg == 2) || (seg == 4)) ? da1 : 0u;
        uint32_t ob = (seg == 0) ? db2 : ((seg == 2) || (seg == 3)) ? db1 : 0u;
        uint32_t sb0 = sbase + (c & 3) * STAGE_B;
        const __nv_bfloat16* ap = Abase + oa + k0;
        const __nv_bfloat16* bp = Bbase + ob + k0;
        CP16(sb0 + (uint32_t)(r0i * ROWB + c0i * 16), ap + (size_t)r0i * DD + c0i * 8);
        CP16(sb0 + (uint32_t)(r1i * ROWB + c0i * 16), ap + (size_t)r1i * DD + c0i * 8);
        uint32_t sb1 = sb0 + TILE10;
        CP16(sb1 + (uint32_t)(r0i * ROWB + c0i * 16), bp + (size_t)r0i * DD + c0i * 8);
        CP16(sb1 + (uint32_t)(r1i * ROWB + c0i * 16), bp + (size_t)r1i * DD + c0i * 8);
    };

    issue(0); CP_COMMIT();
    issue(1); CP_COMMIT();
    issue(2); CP_COMMIT();

    for (int c = 0; c < NCHUNK_M; c++) {
        CP_WAIT2();
        __syncthreads();
        int cn = c + 3;
        if (cn < NCHUNK_M) issue(cn);
        CP_COMMIT();

        uint32_t sa = sbase + (c & 3) * STAGE_B;
        uint32_t sb = sa + TILE10;
#pragma unroll
        for (int k16 = 0; k16 < 2; k16++) {
            uint32_t a[4][4];
#pragma unroll
            for (int mt = 0; mt < 4; mt++) {
                uint32_t addr = sa + (uint32_t)((wm * 64 + mt * 16) * ROWB) + aRowOff + k16 * 32;
                LDSM4(a[mt][0], a[mt][1], a[mt][2], a[mt][3], addr);
            }
            uint32_t bfr[2][4];
#pragma unroll
            for (int nt2 = 0; nt2 < 2; nt2++) {
                uint32_t addr = sb + (uint32_t)((wn * 32 + nt2 * 16) * ROWB) + bRowOff + k16 * 32;
                LDSM4(bfr[nt2][0], bfr[nt2][1], bfr[nt2][2], bfr[nt2][3], addr);
            }
#pragma unroll
            for (int mt = 0; mt < 4; mt++)
#pragma unroll
                for (int nt = 0; nt < 4; nt++)
                    MMA_BF16(acc[mt][nt], a[mt], bfr[nt >> 1][(nt & 1) * 2],
                             bfr[nt >> 1][(nt & 1) * 2 + 1]);
        }
    }
    CP_WAIT0();

    const int mrow = lane >> 2, ncol = (lane & 3) * 2;
#pragma unroll
    for (int mt = 0; mt < 4; mt++) {
#pragma unroll
        for (int half = 0; half < 2; half++) {
            int gr = m0 + wm * 64 + mt * 16 + mrow + half * 8;
            size_t base = (size_t)gr * DD + n0 + wn * 32 + ncol;
#pragma unroll
            for (int nt = 0; nt < 4; nt++) {
                float vx = acc[mt][nt][half * 2 + 0];
                float vy = acc[mt][nt][half * 2 + 1];
                float2 fv; fv.x = vx; fv.y = vy;
                *reinterpret_cast<float2*>(of + base + nt * 8) = fv;
                __half2 hv; hv.x = __float2half_rn(vx); hv.y = __float2half_rn(vy);
                *reinterpret_cast<__half2*>(oh + base + nt * 8) = hv;
            }
        }
    }
}

// ---------------- logits GEMM (fp16 single-product, 16 chunks, sigmoid epilogue) ----------------
__global__ void __launch_bounds__(NTHR, 2) mma_logits(
    const __half* __restrict__ Q, const __half* __restrict__ K,
    float* __restrict__ gout,
    const float* __restrict__ taup, const float* __restrict__ biasp) {
    extern __shared__ __align__(128) char smem[];
    const int NCHUNK_M = 16;
    const int tid  = threadIdx.x;
    const int lane = tid & 31, warp = tid >> 5;
    const int wm = warp >> 2, wn = warp & 3;
    const int m0 = blockIdx.y * 128, n0 = blockIdx.x * 128;

    const __half* Abase = Q + (size_t)blockIdx.z * MM * DD + (size_t)m0 * DD;
    const __half* Bbase = K + (size_t)blockIdx.z * NN * DD + (size_t)n0 * DD;

    const uint32_t sbase = smem_u32(smem);
    const int r0i = tid >> 2, c0i = tid & 3;
    const int r1i = r0i + 64;

    const uint32_t aRowOff = (uint32_t)(((lane & 7) + (lane & 8)) * ROWB + (lane & 16));
    const uint32_t bRowOff = (uint32_t)(((lane & 7) + ((lane & 16) >> 1)) * ROWB + ((lane & 8) << 1));

    float acc[4][4][4];
#pragma unroll
    for (int i = 0; i < 4; i++)
#pragma unroll
        for (int j = 0; j < 4; j++)
#pragma unroll
            for (int q = 0; q < 4; q++) acc[i][j][q] = 0.f;

    auto issue = [&](int c) {
        int k0 = c * KT;
        uint32_t sb0 = sbase + (c & 3) * STAGE_B;
        const __half* ap = Abase + k0;
        const __half* bp = Bbase + k0;
        CP16(sb0 + (uint32_t)(r0i * ROWB + c0i * 16), ap + (size_t)r0i * DD + c0i * 8);
        CP16(sb0 + (uint32_t)(r1i * ROWB + c0i * 16), ap + (size_t)r1i * DD + c0i * 8);
        uint32_t sb1 = sb0 + TILE10;
        CP16(sb1 + (uint32_t)(r0i * ROWB + c0i * 16), bp + (size_t)r0i * DD + c0i * 8);
        CP16(sb1 + (uint32_t)(r1i * ROWB + c0i * 16), bp + (size_t)r1i * DD + c0i * 8);
    };

    issue(0); CP_COMMIT();
    issue(1); CP_COMMIT();
    issue(2); CP_COMMIT();

    for (int c = 0; c < NCHUNK_M; c++) {
        CP_WAIT2();
        __syncthreads();
        int cn = c + 3;
        if (cn < NCHUNK_M) issue(cn);
        CP_COMMIT();

        uint32_t sa = sbase + (c & 3) * STAGE_B;
        uint32_t sb = sa + TILE10;
#pragma unroll
        for (int k16 = 0; k16 < 2; k16++) {
            uint32_t a[4][4];
#pragma unroll
            for (int mt = 0; mt < 4; mt++) {
                uint32_t addr = sa + (uint32_t)((wm * 64 + mt * 16) * ROWB) + aRowOff + k16 * 32;
                LDSM4(a[mt][0], a[mt][1], a[mt][2], a[mt][3], addr);
            }
            uint32_t bfr[2][4];
#pragma unroll
            for (int nt2 = 0; nt2 < 2; nt2++) {
                uint32_t addr = sb + (uint32_t)((wn * 32 + nt2 * 16) * ROWB) + bRowOff + k16 * 32;
                LDSM4(bfr[nt2][0], bfr[nt2][1], bfr[nt2][2], bfr[nt2][3], addr);
            }
#pragma unroll
            for (int mt = 0; mt < 4; mt++)
#pragma unroll
                for (int nt = 0; nt < 4; nt++)
                    MMA_FP16(acc[mt][nt], a[mt], bfr[nt >> 1][(nt & 1) * 2],
                             bfr[nt >> 1][(nt & 1) * 2 + 1]);
        }
    }
    CP_WAIT0();

    const int mrow = lane >> 2, ncol = (lane & 3) * 2;
    float alpha = log1pf(expf(*taup)) + 1e-6f;
    float beta  = *biasp;
    float* Cb = gout + (size_t)blockIdx.z * MM * NN;
#pragma unroll
    for (int mt = 0; mt < 4; mt++) {
#pragma unroll
        for (int half = 0; half < 2; half++) {
            int gr = m0 + wm * 64 + mt * 16 + mrow + half * 8;
            float* crow = Cb + (size_t)gr * NN + n0 + wn * 32 + ncol;
#pragma unroll
            for (int nt = 0; nt < 4; nt++) {
                float2 f;
                f.x = 1.f / (1.f + expf(-(alpha * acc[mt][nt][half * 2 + 0] + beta)));
                f.y = 1.f / (1.f + expf(-(alpha * acc[mt][nt][half * 2 + 1] + beta)));
                *reinterpret_cast<float2*>(crow + nt * 8) = f;
            }
        }
    }
}

// ---------------- prior / rho-inverse per batch ----------------
__global__ void prior_kernel(const int* __restrict__ y) {
    int b = blockIdx.x;
    __shared__ int cnt[CC];
    int t = threadIdx.x;
    if (t < CC) cnt[t] = 0;
    __syncthreads();
    for (int i = t; i < NN; i += 256) atomicAdd(&cnt[y[(size_t)b * NN + i]], 1);
    __syncthreads();
    if (t == 0) {
        int tot = 0;
        for (int c = 0; c < CC; c++) tot += cnt[c];
        float denom = fmaxf((float)tot, 1.f);
        for (int c = 0; c < CC; c++) {
            float pr = (float)cnt[c] / denom;
            g_prior[b * CC + c]  = pr;
            g_rhoinv[b * CC + c] = 1.f / fmaxf(1.f - pr, 1e-6f);
        }
    }
}

// ---------------- top-k select (fused passes, logit band + fp64 fix-up) ----------------
__device__ __forceinline__ unsigned f2u(float f) {
    unsigned u = __float_as_uint(f);
    return (u & 0x80000000u) ? ~u : (u | 0x80000000u);
}

#define BAND_CAP 64

__global__ void select_agg(const int* __restrict__ y,
                           const float* __restrict__ qf, const float* __restrict__ kf,
                           const float* __restrict__ taup, const float* __restrict__ biasp,
                           float* __restrict__ out) {
    int m = blockIdx.x, b = blockIdx.y;
    const float* grow = g_gamma + ((size_t)b * MM + m) * NN;
    __shared__ float gs[NN];
    __shared__ unsigned short cand[NN];
    __shared__ unsigned whist[8][256];
    __shared__ unsigned hist[256];
    __shared__ unsigned sh_pref, sh_k, sh_nc;
    __shared__ float S[CC], W[CC], sh_prior[CC], sh_rinv[CC];
    __shared__ unsigned cntk;
    __shared__ unsigned sh_above, sh_nb, sh_kept;
    __shared__ unsigned short bandIdx[BAND_CAP];
    __shared__ unsigned char bandKeep[BAND_CAP];
    __shared__ double Lband[BAND_CAP];
    __shared__ float Gband[BAND_CAP];
    const int t = threadIdx.x;
    const int warp = t >> 5, lane = t & 31;

    for (int i = t; i < 8 * 256; i += 256) (&whist[0][0])[i] = 0u;
    if (t < CC) {
        S[t] = 0.f; W[t] = 0.f;
        sh_prior[t] = g_prior[b * CC + t];
        sh_rinv[t]  = g_rhoinv[b * CC + t];
    }
    if (t == 0) { cntk = 0; sh_nc = 0; sh_above = 0; sh_nb = 0; sh_kept = 0; }
    __syncthreads();

    // ---- fused load + pass-1 histogram ----
    for (int i = t; i < NN / 4; i += 256) {
        float4 v = reinterpret_cast<const float4*>(grow)[i];
        reinterpret_cast<float4*>(gs)[i] = v;
        atomicAdd(&whist[warp][f2u(v.x) >> 24], 1u);
        atomicAdd(&whist[warp][f2u(v.y) >> 24], 1u);
        atomicAdd(&whist[warp][f2u(v.z) >> 24], 1u);
        atomicAdd(&whist[warp][f2u(v.w) >> 24], 1u);
    }
    __syncthreads();
    {
        unsigned h = 0;
#pragma unroll
        for (int w = 0; w < 8; w++) h += whist[w][t];
        hist[t] = h;
    }
    __syncthreads();
    if (t == 0) {
        unsigned acc = 0, krem = KTOP;
        int bin = 0;
        for (int i = 255; i >= 0; i--) {
            unsigned h = hist[i];
            if (acc + h >= KTOP) { bin = i; krem = KTOP - acc; break; }
            acc += h;
        }
        sh_pref = (unsigned)bin << 24;
        sh_k = krem;
    }
    __syncthreads();
    unsigned prefix = sh_pref;

    for (int i = t; i < NN; i += 256) {
        if ((f2u(gs[i]) & 0xFF000000u) == prefix) {
            unsigned idx = atomicAdd(&sh_nc, 1u);
            cand[idx] = (unsigned short)i;
        }
    }
    __syncthreads();
    const int ncand = (int)sh_nc;

#pragma unroll
    for (int shift = 16; shift >= 0; shift -= 8) {
        hist[t] = 0;
        __syncthreads();
        unsigned pm = 0xFFFFFFFFu << (shift + 8);
        for (int j = t; j < ncand; j += 256) {
            unsigned u = f2u(gs[cand[j]]);
            if ((u & pm) == prefix) atomicAdd(&hist[(u >> shift) & 255u], 1u);
        }
        __syncthreads();
        if (t == 0) {
            unsigned kneed = sh_k, acc = 0, krem = kneed;
            int bin = 0;
            for (int i = 255; i >= 0; i--) {
                unsigned h = hist[i];
                if (acc + h >= kneed) { bin = i; krem = kneed - acc; break; }
                acc += h;
            }
            sh_pref = prefix | ((unsigned)bin << shift);
            sh_k = krem;
        }
        __syncthreads();
        prefix = sh_pref;
    }
    const float v64f = __uint_as_float(prefix & 0x7FFFFFFFu);

    // ---- band bounds: +/- 8e-3 in LOGIT space ----
    float hi, lo;
    if (v64f > 0.999999f || v64f < 1e-6f) {
        hi = v64f + 2e-5f;
        lo = v64f - 2e-5f;
    } else {
        const float LD = 8e-3f;
        float l64 = logf(v64f / (1.f - v64f));
        hi = 1.f / (1.f + expf(-(l64 + LD)));
        lo = 1.f / (1.f + expf(-(l64 - LD)));
        hi = fmaxf(hi, v64f + 1e-7f);
        lo = fminf(lo, v64f - 1e-7f);
    }

    // ---- fused: accumulate DEFINITE members (kept in every path) + gather band ----
    const int* yrow = y + (size_t)b * NN;
    for (int i = t; i < NN; i += 256) {
        float g = gs[i];
        if (g > hi) {
            atomicAdd(&sh_above, 1u);
            int c = yrow[i];
            atomicAdd(&S[c], g);
            atomicAdd(&W[c], (1.f - g) * sh_rinv[c]);
        } else if (g >= lo) {
            unsigned idx = atomicAdd(&sh_nb, 1u);
            if (idx < BAND_CAP) bandIdx[idx] = (unsigned short)i;
        }
    }
    __syncthreads();
    const int above = (int)sh_above;
    const int nb = (int)sh_nb;
    const int need = (int)KTOP - above;
    const bool fallback = (nb > BAND_CAP) || (need < 0);

    if (!fallback) {
        if (nb > need) {
            // fp64 exact dot of band members from fp32 Q/K
            const size_t qoff = ((size_t)b * MM + m) * DD;
            const float* qr = qf + qoff;
            for (int j = warp; j < nb; j += 8) {
                int n = bandIdx[j];
                const float* kr = kf + ((size_t)b * NN + n) * DD;
                double acc = 0.0;
                for (int e = lane; e < DD; e += 32)
                    acc = fma((double)qr[e], (double)kr[e], acc);
#pragma unroll
                for (int o = 16; o > 0; o >>= 1)
                    acc += __shfl_down_sync(0xFFFFFFFFu, acc, o);
                if (lane == 0) Lband[j] = acc;
            }
            __syncthreads();
            if (t < nb) {
                float alpha = log1pf(expf(*taup)) + 1e-6f;
                float beta  = *biasp;
                float dotf = (float)Lband[t];
                float l = __fadd_rn(__fmul_rn(alpha, dotf), beta);
                Gband[t] = 1.f / (1.f + expf(-l));
            }
            __syncthreads();
            if (t < nb) {
                float gt = Gband[t];
                int rank = 0;
                for (int j = 0; j < nb; j++) rank += (Gband[j] > gt);
                unsigned char kp = (rank < need) ? 1 : 0;
                bandKeep[t] = kp;
                if (kp) atomicAdd(&sh_kept, 1u);
            }
            __syncthreads();
            for (int j = t; j < nb; j += 256) {
                if (bandKeep[j]) {
                    int i = bandIdx[j];
                    float g = Gband[j];
                    int c = yrow[i];
                    atomicAdd(&S[c], g);
                    atomicAdd(&W[c], (1.f - g) * sh_rinv[c]);
                }
            }
            if (t == 0) cntk = (unsigned)above + sh_kept;
        } else {
            for (int j = t; j < nb; j += 256) {
                int i = bandIdx[j];
                float g = gs[i];
                int c = yrow[i];
                atomicAdd(&S[c], g);
                atomicAdd(&W[c], (1.f - g) * sh_rinv[c]);
            }
            if (t == 0) cntk = (unsigned)(above + nb);
        }
        __syncthreads();
    } else {
        // pathological band: add remaining members with >=prefix semantics, excluding
        // already-accumulated definite (g > hi) ones.
        for (int i = t; i < NN; i += 256) {
            float g = gs[i];
            if (g <= hi && f2u(g) >= prefix) {
                int c = yrow[i];
                atomicAdd(&S[c], g);
                atomicAdd(&W[c], (1.f - g) * sh_rinv[c]);
                atomicAdd(&sh_kept, 1u);
            }
        }
        __syncthreads();
        if (t == 0) cntk = (unsigned)above + sh_kept;
        __syncthreads();
    }

    if (t == 0) {
        float Wt = 0.f;
        for (int c = 0; c < CC; c++) Wt += W[c];
        float dq = fmaxf((float)cntk, 1.f);
        float p[CC];
        float sum = 0.f;
        for (int c = 0; c < CC; c++) {
            float v = S[c] + sh_prior[c] * (Wt - W[c]);
            v = fmaxf(v, 0.f) / dq;
            p[c] = v;
            sum += v;
        }
        float inv = 1.f / fmaxf(sum, 1e-12f);
        float* orow = out + ((size_t)b * MM + m) * CC;
        for (int c = 0; c < CC; c++) orow[c] = p[c] * inv;
    }
}

// ---------------- launcher ----------------
extern "C" void kernel_launch(void* const* d_in, const int* in_sizes, int n_in,
                              void* d_out, int out_size) {
    const float* Hs   = (const float*)d_in[0];
    const float* Hq   = (const float*)d_in[1];
    const int*   ys   = (const int*)d_in[2];
    const float* lnw  = (const float*)d_in[4];
    const float* lnb  = (const float*)d_in[5];
    const float* WQ   = (const float*)d_in[6];
    const float* WK   = (const float*)d_in[7];
    const float* taup = (const float*)d_in[8];
    const float* bisp = (const float*)d_in[9];
    float* out = (float*)d_out;

    __nv_bfloat16 *hqB, *hsB, *wqB, *wkB;
    float *qF, *kF;
    __half *qH, *kH;
    float* Gam;
    cudaGetSymbolAddress((void**)&hqB, g_hq);
    cudaGetSymbolAddress((void**)&hsB, g_hs);
    cudaGetSymbolAddress((void**)&wqB, g_wq);
    cudaGetSymbolAddress((void**)&wkB, g_wk);
    cudaGetSymbolAddress((void**)&qF, g_qf);
    cudaGetSymbolAddress((void**)&kF, g_kf);
    cudaGetSymbolAddress((void**)&qH, g_qh);
    cudaGetSymbolAddress((void**)&kH, g_kh);
    cudaGetSymbolAddress((void**)&Gam, g_gamma);

    const size_t HQ = (size_t)BB * MM * DD;
    const size_t HS = (size_t)BB * NN * DD;
    const size_t WW = (size_t)DD * DD;

    cudaFuncSetAttribute(mma_proj, cudaFuncAttributeMaxDynamicSharedMemorySize, SMEM_GEMM);
    cudaFuncSetAttribute(mma_logits, cudaFuncAttributeMaxDynamicSharedMemorySize, SMEM_GEMM);

    // 1) LayerNorm + splits
    ln_split<<<BB * MM, 128>>>(Hq, lnw, lnb, hqB, hqB + HQ, hqB + 2 * HQ);
    ln_split<<<BB * NN, 128>>>(Hs, lnw, lnb, hsB, hsB + HS, hsB + 2 * HS);
    split3<<<(int)((WW + 255) / 256), 256>>>(WQ, wqB, wqB + WW, wqB + 2 * WW, (int)WW);
    split3<<<(int)((WW + 255) / 256), 256>>>(WK, wkB, wkB + WW, wkB + 2 * WW, (int)WW);

    // 2) priors
    prior_kernel<<<BB, 256>>>(ys);

    // 3) merged projections (Q tiles + K tiles in one grid; per-tile arithmetic identical)
    mma_proj<<<dim3(DD / 128, QTILES + (BB * NN) / 128, 1), NTHR, SMEM_GEMM>>>(
        hqB, hqB + HQ, hqB + 2 * HQ, wqB, wqB + WW, wqB + 2 * WW, qF, qH,
        hsB, hsB + HS, hsB + 2 * HS, wkB, wkB + WW, wkB + 2 * WW, kF, kH);

    // 4) gamma~ = sigmoid(tau * [fp16 Q K^T] + bias) — single-product, 16 chunks
    mma_logits<<<dim3(NN / 128, MM / 128, BB), NTHR, SMEM_GEMM>>>(qH, kH, Gam, taup, bisp);

    // 5) top-k select (fused passes, logit band + fp64 fix-up) + aggregate
    select_agg<<<dim3(MM, BB), 256>>>(ys, qF, kF, taup, bisp, out);
}

// round 16
// speedup vs baseline: 1.7659x; 1.0469x over previous
#include <cuda_runtime.h>
#include <cuda_bf16.h>
#include <cuda_fp16.h>
#include <cstdint>

#define BB 4
#define NN 4096
#define MM 2048
#define DD 512
#define CC 10
#define KTOP 64u

// ---------------- scratch (device globals; no cudaMalloc allowed) ----------------
__device__ __align__(256) __nv_bfloat16 g_hq[3][BB * MM * DD];
__device__ __align__(256) __nv_bfloat16 g_hs[3][BB * NN * DD];
__device__ __align__(256) __nv_bfloat16 g_wq[3][DD * DD];
__device__ __align__(256) __nv_bfloat16 g_wk[3][DD * DD];
__device__ __align__(256) float  g_qf[BB * MM * DD];
__device__ __align__(256) float  g_kf[BB * NN * DD];
__device__ __align__(256) __half g_qh[BB * MM * DD];
__device__ __align__(256) __half g_kh[BB * NN * DD];
__device__ float g_logit[(size_t)BB * MM * NN];   // raw logits (sigmoid deferred)
__device__ float g_prior[BB * CC];
__device__ float g_rhoinv[BB * CC];

// ---------------- helpers ----------------
__device__ __forceinline__ uint32_t smem_u32(const void* p) {
    uint32_t a;
    asm("{ .reg .u64 t; cvta.to.shared.u64 t, %1; cvt.u32.u64 %0, t; }" : "=r"(a) : "l"(p));
    return a;
}

#define CP16(dst, src) \
    asm volatile("cp.async.cg.shared.global [%0], [%1], 16;" :: "r"(dst), "l"(src))
#define CP_COMMIT() asm volatile("cp.async.commit_group;" ::: "memory")
#define CP_WAIT2()  asm volatile("cp.async.wait_group 2;" ::: "memory")
#define CP_WAIT0()  asm volatile("cp.async.wait_group 0;" ::: "memory")

#define LDSM4(r0, r1, r2, r3, addr) \
    asm volatile("ldmatrix.sync.aligned.m8n8.x4.shared.b16 {%0,%1,%2,%3}, [%4];" \
                 : "=r"(r0), "=r"(r1), "=r"(r2), "=r"(r3) : "r"(addr))

#define MMA_BF16(d, a, b0, b1) \
    asm volatile("mma.sync.aligned.m16n8k16.row.col.f32.bf16.bf16.f32 " \
                 "{%0,%1,%2,%3}, {%4,%5,%6,%7}, {%8,%9}, {%0,%1,%2,%3};" \
                 : "+f"((d)[0]), "+f"((d)[1]), "+f"((d)[2]), "+f"((d)[3]) \
                 : "r"((a)[0]), "r"((a)[1]), "r"((a)[2]), "r"((a)[3]), "r"(b0), "r"(b1))

#define MMA_FP16(d, a, b0, b1) \
    asm volatile("mma.sync.aligned.m16n8k16.row.col.f32.f16.f16.f32 " \
                 "{%0,%1,%2,%3}, {%4,%5,%6,%7}, {%8,%9}, {%0,%1,%2,%3};" \
                 : "+f"((d)[0]), "+f"((d)[1]), "+f"((d)[2]), "+f"((d)[3]) \
                 : "r"((a)[0]), "r"((a)[1]), "r"((a)[2]), "r"((a)[3]), "r"(b0), "r"(b1))

// ---------------- LayerNorm fused with 3-way bf16 split ----------------
__global__ void ln_split(const float* __restrict__ x, const float* __restrict__ w,
                         const float* __restrict__ b,
                         __nv_bfloat16* __restrict__ o0, __nv_bfloat16* __restrict__ o1,
                         __nv_bfloat16* __restrict__ o2) {
    int row = blockIdx.x;
    const float* xr = x + (size_t)row * DD;
    int t = threadIdx.x;
    float v[4];
    float s = 0.f, s2 = 0.f;
#pragma unroll
    for (int i = 0; i < 4; i++) {
        v[i] = xr[t + i * 128];
        s += v[i];
        s2 += v[i] * v[i];
    }
#pragma unroll
    for (int o = 16; o > 0; o >>= 1) {
        s  += __shfl_down_sync(0xFFFFFFFFu, s, o);
        s2 += __shfl_down_sync(0xFFFFFFFFu, s2, o);
    }
    __shared__ float ps[4], ps2[4];
    if ((t & 31) == 0) { ps[t >> 5] = s; ps2[t >> 5] = s2; }
    __syncthreads();
    s  = ps[0] + ps[1] + ps[2] + ps[3];
    s2 = ps2[0] + ps2[1] + ps2[2] + ps2[3];
    float mu  = s * (1.f / DD);
    float var = s2 * (1.f / DD) - mu * mu;
    float rs  = 1.f / sqrtf(var + 1e-5f);
#pragma unroll
    for (int i = 0; i < 4; i++) {
        int c = t + i * 128;
        float val = (v[i] - mu) * rs * w[c] + b[c];
        __nv_bfloat16 h0 = __float2bfloat16_rn(val);
        float r1 = val - __bfloat162float(h0);
        __nv_bfloat16 h1 = __float2bfloat16_rn(r1);
        float r2 = r1 - __bfloat162float(h1);
        __nv_bfloat16 h2 = __float2bfloat16_rn(r2);
        size_t oi = (size_t)row * DD + c;
        o0[oi] = h0; o1[oi] = h1; o2[oi] = h2;
    }
}

__global__ void split3(const float* __restrict__ x, __nv_bfloat16* __restrict__ o0,
                       __nv_bfloat16* __restrict__ o1, __nv_bfloat16* __restrict__ o2, int n) {
    int i = blockIdx.x * 256 + threadIdx.x;
    if (i < n) {
        float v = x[i];
        __nv_bfloat16 h0 = __float2bfloat16_rn(v);
        float r1 = v - __bfloat162float(h0);
        __nv_bfloat16 h1 = __float2bfloat16_rn(r1);
        float r2 = r1 - __bfloat162float(h1);
        __nv_bfloat16 h2 = __float2bfloat16_rn(r2);
        o0[i] = h0; o1[i] = h1; o2[i] = h2;
    }
}

// ---------------- tiling constants ----------------
#define KT 32
#define ROWB 80
#define TILE10 (128 * ROWB)
#define STAGE_B (2 * TILE10)
#define SMEM_GEMM (4 * STAGE_B)
#define NTHR 256
#define QTILES ((BB * MM) / 128)     // 64

// ---------------- merged projection GEMM (Q tiles then K tiles in one grid) ----------------
__global__ void __launch_bounds__(NTHR, 2) mma_proj(
    const __nv_bfloat16* __restrict__ qA0, const __nv_bfloat16* __restrict__ qA1,
    const __nv_bfloat16* __restrict__ qA2,
    const __nv_bfloat16* __restrict__ qB0, const __nv_bfloat16* __restrict__ qB1,
    const __nv_bfloat16* __restrict__ qB2,
    float* __restrict__ qof, __half* __restrict__ qoh,
    const __nv_bfloat16* __restrict__ sA0, const __nv_bfloat16* __restrict__ sA1,
    const __nv_bfloat16* __restrict__ sA2,
    const __nv_bfloat16* __restrict__ sB0, const __nv_bfloat16* __restrict__ sB1,
    const __nv_bfloat16* __restrict__ sB2,
    float* __restrict__ sof, __half* __restrict__ soh) {
    extern __shared__ __align__(128) char smem[];
    const int NCHUNK_M = 96;
    const int tid  = threadIdx.x;
    const int lane = tid & 31, warp = tid >> 5;
    const int wm = warp >> 2, wn = warp & 3;

    const bool isQ = (blockIdx.y < QTILES);
    const int mtile = isQ ? blockIdx.y : (blockIdx.y - QTILES);
    const int m0 = mtile * 128, n0 = blockIdx.x * 128;

    const __nv_bfloat16* A0 = isQ ? qA0 : sA0;
    const __nv_bfloat16* A1 = isQ ? qA1 : sA1;
    const __nv_bfloat16* A2 = isQ ? qA2 : sA2;
    const __nv_bfloat16* B0 = isQ ? qB0 : sB0;
    const __nv_bfloat16* B1 = isQ ? qB1 : sB1;
    const __nv_bfloat16* B2 = isQ ? qB2 : sB2;
    float*  of = isQ ? qof : sof;
    __half* oh = isQ ? qoh : soh;

    const __nv_bfloat16* Abase = A0 + (size_t)m0 * DD;
    const __nv_bfloat16* Bbase = B0 + (size_t)n0 * DD;
    const uint32_t da1 = (uint32_t)(A1 - A0), da2 = (uint32_t)(A2 - A0);
    const uint32_t db1 = (uint32_t)(B1 - B0), db2 = (uint32_t)(B2 - B0);

    const uint32_t sbase = smem_u32(smem);
    const int r0i = tid >> 2, c0i = tid & 3;
    const int r1i = r0i + 64;

    const uint32_t aRowOff = (uint32_t)(((lane & 7) + (lane & 8)) * ROWB + (lane & 16));
    const uint32_t bRowOff = (uint32_t)(((lane & 7) + ((lane & 16) >> 1)) * ROWB + ((lane & 8) << 1));

    float acc[4][4][4];
#pragma unroll
    for (int i = 0; i < 4; i++)
#pragma unroll
        for (int j = 0; j < 4; j++)
#pragma unroll
            for (int q = 0; q < 4; q++) acc[i][j][q] = 0.f;

    auto issue = [&](int c) {
        int seg = c >> 4, k0 = (c & 15) * KT;
        uint32_t oa = (seg == 1) ? da2 : ((seg == 2) || (seg == 4)) ? da1 : 0u;
        uint32_t ob = (seg == 0) ? db2 : ((seg == 2) || (seg == 3)) ? db1 : 0u;
        uint32_t sb0 = sbase + (c & 3) * STAGE_B;
        const __nv_bfloat16* ap = Abase + oa + k0;
        const __nv_bfloat16* bp = Bbase + ob + k0;
        CP16(sb0 + (uint32_t)(r0i * ROWB + c0i * 16), ap + (size_t)r0i * DD + c0i * 8);
        CP16(sb0 + (uint32_t)(r1i * ROWB + c0i * 16), ap + (size_t)r1i * DD + c0i * 8);
        uint32_t sb1 = sb0 + TILE10;
        CP16(sb1 + (uint32_t)(r0i * ROWB + c0i * 16), bp + (size_t)r0i * DD + c0i * 8);
        CP16(sb1 + (uint32_t)(r1i * ROWB + c0i * 16), bp + (size_t)r1i * DD + c0i * 8);
    };

    issue(0); CP_COMMIT();
    issue(1); CP_COMMIT();
    issue(2); CP_COMMIT();

    for (int c = 0; c < NCHUNK_M; c++) {
        CP_WAIT2();
        __syncthreads();
        int cn = c + 3;
        if (cn < NCHUNK_M) issue(cn);
        CP_COMMIT();

        uint32_t sa = sbase + (c & 3) * STAGE_B;
        uint32_t sb = sa + TILE10;
#pragma unroll
        for (int k16 = 0; k16 < 2; k16++) {
            uint32_t a[4][4];
#pragma unroll
            for (int mt = 0; mt < 4; mt++) {
                uint32_t addr = sa + (uint32_t)((wm * 64 + mt * 16) * ROWB) + aRowOff + k16 * 32;
                LDSM4(a[mt][0], a[mt][1], a[mt][2], a[mt][3], addr);
            }
            uint32_t bfr[2][4];
#pragma unroll
            for (int nt2 = 0; nt2 < 2; nt2++) {
                uint32_t addr = sb + (uint32_t)((wn * 32 + nt2 * 16) * ROWB) + bRowOff + k16 * 32;
                LDSM4(bfr[nt2][0], bfr[nt2][1], bfr[nt2][2], bfr[nt2][3], addr);
            }
#pragma unroll
            for (int mt = 0; mt < 4; mt++)
#pragma unroll
                for (int nt = 0; nt < 4; nt++)
                    MMA_BF16(acc[mt][nt], a[mt], bfr[nt >> 1][(nt & 1) * 2],
                             bfr[nt >> 1][(nt & 1) * 2 + 1]);
        }
    }
    CP_WAIT0();

    const int mrow = lane >> 2, ncol = (lane & 3) * 2;
#pragma unroll
    for (int mt = 0; mt < 4; mt++) {
#pragma unroll
        for (int half = 0; half < 2; half++) {
            int gr = m0 + wm * 64 + mt * 16 + mrow + half * 8;
            size_t base = (size_t)gr * DD + n0 + wn * 32 + ncol;
#pragma unroll
            for (int nt = 0; nt < 4; nt++) {
                float vx = acc[mt][nt][half * 2 + 0];
                float vy = acc[mt][nt][half * 2 + 1];
                float2 fv; fv.x = vx; fv.y = vy;
                *reinterpret_cast<float2*>(of + base + nt * 8) = fv;
                __half2 hv; hv.x = __float2half_rn(vx); hv.y = __float2half_rn(vy);
                *reinterpret_cast<__half2*>(oh + base + nt * 8) = hv;
            }
        }
    }
}

// ---------------- logits GEMM (fp16 single-product; stores RAW logits) ----------------
__global__ void __launch_bounds__(NTHR, 2) mma_logits(
    const __half* __restrict__ Q, const __half* __restrict__ K,
    float* __restrict__ lout,
    const float* __restrict__ taup, const float* __restrict__ biasp) {
    extern __shared__ __align__(128) char smem[];
    const int NCHUNK_M = 16;
    const int tid  = threadIdx.x;
    const int lane = tid & 31, warp = tid >> 5;
    const int wm = warp >> 2, wn = warp & 3;
    const int m0 = blockIdx.y * 128, n0 = blockIdx.x * 128;

    const __half* Abase = Q + (size_t)blockIdx.z * MM * DD + (size_t)m0 * DD;
    const __half* Bbase = K + (size_t)blockIdx.z * NN * DD + (size_t)n0 * DD;

    const uint32_t sbase = smem_u32(smem);
    const int r0i = tid >> 2, c0i = tid & 3;
    const int r1i = r0i + 64;

    const uint32_t aRowOff = (uint32_t)(((lane & 7) + (lane & 8)) * ROWB + (lane & 16));
    const uint32_t bRowOff = (uint32_t)(((lane & 7) + ((lane & 16) >> 1)) * ROWB + ((lane & 8) << 1));

    float acc[4][4][4];
#pragma unroll
    for (int i = 0; i < 4; i++)
#pragma unroll
        for (int j = 0; j < 4; j++)
#pragma unroll
            for (int q = 0; q < 4; q++) acc[i][j][q] = 0.f;

    auto issue = [&](int c) {
        int k0 = c * KT;
        uint32_t sb0 = sbase + (c & 3) * STAGE_B;
        const __half* ap = Abase + k0;
        const __half* bp = Bbase + k0;
        CP16(sb0 + (uint32_t)(r0i * ROWB + c0i * 16), ap + (size_t)r0i * DD + c0i * 8);
        CP16(sb0 + (uint32_t)(r1i * ROWB + c0i * 16), ap + (size_t)r1i * DD + c0i * 8);
        uint32_t sb1 = sb0 + TILE10;
        CP16(sb1 + (uint32_t)(r0i * ROWB + c0i * 16), bp + (size_t)r0i * DD + c0i * 8);
        CP16(sb1 + (uint32_t)(r1i * ROWB + c0i * 16), bp + (size_t)r1i * DD + c0i * 8);
    };

    issue(0); CP_COMMIT();
    issue(1); CP_COMMIT();
    issue(2); CP_COMMIT();

    for (int c = 0; c < NCHUNK_M; c++) {
        CP_WAIT2();
        __syncthreads();
        int cn = c + 3;
        if (cn < NCHUNK_M) issue(cn);
        CP_COMMIT();

        uint32_t sa = sbase + (c & 3) * STAGE_B;
        uint32_t sb = sa + TILE10;
#pragma unroll
        for (int k16 = 0; k16 < 2; k16++) {
            uint32_t a[4][4];
#pragma unroll
            for (int mt = 0; mt < 4; mt++) {
                uint32_t addr = sa + (uint32_t)((wm * 64 + mt * 16) * ROWB) + aRowOff + k16 * 32;
                LDSM4(a[mt][0], a[mt][1], a[mt][2], a[mt][3], addr);
            }
            uint32_t bfr[2][4];
#pragma unroll
            for (int nt2 = 0; nt2 < 2; nt2++) {
                uint32_t addr = sb + (uint32_t)((wn * 32 + nt2 * 16) * ROWB) + bRowOff + k16 * 32;
                LDSM4(bfr[nt2][0], bfr[nt2][1], bfr[nt2][2], bfr[nt2][3], addr);
            }
#pragma unroll
            for (int mt = 0; mt < 4; mt++)
#pragma unroll
                for (int nt = 0; nt < 4; nt++)
                    MMA_FP16(acc[mt][nt], a[mt], bfr[nt >> 1][(nt & 1) * 2],
                             bfr[nt >> 1][(nt & 1) * 2 + 1]);
        }
    }
    CP_WAIT0();

    const int mrow = lane >> 2, ncol = (lane & 3) * 2;
    float alpha = log1pf(expf(*taup)) + 1e-6f;
    float beta  = *biasp;
    float* Cb = lout + (size_t)blockIdx.z * MM * NN;
#pragma unroll
    for (int mt = 0; mt < 4; mt++) {
#pragma unroll
        for (int half = 0; half < 2; half++) {
            int gr = m0 + wm * 64 + mt * 16 + mrow + half * 8;
            float* crow = Cb + (size_t)gr * NN + n0 + wn * 32 + ncol;
#pragma unroll
            for (int nt = 0; nt < 4; nt++) {
                float2 f;
                f.x = __fadd_rn(__fmul_rn(alpha, acc[mt][nt][half * 2 + 0]), beta);
                f.y = __fadd_rn(__fmul_rn(alpha, acc[mt][nt][half * 2 + 1]), beta);
                *reinterpret_cast<float2*>(crow + nt * 8) = f;
            }
        }
    }
}

// ---------------- prior / rho-inverse per batch ----------------
__global__ void prior_kernel(const int* __restrict__ y) {
    int b = blockIdx.x;
    __shared__ int cnt[CC];
    int t = threadIdx.x;
    if (t < CC) cnt[t] = 0;
    __syncthreads();
    for (int i = t; i < NN; i += 256) atomicAdd(&cnt[y[(size_t)b * NN + i]], 1);
    __syncthreads();
    if (t == 0) {
        int tot = 0;
        for (int c = 0; c < CC; c++) tot += cnt[c];
        float denom = fmaxf((float)tot, 1.f);
        for (int c = 0; c < CC; c++) {
            float pr = (float)cnt[c] / denom;
            g_prior[b * CC + c]  = pr;
            g_rhoinv[b * CC + c] = 1.f / fmaxf(1.f - pr, 1e-6f);
        }
    }
}

// ---------------- top-k select in LOGIT space (sigmoid only for kept members) ----------------
__device__ __forceinline__ unsigned f2u(float f) {
    unsigned u = __float_as_uint(f);
    return (u & 0x80000000u) ? ~u : (u | 0x80000000u);
}

#define BAND_CAP 64
#define LBAND 8e-3f

__global__ void select_agg(const int* __restrict__ y,
                           const float* __restrict__ qf, const float* __restrict__ kf,
                           const float* __restrict__ taup, const float* __restrict__ biasp,
                           float* __restrict__ out) {
    int m = blockIdx.x, b = blockIdx.y;
    const float* lrow = g_logit + ((size_t)b * MM + m) * NN;
    __shared__ float ls[NN];
    __shared__ unsigned short cand[NN];
    __shared__ unsigned whist[8][256];
    __shared__ unsigned hist[256];
    __shared__ unsigned sh_pref, sh_k, sh_nc;
    __shared__ float S[CC], W[CC], sh_prior[CC], sh_rinv[CC];
    __shared__ unsigned cntk;
    __shared__ unsigned sh_above, sh_nb, sh_kept;
    __shared__ unsigned short bandIdx[BAND_CAP];
    __shared__ unsigned char bandKeep[BAND_CAP];
    __shared__ double Lband[BAND_CAP];
    __shared__ float Gband[BAND_CAP];
    const int t = threadIdx.x;
    const int warp = t >> 5, lane = t & 31;

    for (int i = t; i < 8 * 256; i += 256) (&whist[0][0])[i] = 0u;
    if (t < CC) {
        S[t] = 0.f; W[t] = 0.f;
        sh_prior[t] = g_prior[b * CC + t];
        sh_rinv[t]  = g_rhoinv[b * CC + t];
    }
    if (t == 0) { cntk = 0; sh_nc = 0; sh_above = 0; sh_nb = 0; sh_kept = 0; }
    __syncthreads();

    // ---- fused load + pass-1 histogram (on logits) ----
    for (int i = t; i < NN / 4; i += 256) {
        float4 v = reinterpret_cast<const float4*>(lrow)[i];
        reinterpret_cast<float4*>(ls)[i] = v;
        atomicAdd(&whist[warp][f2u(v.x) >> 24], 1u);
        atomicAdd(&whist[warp][f2u(v.y) >> 24], 1u);
        atomicAdd(&whist[warp][f2u(v.z) >> 24], 1u);
        atomicAdd(&whist[warp][f2u(v.w) >> 24], 1u);
    }
    __syncthreads();
    {
        unsigned h = 0;
#pragma unroll
        for (int w = 0; w < 8; w++) h += whist[w][t];
        hist[t] = h;
    }
    __syncthreads();
    if (t == 0) {
        unsigned acc = 0, krem = KTOP;
        int bin = 0;
        for (int i = 255; i >= 0; i--) {
            unsigned h = hist[i];
            if (acc + h >= KTOP) { bin = i; krem = KTOP - acc; break; }
            acc += h;
        }
        sh_pref = (unsigned)bin << 24;
        sh_k = krem;
    }
    __syncthreads();
    unsigned prefix = sh_pref;

    for (int i = t; i < NN; i += 256) {
        if ((f2u(ls[i]) & 0xFF000000u) == prefix) {
            unsigned idx = atomicAdd(&sh_nc, 1u);
            cand[idx] = (unsigned short)i;
        }
    }
    __syncthreads();
    const int ncand = (int)sh_nc;

#pragma unroll
    for (int shift = 16; shift >= 0; shift -= 8) {
        hist[t] = 0;
        __syncthreads();
        unsigned pm = 0xFFFFFFFFu << (shift + 8);
        for (int j = t; j < ncand; j += 256) {
            unsigned u = f2u(ls[cand[j]]);
            if ((u & pm) == prefix) atomicAdd(&hist[(u >> shift) & 255u], 1u);
        }
        __syncthreads();
        if (t == 0) {
            unsigned kneed = sh_k, acc = 0, krem = kneed;
            int bin = 0;
            for (int i = 255; i >= 0; i--) {
                unsigned h = hist[i];
                if (acc + h >= kneed) { bin = i; krem = kneed - acc; break; }
                acc += h;
            }
            sh_pref = prefix | ((unsigned)bin << shift);
            sh_k = krem;
        }
        __syncthreads();
        prefix = sh_pref;
    }
    // v64 = 64th-largest logit; band directly in logit space
    const float v64f = __uint_as_float((prefix & 0x80000000u) ? (prefix | 0x80000000u) ^ 0x80000000u
                                                              : ~prefix);
    // NOTE: inverse of f2u: if top bit set -> positive float (clear top bit kept via u|0x8..)
    const float v64 = (prefix & 0x80000000u) ? __uint_as_float(prefix & 0x7FFFFFFFu)
                                             : __uint_as_float(~prefix);
    (void)v64f;
    const float hi = v64 + LBAND;
    const float lo = v64 - LBAND;

    // ---- fused: accumulate DEFINITE members (sigmoid here, ~64/row) + gather band ----
    const int* yrow = y + (size_t)b * NN;
    for (int i = t; i < NN; i += 256) {
        float l = ls[i];
        if (l > hi) {
            atomicAdd(&sh_above, 1u);
            float g = 1.f / (1.f + expf(-l));
            int c = yrow[i];
            atomicAdd(&S[c], g);
            atomicAdd(&W[c], (1.f - g) * sh_rinv[c]);
        } else if (l >= lo) {
            unsigned idx = atomicAdd(&sh_nb, 1u);
            if (idx < BAND_CAP) bandIdx[idx] = (unsigned short)i;
        }
    }
    __syncthreads();
    const int above = (int)sh_above;
    const int nb = (int)sh_nb;
    const int need = (int)KTOP - above;
    const bool fallback = (nb > BAND_CAP) || (need < 0);

    if (!fallback) {
        if (nb > need) {
            // fp64 exact dot of band members from fp32 Q/K
            const size_t qoff = ((size_t)b * MM + m) * DD;
            const float* qr = qf + qoff;
            for (int j = warp; j < nb; j += 8) {
                int n = bandIdx[j];
                const float* kr = kf + ((size_t)b * NN + n) * DD;
                double acc = 0.0;
                for (int e = lane; e < DD; e += 32)
                    acc = fma((double)qr[e], (double)kr[e], acc);
#pragma unroll
                for (int o = 16; o > 0; o >>= 1)
                    acc += __shfl_down_sync(0xFFFFFFFFu, acc, o);
                if (lane == 0) Lband[j] = acc;
            }
            __syncthreads();
            if (t < nb) {
                float alpha = log1pf(expf(*taup)) + 1e-6f;
                float beta  = *biasp;
                float dotf = (float)Lband[t];
                float l = __fadd_rn(__fmul_rn(alpha, dotf), beta);
                Gband[t] = 1.f / (1.f + expf(-l));
            }
            __syncthreads();
            if (t < nb) {
                float gt = Gband[t];
                int rank = 0;
                for (int j = 0; j < nb; j++) rank += (Gband[j] > gt);
                unsigned char kp = (rank < need) ? 1 : 0;
                bandKeep[t] = kp;
                if (kp) atomicAdd(&sh_kept, 1u);
            }
            __syncthreads();
            for (int j = t; j < nb; j += 256) {
                if (bandKeep[j]) {
                    int i = bandIdx[j];
                    float g = Gband[j];
                    int c = yrow[i];
                    atomicAdd(&S[c], g);
                    atomicAdd(&W[c], (1.f - g) * sh_rinv[c]);
                }
            }
            if (t == 0) cntk = (unsigned)above + sh_kept;
        } else {
            for (int j = t; j < nb; j += 256) {
                int i = bandIdx[j];
                float g = 1.f / (1.f + expf(-ls[i]));
                int c = yrow[i];
                atomicAdd(&S[c], g);
                atomicAdd(&W[c], (1.f - g) * sh_rinv[c]);
            }
            if (t == 0) cntk = (unsigned)(above + nb);
        }
        __syncthreads();
    } else {
        // pathological band: remaining members with >=prefix semantics on logits
        for (int i = t; i < NN; i += 256) {
            float l = ls[i];
            if (l <= hi && f2u(l) >= prefix) {
                float g = 1.f / (1.f + expf(-l));
                int c = yrow[i];
                atomicAdd(&S[c], g);
                atomicAdd(&W[c], (1.f - g) * sh_rinv[c]);
                atomicAdd(&sh_kept, 1u);
            }
        }
        __syncthreads();
        if (t == 0) cntk = (unsigned)above + sh_kept;
        __syncthreads();
    }

    if (t == 0) {
        float Wt = 0.f;
        for (int c = 0; c < CC; c++) Wt += W[c];
        float dq = fmaxf((float)cntk, 1.f);
        float p[CC];
        float sum = 0.f;
        for (int c = 0; c < CC; c++) {
            float v = S[c] + sh_prior[c] * (Wt - W[c]);
            v = fmaxf(v, 0.f) / dq;
            p[c] = v;
            sum += v;
        }
        float inv = 1.f / fmaxf(sum, 1e-12f);
        float* orow = out + ((size_t)b * MM + m) * CC;
        for (int c = 0; c < CC; c++) orow[c] = p[c] * inv;
    }
}

// ---------------- launcher ----------------
extern "C" void kernel_launch(void* const* d_in, const int* in_sizes, int n_in,
                              void* d_out, int out_size) {
    const float* Hs   = (const float*)d_in[0];
    const float* Hq   = (const float*)d_in[1];
    const int*   ys   = (const int*)d_in[2];
    const float* lnw  = (const float*)d_in[4];
    const float* lnb  = (const float*)d_in[5];
    const float* WQ   = (const float*)d_in[6];
    const float* WK   = (const float*)d_in[7];
    const float* taup = (const float*)d_in[8];
    const float* bisp = (const float*)d_in[9];
    float* out = (float*)d_out;

    __nv_bfloat16 *hqB, *hsB, *wqB, *wkB;
    float *qF, *kF;
    __half *qH, *kH;
    float* Lg;
    cudaGetSymbolAddress((void**)&hqB, g_hq);
    cudaGetSymbolAddress((void**)&hsB, g_hs);
    cudaGetSymbolAddress((void**)&wqB, g_wq);
    cudaGetSymbolAddress((void**)&wkB, g_wk);
    cudaGetSymbolAddress((void**)&qF, g_qf);
    cudaGetSymbolAddress((void**)&kF, g_kf);
    cudaGetSymbolAddress((void**)&qH, g_qh);
    cudaGetSymbolAddress((void**)&kH, g_kh);
    cudaGetSymbolAddress((void**)&Lg, g_logit);

    const size_t HQ = (size_t)BB * MM * DD;
    const size_t HS = (size_t)BB * NN * DD;
    const size_t WW = (size_t)DD * DD;

    cudaFuncSetAttribute(mma_proj, cudaFuncAttributeMaxDynamicSharedMemorySize, SMEM_GEMM);
    cudaFuncSetAttribute(mma_logits, cudaFuncAttributeMaxDynamicSharedMemorySize, SMEM_GEMM);

    // 1) LayerNorm + splits
    ln_split<<<BB * MM, 128>>>(Hq, lnw, lnb, hqB, hqB + HQ, hqB + 2 * HQ);
    ln_split<<<BB * NN, 128>>>(Hs, lnw, lnb, hsB, hsB + HS, hsB + 2 * HS);
    split3<<<(int)((WW + 255) / 256), 256>>>(WQ, wqB, wqB + WW, wqB + 2 * WW, (int)WW);
    split3<<<(int)((WW + 255) / 256), 256>>>(WK, wkB, wkB + WW, wkB + 2 * WW, (int)WW);

    // 2) priors
    prior_kernel<<<BB, 256>>>(ys);

    // 3) merged projections
    mma_proj<<<dim3(DD / 128, QTILES + (BB * NN) / 128, 1), NTHR, SMEM_GEMM>>>(
        hqB, hqB + HQ, hqB + 2 * HQ, wqB, wqB + WW, wqB + 2 * WW, qF, qH,
        hsB, hsB + HS, hsB + 2 * HS, wkB, wkB + WW, wkB + 2 * WW, kF, kH);

    // 4) raw logits (sigmoid deferred to select)
    mma_logits<<<dim3(NN / 128, MM / 128, BB), NTHR, SMEM_GEMM>>>(qH, kH, Lg, taup, bisp);

    // 5) top-k select in logit space + aggregate
    select_agg<<<dim3(MM, BB), 256>>>(ys, qF, kF, taup, bisp, out);
}

// round 17
// speedup vs baseline: 2.0643x; 1.1690x over previous
#include <cuda_runtime.h>
#include <cuda_bf16.h>
#include <cuda_fp16.h>
#include <cstdint>

#define BB 4
#define NN 4096
#define MM 2048
#define DD 512
#define CC 10
#define KTOP 64u

// ---------------- scratch (device globals; no cudaMalloc allowed) ----------------
__device__ __align__(256) __nv_bfloat16 g_hq[3][BB * MM * DD];
__device__ __align__(256) __nv_bfloat16 g_hs[3][BB * NN * DD];
__device__ __align__(256) __nv_bfloat16 g_wq[3][DD * DD];
__device__ __align__(256) __nv_bfloat16 g_wk[3][DD * DD];
__device__ __align__(256) float  g_qf[BB * MM * DD];
__device__ __align__(256) float  g_kf[BB * NN * DD];
__device__ __align__(256) __half g_qh[BB * MM * DD];
__device__ __align__(256) __half g_kh[BB * NN * DD];
__device__ __align__(256) __half g_logit[(size_t)BB * MM * NN];  // fp16 raw logits
__device__ float g_prior[BB * CC];
__device__ float g_rhoinv[BB * CC];

// ---------------- helpers ----------------
__device__ __forceinline__ uint32_t smem_u32(const void* p) {
    uint32_t a;
    asm("{ .reg .u64 t; cvta.to.shared.u64 t, %1; cvt.u32.u64 %0, t; }" : "=r"(a) : "l"(p));
    return a;
}

#define CP16(dst, src) \
    asm volatile("cp.async.cg.shared.global [%0], [%1], 16;" :: "r"(dst), "l"(src))
#define CP_COMMIT() asm volatile("cp.async.commit_group;" ::: "memory")
#define CP_WAIT2()  asm volatile("cp.async.wait_group 2;" ::: "memory")
#define CP_WAIT0()  asm volatile("cp.async.wait_group 0;" ::: "memory")

#define LDSM4(r0, r1, r2, r3, addr) \
    asm volatile("ldmatrix.sync.aligned.m8n8.x4.shared.b16 {%0,%1,%2,%3}, [%4];" \
                 : "=r"(r0), "=r"(r1), "=r"(r2), "=r"(r3) : "r"(addr))

#define MMA_BF16(d, a, b0, b1) \
    asm volatile("mma.sync.aligned.m16n8k16.row.col.f32.bf16.bf16.f32 " \
                 "{%0,%1,%2,%3}, {%4,%5,%6,%7}, {%8,%9}, {%0,%1,%2,%3};" \
                 : "+f"((d)[0]), "+f"((d)[1]), "+f"((d)[2]), "+f"((d)[3]) \
                 : "r"((a)[0]), "r"((a)[1]), "r"((a)[2]), "r"((a)[3]), "r"(b0), "r"(b1))

#define MMA_FP16(d, a, b0, b1) \
    asm volatile("mma.sync.aligned.m16n8k16.row.col.f32.f16.f16.f32 " \
                 "{%0,%1,%2,%3}, {%4,%5,%6,%7}, {%8,%9}, {%0,%1,%2,%3};" \
                 : "+f"((d)[0]), "+f"((d)[1]), "+f"((d)[2]), "+f"((d)[3]) \
                 : "r"((a)[0]), "r"((a)[1]), "r"((a)[2]), "r"((a)[3]), "r"(b0), "r"(b1))

// ---------------- LayerNorm fused with 3-way bf16 split ----------------
__global__ void ln_split(const float* __restrict__ x, const float* __restrict__ w,
                         const float* __restrict__ b,
                         __nv_bfloat16* __restrict__ o0, __nv_bfloat16* __restrict__ o1,
                         __nv_bfloat16* __restrict__ o2) {
    int row = blockIdx.x;
    const float* xr = x + (size_t)row * DD;
    int t = threadIdx.x;
    float v[4];
    float s = 0.f, s2 = 0.f;
#pragma unroll
    for (int i = 0; i < 4; i++) {
        v[i] = xr[t + i * 128];
        s += v[i];
        s2 += v[i] * v[i];
    }
#pragma unroll
    for (int o = 16; o > 0; o >>= 1) {
        s  += __shfl_down_sync(0xFFFFFFFFu, s, o);
        s2 += __shfl_down_sync(0xFFFFFFFFu, s2, o);
    }
    __shared__ float ps[4], ps2[4];
    if ((t & 31) == 0) { ps[t >> 5] = s; ps2[t >> 5] = s2; }
    __syncthreads();
    s  = ps[0] + ps[1] + ps[2] + ps[3];
    s2 = ps2[0] + ps2[1] + ps2[2] + ps2[3];
    float mu  = s * (1.f / DD);
    float var = s2 * (1.f / DD) - mu * mu;
    float rs  = 1.f / sqrtf(var + 1e-5f);
#pragma unroll
    for (int i = 0; i < 4; i++) {
        int c = t + i * 128;
        float val = (v[i] - mu) * rs * w[c] + b[c];
        __nv_bfloat16 h0 = __float2bfloat16_rn(val);
        float r1 = val - __bfloat162float(h0);
        __nv_bfloat16 h1 = __float2bfloat16_rn(r1);
        float r2 = r1 - __bfloat162float(h1);
        __nv_bfloat16 h2 = __float2bfloat16_rn(r2);
        size_t oi = (size_t)row * DD + c;
        o0[oi] = h0; o1[oi] = h1; o2[oi] = h2;
    }
}

__global__ void split3(const float* __restrict__ x, __nv_bfloat16* __restrict__ o0,
                       __nv_bfloat16* __restrict__ o1, __nv_bfloat16* __restrict__ o2, int n) {
    int i = blockIdx.x * 256 + threadIdx.x;
    if (i < n) {
        float v = x[i];
        __nv_bfloat16 h0 = __float2bfloat16_rn(v);
        float r1 = v - __bfloat162float(h0);
        __nv_bfloat16 h1 = __float2bfloat16_rn(r1);
        float r2 = r1 - __bfloat162float(h1);
        __nv_bfloat16 h2 = __float2bfloat16_rn(r2);
        o0[i] = h0; o1[i] = h1; o2[i] = h2;
    }
}

// ---------------- tiling constants ----------------
#define KT 32
#define ROWB 80
#define TILE10 (128 * ROWB)
#define STAGE_B (2 * TILE10)
#define SMEM_GEMM (4 * STAGE_B)
#define NTHR 256
#define QTILES ((BB * MM) / 128)     // 64

// ---------------- merged projection GEMM (Q tiles then K tiles in one grid) ----------------
__global__ void __launch_bounds__(NTHR, 2) mma_proj(
    const __nv_bfloat16* __restrict__ qA0, const __nv_bfloat16* __restrict__ qA1,
    const __nv_bfloat16* __restrict__ qA2,
    const __nv_bfloat16* __restrict__ qB0, const __nv_bfloat16* __restrict__ qB1,
    const __nv_bfloat16* __restrict__ qB2,
    float* __restrict__ qof, __half* __restrict__ qoh,
    const __nv_bfloat16* __restrict__ sA0, const __nv_bfloat16* __restrict__ sA1,
    const __nv_bfloat16* __restrict__ sA2,
    const __nv_bfloat16* __restrict__ sB0, const __nv_bfloat16* __restrict__ sB1,
    const __nv_bfloat16* __restrict__ sB2,
    float* __restrict__ sof, __half* __restrict__ soh) {
    extern __shared__ __align__(128) char smem[];
    const int NCHUNK_M = 96;
    const int tid  = threadIdx.x;
    const int lane = tid & 31, warp = tid >> 5;
    const int wm = warp >> 2, wn = warp & 3;

    const bool isQ = (blockIdx.y < QTILES);
    const int mtile = isQ ? blockIdx.y : (blockIdx.y - QTILES);
    const int m0 = mtile * 128, n0 = blockIdx.x * 128;

    const __nv_bfloat16* A0 = isQ ? qA0 : sA0;
    const __nv_bfloat16* A1 = isQ ? qA1 : sA1;
    const __nv_bfloat16* A2 = isQ ? qA2 : sA2;
    const __nv_bfloat16* B0 = isQ ? qB0 : sB0;
    const __nv_bfloat16* B1 = isQ ? qB1 : sB1;
    const __nv_bfloat16* B2 = isQ ? qB2 : sB2;
    float*  of = isQ ? qof : sof;
    __half* oh = isQ ? qoh : soh;

    const __nv_bfloat16* Abase = A0 + (size_t)m0 * DD;
    const __nv_bfloat16* Bbase = B0 + (size_t)n0 * DD;
    const uint32_t da1 = (uint32_t)(A1 - A0), da2 = (uint32_t)(A2 - A0);
    const uint32_t db1 = (uint32_t)(B1 - B0), db2 = (uint32_t)(B2 - B0);

    const uint32_t sbase = smem_u32(smem);
    const int r0i = tid >> 2, c0i = tid & 3;
    const int r1i = r0i + 64;

    const uint32_t aRowOff = (uint32_t)(((lane & 7) + (lane & 8)) * ROWB + (lane & 16));
    const uint32_t bRowOff = (uint32_t)(((lane & 7) + ((lane & 16) >> 1)) * ROWB + ((lane & 8) << 1));

    float acc[4][4][4];
#pragma unroll
    for (int i = 0; i < 4; i++)
#pragma unroll
        for (int j = 0; j < 4; j++)
#pragma unroll
            for (int q = 0; q < 4; q++) acc[i][j][q] = 0.f;

    auto issue = [&](int c) {
        int seg = c >> 4, k0 = (c & 15) * KT;
        uint32_t oa = (seg == 1) ? da2 : ((seg == 2) || (seg == 4)) ? da1 : 0u;
        uint32_t ob = (seg == 0) ? db2 : ((seg == 2) || (seg == 3)) ? db1 : 0u;
        uint32_t sb0 = sbase + (c & 3) * STAGE_B;
        const __nv_bfloat16* ap = Abase + oa + k0;
        const __nv_bfloat16* bp = Bbase + ob + k0;
        CP16(sb0 + (uint32_t)(r0i * ROWB + c0i * 16), ap + (size_t)r0i * DD + c0i * 8);
        CP16(sb0 + (uint32_t)(r1i * ROWB + c0i * 16), ap + (size_t)r1i * DD + c0i * 8);
        uint32_t sb1 = sb0 + TILE10;
        CP16(sb1 + (uint32_t)(r0i * ROWB + c0i * 16), bp + (size_t)r0i * DD + c0i * 8);
        CP16(sb1 + (uint32_t)(r1i * ROWB + c0i * 16), bp + (size_t)r1i * DD + c0i * 8);
    };

    issue(0); CP_COMMIT();
    issue(1); CP_COMMIT();
    issue(2); CP_COMMIT();

    for (int c = 0; c < NCHUNK_M; c++) {
        CP_WAIT2();
        __syncthreads();
        int cn = c + 3;
        if (cn < NCHUNK_M) issue(cn);
        CP_COMMIT();

        uint32_t sa = sbase + (c & 3) * STAGE_B;
        uint32_t sb = sa + TILE10;
#pragma unroll
        for (int k16 = 0; k16 < 2; k16++) {
            uint32_t a[4][4];
#pragma unroll
            for (int mt = 0; mt < 4; mt++) {
                uint32_t addr = sa + (uint32_t)((wm * 64 + mt * 16) * ROWB) + aRowOff + k16 * 32;
                LDSM4(a[mt][0], a[mt][1], a[mt][2], a[mt][3], addr);
            }
            uint32_t bfr[2][4];
#pragma unroll
            for (int nt2 = 0; nt2 < 2; nt2++) {
                uint32_t addr = sb + (uint32_t)((wn * 32 + nt2 * 16) * ROWB) + bRowOff + k16 * 32;
                LDSM4(bfr[nt2][0], bfr[nt2][1], bfr[nt2][2], bfr[nt2][3], addr);
            }
#pragma unroll
            for (int mt = 0; mt < 4; mt++)
#pragma unroll
                for (int nt = 0; nt < 4; nt++)
                    MMA_BF16(acc[mt][nt], a[mt], bfr[nt >> 1][(nt & 1) * 2],
                             bfr[nt >> 1][(nt & 1) * 2 + 1]);
        }
    }
    CP_WAIT0();

    const int mrow = lane >> 2, ncol = (lane & 3) * 2;
#pragma unroll
    for (int mt = 0; mt < 4; mt++) {
#pragma unroll
        for (int half = 0; half < 2; half++) {
            int gr = m0 + wm * 64 + mt * 16 + mrow + half * 8;
            size_t base = (size_t)gr * DD + n0 + wn * 32 + ncol;
#pragma unroll
            for (int nt = 0; nt < 4; nt++) {
                float vx = acc[mt][nt][half * 2 + 0];
                float vy = acc[mt][nt][half * 2 + 1];
                float2 fv; fv.x = vx; fv.y = vy;
                *reinterpret_cast<float2*>(of + base + nt * 8) = fv;
                __half2 hv; hv.x = __float2half_rn(vx); hv.y = __float2half_rn(vy);
                *reinterpret_cast<__half2*>(oh + base + nt * 8) = hv;
            }
        }
    }
}

// ---------------- logits GEMM (fp16 single-product; stores fp16 raw logits) ----------------
__global__ void __launch_bounds__(NTHR, 2) mma_logits(
    const __half* __restrict__ Q, const __half* __restrict__ K,
    __half* __restrict__ lout,
    const float* __restrict__ taup, const float* __restrict__ biasp) {
    extern __shared__ __align__(128) char smem[];
    const int NCHUNK_M = 16;
    const int tid  = threadIdx.x;
    const int lane = tid & 31, warp = tid >> 5;
    const int wm = warp >> 2, wn = warp & 3;
    const int m0 = blockIdx.y * 128, n0 = blockIdx.x * 128;

    const __half* Abase = Q + (size_t)blockIdx.z * MM * DD + (size_t)m0 * DD;
    const __half* Bbase = K + (size_t)blockIdx.z * NN * DD + (size_t)n0 * DD;

    const uint32_t sbase = smem_u32(smem);
    const int r0i = tid >> 2, c0i = tid & 3;
    const int r1i = r0i + 64;

    const uint32_t aRowOff = (uint32_t)(((lane & 7) + (lane & 8)) * ROWB + (lane & 16));
    const uint32_t bRowOff = (uint32_t)(((lane & 7) + ((lane & 16) >> 1)) * ROWB + ((lane & 8) << 1));

    float acc[4][4][4];
#pragma unroll
    for (int i = 0; i < 4; i++)
#pragma unroll
        for (int j = 0; j < 4; j++)
#pragma unroll
            for (int q = 0; q < 4; q++) acc[i][j][q] = 0.f;

    auto issue = [&](int c) {
        int k0 = c * KT;
        uint32_t sb0 = sbase + (c & 3) * STAGE_B;
        const __half* ap = Abase + k0;
        const __half* bp = Bbase + k0;
        CP16(sb0 + (uint32_t)(r0i * ROWB + c0i * 16), ap + (size_t)r0i * DD + c0i * 8);
        CP16(sb0 + (uint32_t)(r1i * ROWB + c0i * 16), ap + (size_t)r1i * DD + c0i * 8);
        uint32_t sb1 = sb0 + TILE10;
        CP16(sb1 + (uint32_t)(r0i * ROWB + c0i * 16), bp + (size_t)r0i * DD + c0i * 8);
        CP16(sb1 + (uint32_t)(r1i * ROWB + c0i * 16), bp + (size_t)r1i * DD + c0i * 8);
    };

    issue(0); CP_COMMIT();
    issue(1); CP_COMMIT();
    issue(2); CP_COMMIT();

    for (int c = 0; c < NCHUNK_M; c++) {
        CP_WAIT2();
        __syncthreads();
        int cn = c + 3;
        if (cn < NCHUNK_M) issue(cn);
        CP_COMMIT();

        uint32_t sa = sbase + (c & 3) * STAGE_B;
        uint32_t sb = sa + TILE10;
#pragma unroll
        for (int k16 = 0; k16 < 2; k16++) {
            uint32_t a[4][4];
#pragma unroll
            for (int mt = 0; mt < 4; mt++) {
                uint32_t addr = sa + (uint32_t)((wm * 64 + mt * 16) * ROWB) + aRowOff + k16 * 32;
                LDSM4(a[mt][0], a[mt][1], a[mt][2], a[mt][3], addr);
            }
            uint32_t bfr[2][4];
#pragma unroll
            for (int nt2 = 0; nt2 < 2; nt2++) {
                uint32_t addr = sb + (uint32_t)((wn * 32 + nt2 * 16) * ROWB) + bRowOff + k16 * 32;
                LDSM4(bfr[nt2][0], bfr[nt2][1], bfr[nt2][2], bfr[nt2][3], addr);
            }
#pragma unroll
            for (int mt = 0; mt < 4; mt++)
#pragma unroll
                for (int nt = 0; nt < 4; nt++)
                    MMA_FP16(acc[mt][nt], a[mt], bfr[nt >> 1][(nt & 1) * 2],
                             bfr[nt >> 1][(nt & 1) * 2 + 1]);
        }
    }
    CP_WAIT0();

    const int mrow = lane >> 2, ncol = (lane & 3) * 2;
    float alpha = log1pf(expf(*taup)) + 1e-6f;
    float beta  = *biasp;
    __half* Cb = lout + (size_t)blockIdx.z * MM * NN;
#pragma unroll
    for (int mt = 0; mt < 4; mt++) {
#pragma unroll
        for (int half = 0; half < 2; half++) {
            int gr = m0 + wm * 64 + mt * 16 + mrow + half * 8;
            __half* crow = Cb + (size_t)gr * NN + n0 + wn * 32 + ncol;
#pragma unroll
            for (int nt = 0; nt < 4; nt++) {
                float lx = __fadd_rn(__fmul_rn(alpha, acc[mt][nt][half * 2 + 0]), beta);
                float ly = __fadd_rn(__fmul_rn(alpha, acc[mt][nt][half * 2 + 1]), beta);
                __half2 hv; hv.x = __float2half_rn(lx); hv.y = __float2half_rn(ly);
                *reinterpret_cast<__half2*>(crow + nt * 8) = hv;
            }
        }
    }
}

// ---------------- prior / rho-inverse per batch ----------------
__global__ void prior_kernel(const int* __restrict__ y) {
    int b = blockIdx.x;
    __shared__ int cnt[CC];
    int t = threadIdx.x;
    if (t < CC) cnt[t] = 0;
    __syncthreads();
    for (int i = t; i < NN; i += 256) atomicAdd(&cnt[y[(size_t)b * NN + i]], 1);
    __syncthreads();
    if (t == 0) {
        int tot = 0;
        for (int c = 0; c < CC; c++) tot += cnt[c];
        float denom = fmaxf((float)tot, 1.f);
        for (int c = 0; c < CC; c++) {
            float pr = (float)cnt[c] / denom;
            g_prior[b * CC + c]  = pr;
            g_rhoinv[b * CC + c] = 1.f / fmaxf(1.f - pr, 1e-6f);
        }
    }
}

// ---------------- top-k select: 16-bit 2-pass radix on fp16 logits ----------------
__device__ __forceinline__ unsigned h2key(unsigned short u) {
    return (u & 0x8000u) ? (unsigned)((~u) & 0xFFFFu) : (unsigned)(u | 0x8000u);
}

#define BAND_CAP 64
#define LBAND 8e-3f

__global__ void select_agg(const int* __restrict__ y,
                           const float* __restrict__ qf, const float* __restrict__ kf,
                           const float* __restrict__ taup, const float* __restrict__ biasp,
                           float* __restrict__ out) {
    int m = blockIdx.x, b = blockIdx.y;
    const __half* lrow = g_logit + ((size_t)b * MM + m) * NN;
    __shared__ __half ls[NN];
    __shared__ unsigned short cand[NN];
    __shared__ unsigned whist[8][256];
    __shared__ unsigned hist[256];
    __shared__ unsigned sh_pref, sh_k, sh_nc;
    __shared__ float S[CC], W[CC], sh_prior[CC], sh_rinv[CC];
    __shared__ unsigned cntk;
    __shared__ unsigned sh_above, sh_nb, sh_kept;
    __shared__ unsigned short bandIdx[BAND_CAP];
    __shared__ unsigned char bandKeep[BAND_CAP];
    __shared__ double Lband[BAND_CAP];
    __shared__ float Gband[BAND_CAP];
    const int t = threadIdx.x;
    const int warp = t >> 5, lane = t & 31;

    for (int i = t; i < 8 * 256; i += 256) (&whist[0][0])[i] = 0u;
    if (t < CC) {
        S[t] = 0.f; W[t] = 0.f;
        sh_prior[t] = g_prior[b * CC + t];
        sh_rinv[t]  = g_rhoinv[b * CC + t];
    }
    if (t == 0) { cntk = 0; sh_nc = 0; sh_above = 0; sh_nb = 0; sh_kept = 0; }
    __syncthreads();

    // ---- fused load + pass-1 histogram on top 8 bits of 16-bit key ----
    for (int i = t; i < NN / 8; i += 256) {
        uint4 v = reinterpret_cast<const uint4*>(lrow)[i];
        reinterpret_cast<uint4*>(ls)[i] = v;
        unsigned ws[4] = {v.x, v.y, v.z, v.w};
#pragma unroll
        for (int q = 0; q < 4; q++) {
            atomicAdd(&whist[warp][h2key((unsigned short)(ws[q] & 0xFFFFu)) >> 8], 1u);
            atomicAdd(&whist[warp][h2key((unsigned short)(ws[q] >> 16)) >> 8], 1u);
        }
    }
    __syncthreads();
    {
        unsigned h = 0;
#pragma unroll
        for (int w = 0; w < 8; w++) h += whist[w][t];
        hist[t] = h;
    }
    __syncthreads();
    if (t == 0) {
        unsigned acc = 0, krem = KTOP;
        int bin = 0;
        for (int i = 255; i >= 0; i--) {
            unsigned h = hist[i];
            if (acc + h >= KTOP) { bin = i; krem = KTOP - acc; break; }
            acc += h;
        }
        sh_pref = (unsigned)bin << 8;
        sh_k = krem;
    }
    __syncthreads();
    unsigned prefix = sh_pref;

    // ---- compact candidates (winning top-8 bin) ----
    for (int i = t; i < NN; i += 256) {
        unsigned key = h2key(__half_as_ushort(ls[i]));
        if ((key & 0xFF00u) == prefix) {
            unsigned idx = atomicAdd(&sh_nc, 1u);
            cand[idx] = (unsigned short)i;
        }
    }
    __syncthreads();
    const int ncand = (int)sh_nc;

    // ---- pass 2: low 8 bits over candidates ----
    hist[t] = 0;
    __syncthreads();
    for (int j = t; j < ncand; j += 256) {
        unsigned key = h2key(__half_as_ushort(ls[cand[j]]));
        atomicAdd(&hist[key & 255u], 1u);
    }
    __syncthreads();
    if (t == 0) {
        unsigned kneed = sh_k, acc = 0;
        int bin = 0;
        for (int i = 255; i >= 0; i--) {
            unsigned h = hist[i];
            if (acc + h >= kneed) { bin = i; break; }
            acc += h;
        }
        sh_pref = prefix | (unsigned)bin;
    }
    __syncthreads();
    prefix = sh_pref;

    // v64 = 64th-largest fp16 logit (invert h2key)
    unsigned short vbits = (prefix & 0x8000u) ? (unsigned short)(prefix & 0x7FFFu)
                                              : (unsigned short)((~prefix) & 0xFFFFu);
    const float v64 = __half2float(__ushort_as_half(vbits));
    const float hi = v64 + LBAND;
    const float lo = v64 - LBAND;

    // ---- fused: accumulate definite members + gather band ----
    const int* yrow = y + (size_t)b * NN;
    for (int i = t; i < NN; i += 256) {
        float l = __half2float(ls[i]);
        if (l > hi) {
            atomicAdd(&sh_above, 1u);
            float g = 1.f / (1.f + expf(-l));
            int c = yrow[i];
            atomicAdd(&S[c], g);
            atomicAdd(&W[c], (1.f - g) * sh_rinv[c]);
        } else if (l >= lo) {
            unsigned idx = atomicAdd(&sh_nb, 1u);
            if (idx < BAND_CAP) bandIdx[idx] = (unsigned short)i;
        }
    }
    __syncthreads();
    const int above = (int)sh_above;
    const int nb = (int)sh_nb;
    const int need = (int)KTOP - above;
    const bool fallback = (nb > BAND_CAP) || (need < 0);

    if (!fallback) {
        if (nb > need) {
            // fp64 exact dot of band members from fp32 Q/K
            const size_t qoff = ((size_t)b * MM + m) * DD;
            const float* qr = qf + qoff;
            for (int j = warp; j < nb; j += 8) {
                int n = bandIdx[j];
                const float* kr = kf + ((size_t)b * NN + n) * DD;
                double acc = 0.0;
                for (int e = lane; e < DD; e += 32)
                    acc = fma((double)qr[e], (double)kr[e], acc);
#pragma unroll
                for (int o = 16; o > 0; o >>= 1)
                    acc += __shfl_down_sync(0xFFFFFFFFu, acc, o);
                if (lane == 0) Lband[j] = acc;
            }
            __syncthreads();
            if (t < nb) {
                float alpha = log1pf(expf(*taup)) + 1e-6f;
                float beta  = *biasp;
                float dotf = (float)Lband[t];
                float l = __fadd_rn(__fmul_rn(alpha, dotf), beta);
                Gband[t] = 1.f / (1.f + expf(-l));
            }
            __syncthreads();
            if (t < nb) {
                float gt = Gband[t];
                int rank = 0;
                for (int j = 0; j < nb; j++) rank += (Gband[j] > gt);
                unsigned char kp = (rank < need) ? 1 : 0;
                bandKeep[t] = kp;
                if (kp) atomicAdd(&sh_kept, 1u);
            }
            __syncthreads();
            for (int j = t; j < nb; j += 256) {
                if (bandKeep[j]) {
                    int i = bandIdx[j];
                    float g = Gband[j];
                    int c = yrow[i];
                    atomicAdd(&S[c], g);
                    atomicAdd(&W[c], (1.f - g) * sh_rinv[c]);
                }
            }
            if (t == 0) cntk = (unsigned)above + sh_kept;
        } else {
            for (int j = t; j < nb; j += 256) {
                int i = bandIdx[j];
                float g = 1.f / (1.f + expf(-__half2float(ls[i])));
                int c = yrow[i];
                atomicAdd(&S[c], g);
                atomicAdd(&W[c], (1.f - g) * sh_rinv[c]);
            }
            if (t == 0) cntk = (unsigned)(above + nb);
        }
        __syncthreads();
    } else {
        // pathological band: remaining members with >= prefix key semantics
        for (int i = t; i < NN; i += 256) {
            float l = __half2float(ls[i]);
            unsigned key = h2key(__half_as_ushort(ls[i]));
            if (l <= hi && key >= prefix) {
                float g = 1.f / (1.f + expf(-l));
                int c = yrow[i];
                atomicAdd(&S[c], g);
                atomicAdd(&W[c], (1.f - g) * sh_rinv[c]);
                atomicAdd(&sh_kept, 1u);
            }
        }
        __syncthreads();
        if (t == 0) cntk = (unsigned)above + sh_kept;
        __syncthreads();
    }

    if (t == 0) {
        float Wt = 0.f;
        for (int c = 0; c < CC; c++) Wt += W[c];
        float dq = fmaxf((float)cntk, 1.f);
        float p[CC];
        float sum = 0.f;
        for (int c = 0; c < CC; c++) {
            float v = S[c] + sh_prior[c] * (Wt - W[c]);
            v = fmaxf(v, 0.f) / dq;
            p[c] = v;
            sum += v;
        }
        float inv = 1.f / fmaxf(sum, 1e-12f);
        float* orow = out + ((size_t)b * MM + m) * CC;
        for (int c = 0; c < CC; c++) orow[c] = p[c] * inv;
    }
}

// ---------------- launcher ----------------
extern "C" void kernel_launch(void* const* d_in, const int* in_sizes, int n_in,
                              void* d_out, int out_size) {
    const float* Hs   = (const float*)d_in[0];
    const float* Hq   = (const float*)d_in[1];
    const int*   ys   = (const int*)d_in[2];
    const float* lnw  = (const float*)d_in[4];
    const float* lnb  = (const float*)d_in[5];
    const float* WQ   = (const float*)d_in[6];
    const float* WK   = (const float*)d_in[7];
    const float* taup = (const float*)d_in[8];
    const float* bisp = (const float*)d_in[9];
    float* out = (float*)d_out;

    __nv_bfloat16 *hqB, *hsB, *wqB, *wkB;
    float *qF, *kF;
    __half *qH, *kH, *Lg;
    cudaGetSymbolAddress((void**)&hqB, g_hq);
    cudaGetSymbolAddress((void**)&hsB, g_hs);
    cudaGetSymbolAddress((void**)&wqB, g_wq);
    cudaGetSymbolAddress((void**)&wkB, g_wk);
    cudaGetSymbolAddress((void**)&qF, g_qf);
    cudaGetSymbolAddress((void**)&kF, g_kf);
    cudaGetSymbolAddress((void**)&qH, g_qh);
    cudaGetSymbolAddress((void**)&kH, g_kh);
    cudaGetSymbolAddress((void**)&Lg, g_logit);

    const size_t HQ = (size_t)BB * MM * DD;
    const size_t HS = (size_t)BB * NN * DD;
    const size_t WW = (size_t)DD * DD;

    cudaFuncSetAttribute(mma_proj, cudaFuncAttributeMaxDynamicSharedMemorySize, SMEM_GEMM);
    cudaFuncSetAttribute(mma_logits, cudaFuncAttributeMaxDynamicSharedMemorySize, SMEM_GEMM);

    // 1) LayerNorm + splits
    ln_split<<<BB * MM, 128>>>(Hq, lnw, lnb, hqB, hqB + HQ, hqB + 2 * HQ);
    ln_split<<<BB * NN, 128>>>(Hs, lnw, lnb, hsB, hsB + HS, hsB + 2 * HS);
    split3<<<(int)((WW + 255) / 256), 256>>>(WQ, wqB, wqB + WW, wqB + 2 * WW, (int)WW);
    split3<<<(int)((WW + 255) / 256), 256>>>(WK, wkB, wkB + WW, wkB + 2 * WW, (int)WW);

    // 2) priors
    prior_kernel<<<BB, 256>>>(ys);

    // 3) merged projections
    mma_proj<<<dim3(DD / 128, QTILES + (BB * NN) / 128, 1), NTHR, SMEM_GEMM>>>(
        hqB, hqB + HQ, hqB + 2 * HQ, wqB, wqB + WW, wqB + 2 * WW, qF, qH,
        hsB, hsB + HS, hsB + 2 * HS, wkB, wkB + WW, wkB + 2 * WW, kF, kH);

    // 4) fp16 raw logits (sigmoid deferred)
    mma_logits<<<dim3(NN / 128, MM / 128, BB), NTHR, SMEM_GEMM>>>(qH, kH, Lg, taup, bisp);

    // 5) top-k select (16-bit 2-pass radix) + aggregate
    select_agg<<<dim3(MM, BB), 256>>>(ys, qF, kF, taup, bisp, out);
}